// round 1
// baseline (speedup 1.0000x reference)
#include <cuda_runtime.h>
#include <math.h>

#define NBATCH 2
#define SEQ    2048
#define DIM    1024
#define LDIM   1024
#define NH     16
#define DH     64
#define MTOT   (NBATCH*SEQ)   /* 4096 */
#define BHTOT  (NBATCH*NH)    /* 32   */

// ---------------- scratch (static device globals; no allocation) ----------------
__device__ float g_Q [ (size_t)MTOT * LDIM ];
__device__ float g_Kb[ (size_t)MTOT * LDIM ];
__device__ float g_V [ (size_t)MTOT * LDIM ];
__device__ float g_Sc[ (size_t)BHTOT * SEQ * SEQ ];   // 512 MB scores [bh][k][q]
__device__ float g_Z [ (size_t)MTOT * LDIM ];
__device__ float g_Z2[ (size_t)MTOT * LDIM ];

// ---------------- classic 128x128x8 SGEMM, row-major, dims % 128 == 0 ----------------
__global__ __launch_bounds__(256) void sgemm128(const float* __restrict__ A,
                                                const float* __restrict__ B,
                                                float* __restrict__ C,
                                                int M, int N, int K) {
    __shared__ float As[8][128];
    __shared__ float Bs[8][128];
    const int tid = threadIdx.x;
    const int bx = blockIdx.x, by = blockIdx.y;
    const float* Ab = A + (size_t)by * 128 * K;
    const float* Bb = B + bx * 128;
    float* Cb = C + (size_t)by * 128 * N + bx * 128;

    const int aRow = tid >> 1, aCol = (tid & 1) * 4;
    const int bRow = tid >> 5, bCol = (tid & 31) * 4;
    const int tr = (tid >> 4) * 8, tc = (tid & 15) * 8;

    float acc[8][8];
#pragma unroll
    for (int i = 0; i < 8; i++)
#pragma unroll
        for (int j = 0; j < 8; j++) acc[i][j] = 0.f;

    for (int k0 = 0; k0 < K; k0 += 8) {
        float4 a4 = *(const float4*)(Ab + (size_t)aRow * K + k0 + aCol);
        As[aCol + 0][aRow] = a4.x;
        As[aCol + 1][aRow] = a4.y;
        As[aCol + 2][aRow] = a4.z;
        As[aCol + 3][aRow] = a4.w;
        *(float4*)(&Bs[bRow][bCol]) = *(const float4*)(Bb + (size_t)(k0 + bRow) * N + bCol);
        __syncthreads();
#pragma unroll
        for (int kk = 0; kk < 8; kk++) {
            float rm[8], rn[8];
#pragma unroll
            for (int i = 0; i < 8; i++) rm[i] = As[kk][tr + i];
#pragma unroll
            for (int j = 0; j < 8; j++) rn[j] = Bs[kk][tc + j];
#pragma unroll
            for (int i = 0; i < 8; i++)
#pragma unroll
                for (int j = 0; j < 8; j++) acc[i][j] = fmaf(rm[i], rn[j], acc[i][j]);
        }
        __syncthreads();
    }
#pragma unroll
    for (int i = 0; i < 8; i++)
#pragma unroll
        for (int j = 0; j < 8; j += 4) {
            float4 o; o.x = acc[i][j]; o.y = acc[i][j+1]; o.z = acc[i][j+2]; o.w = acc[i][j+3];
            *(float4*)(Cb + (size_t)(tr + i) * N + tc + j) = o;
        }
}

// ---------------- scores[bh][k][q] = (K_k . Q_q) / 32 ; batched 64x64 tiles over d=64 ----------------
__global__ __launch_bounds__(256) void scores64(const float* __restrict__ Qm,
                                                const float* __restrict__ Km) {
    // grid: (qtile=32, ktile=32, bh=32)
    __shared__ float Ks[64][65];  // [d][k_local]
    __shared__ float Qs[64][65];  // [d][q_local]
    const int tid = threadIdx.x;
    const int bh = blockIdx.z;
    const int b = bh >> 4, h = bh & 15;
    const int kt = blockIdx.y * 64;
    const int qt = blockIdx.x * 64;

    const float* Kbp = Km + ((size_t)b * SEQ + kt) * LDIM + h * DH;
    const float* Qbp = Qm + ((size_t)b * SEQ + qt) * LDIM + h * DH;

    const int row = tid >> 2;              // 0..63
    const int c4  = (tid & 3) * 4;         // base d within 16-group
#pragma unroll
    for (int r = 0; r < 4; r++) {
        int d0 = c4 + 16 * r;
        float4 kv = *(const float4*)(Kbp + (size_t)row * LDIM + d0);
        float4 qv = *(const float4*)(Qbp + (size_t)row * LDIM + d0);
        Ks[d0 + 0][row] = kv.x; Ks[d0 + 1][row] = kv.y; Ks[d0 + 2][row] = kv.z; Ks[d0 + 3][row] = kv.w;
        Qs[d0 + 0][row] = qv.x; Qs[d0 + 1][row] = qv.y; Qs[d0 + 2][row] = qv.z; Qs[d0 + 3][row] = qv.w;
    }
    __syncthreads();

    const int tr = (tid >> 4) * 4;   // k_local base
    const int tc = (tid & 15) * 4;   // q_local base
    float acc[4][4];
#pragma unroll
    for (int i = 0; i < 4; i++)
#pragma unroll
        for (int j = 0; j < 4; j++) acc[i][j] = 0.f;

#pragma unroll 8
    for (int d = 0; d < 64; d++) {
        float rm[4], rn[4];
#pragma unroll
        for (int i = 0; i < 4; i++) rm[i] = Ks[d][tr + i];
#pragma unroll
        for (int j = 0; j < 4; j++) rn[j] = Qs[d][tc + j];
#pragma unroll
        for (int i = 0; i < 4; i++)
#pragma unroll
            for (int j = 0; j < 4; j++) acc[i][j] = fmaf(rm[i], rn[j], acc[i][j]);
    }

    float* outp = g_Sc + (size_t)bh * SEQ * SEQ;
#pragma unroll
    for (int i = 0; i < 4; i++) {
        float4 o;
        o.x = acc[i][0] * 0.03125f; o.y = acc[i][1] * 0.03125f;
        o.z = acc[i][2] * 0.03125f; o.w = acc[i][3] * 0.03125f;
        *(float4*)(outp + (size_t)(kt + tr + i) * SEQ + qt + tc) = o;
    }
}

// ---------------- softmax over q (last axis) per [bh][k] row of length 2048 ----------------
__global__ __launch_bounds__(256) void softmax_q() {
    const size_t rowi = blockIdx.x;
    float* p = g_Sc + rowi * SEQ;
    const int t = threadIdx.x;
    float v[8];
    float mx = -3.402823e38f;
#pragma unroll
    for (int i = 0; i < 8; i++) { v[i] = p[t + 256 * i]; mx = fmaxf(mx, v[i]); }

    __shared__ float red[256];
    red[t] = mx; __syncthreads();
    for (int s = 128; s > 0; s >>= 1) {
        if (t < s) red[t] = fmaxf(red[t], red[t + s]);
        __syncthreads();
    }
    mx = red[0];
    __syncthreads();

    float sum = 0.f;
#pragma unroll
    for (int i = 0; i < 8; i++) { v[i] = expf(v[i] - mx); sum += v[i]; }
    red[t] = sum; __syncthreads();
    for (int s = 128; s > 0; s >>= 1) {
        if (t < s) red[t] = red[t] + red[t + s];
        __syncthreads();
    }
    const float inv = 1.f / red[0];
#pragma unroll
    for (int i = 0; i < 8; i++) p[t + 256 * i] = v[i] * inv;
}

// ---------------- Z[b, q, h*64+d] = sum_k attn[bh][k][q] * V[b, k, h*64+d] ----------------
__global__ __launch_bounds__(256) void att_out(const float* __restrict__ Vm) {
    // grid: (qtile=32, bh=32)
    __shared__ float As[16][64];  // [k][q]
    __shared__ float Bs[16][64];  // [k][d]
    const int tid = threadIdx.x;
    const int bh = blockIdx.y;
    const int b = bh >> 4, h = bh & 15;
    const int qt = blockIdx.x * 64;

    const float* Ab = g_Sc + (size_t)bh * SEQ * SEQ;
    const float* Vb = Vm + ((size_t)b * SEQ) * LDIM + h * DH;

    const int lr = tid >> 4;          // 0..15 (k)
    const int lc = (tid & 15) * 4;    // 0..60
    const int tr = (tid >> 4) * 4;    // q_local base
    const int tc = (tid & 15) * 4;    // d base

    float acc[4][4];
#pragma unroll
    for (int i = 0; i < 4; i++)
#pragma unroll
        for (int j = 0; j < 4; j++) acc[i][j] = 0.f;

    for (int k0 = 0; k0 < SEQ; k0 += 16) {
        *(float4*)(&As[lr][lc]) = *(const float4*)(Ab + (size_t)(k0 + lr) * SEQ + qt + lc);
        *(float4*)(&Bs[lr][lc]) = *(const float4*)(Vb + (size_t)(k0 + lr) * LDIM + lc);
        __syncthreads();
#pragma unroll
        for (int kk = 0; kk < 16; kk++) {
            float rm[4], rn[4];
#pragma unroll
            for (int i = 0; i < 4; i++) rm[i] = As[kk][tr + i];
#pragma unroll
            for (int j = 0; j < 4; j++) rn[j] = Bs[kk][tc + j];
#pragma unroll
            for (int i = 0; i < 4; i++)
#pragma unroll
                for (int j = 0; j < 4; j++) acc[i][j] = fmaf(rm[i], rn[j], acc[i][j]);
        }
        __syncthreads();
    }
#pragma unroll
    for (int i = 0; i < 4; i++) {
        float4 o; o.x = acc[i][0]; o.y = acc[i][1]; o.z = acc[i][2]; o.w = acc[i][3];
        *(float4*)(g_Z + ((size_t)b * SEQ + qt + tr + i) * LDIM + h * DH + tc) = o;
    }
}

// ---------------- row L2 normalize (1024 cols) ----------------
__global__ __launch_bounds__(256) void l2norm_rows(const float* __restrict__ in,
                                                   float* __restrict__ out) {
    const size_t rowi = blockIdx.x;
    const float* p = in + rowi * DIM;
    float* o = out + rowi * DIM;
    const int t = threadIdx.x;
    float v[4];
    float ss = 0.f;
#pragma unroll
    for (int i = 0; i < 4; i++) { v[i] = p[t + 256 * i]; ss += v[i] * v[i]; }
    __shared__ float red[256];
    red[t] = ss; __syncthreads();
    for (int s = 128; s > 0; s >>= 1) {
        if (t < s) red[t] = red[t] + red[t + s];
        __syncthreads();
    }
    const float n = sqrtf(red[0]);
    const float sc = 1.f / fmaxf(n, 1e-12f);
#pragma unroll
    for (int i = 0; i < 4; i++) o[t + 256 * i] = v[i] * sc;
}

// ---------------- row L2 normalize + exact GELU ----------------
__global__ __launch_bounds__(256) void l2norm_gelu(const float* __restrict__ in,
                                                   float* __restrict__ out) {
    const size_t rowi = blockIdx.x;
    const float* p = in + rowi * DIM;
    float* o = out + rowi * DIM;
    const int t = threadIdx.x;
    float v[4];
    float ss = 0.f;
#pragma unroll
    for (int i = 0; i < 4; i++) { v[i] = p[t + 256 * i]; ss += v[i] * v[i]; }
    __shared__ float red[256];
    red[t] = ss; __syncthreads();
    for (int s = 128; s > 0; s >>= 1) {
        if (t < s) red[t] = red[t] + red[t + s];
        __syncthreads();
    }
    const float n = sqrtf(red[0]);
    const float sc = 1.f / fmaxf(n, 1e-12f);
#pragma unroll
    for (int i = 0; i < 4; i++) {
        float y = v[i] * sc;
        o[t + 256 * i] = 0.5f * y * (1.f + erff(y * 0.70710678118654752f));
    }
}

// ---------------- host launcher ----------------
extern "C" void kernel_launch(void* const* d_in, const int* in_sizes, int n_in,
                              void* d_out, int out_size) {
    const float* x   = (const float*)d_in[0];
    const float* Wq  = (const float*)d_in[1];
    const float* Wk  = (const float*)d_in[2];
    const float* Wv  = (const float*)d_in[3];
    const float* Wo  = (const float*)d_in[4];
    const float* Wff = (const float*)d_in[5];
    float* outp = (float*)d_out;

    float *pQ, *pK, *pV, *pZ, *pZ2;
    cudaGetSymbolAddress((void**)&pQ,  g_Q);
    cudaGetSymbolAddress((void**)&pK,  g_Kb);
    cudaGetSymbolAddress((void**)&pV,  g_V);
    cudaGetSymbolAddress((void**)&pZ,  g_Z);
    cudaGetSymbolAddress((void**)&pZ2, g_Z2);

    dim3 gW(LDIM / 128, MTOT / 128);

    // QKV projections
    sgemm128<<<gW, 256>>>(x, Wq, pQ, MTOT, LDIM, DIM);
    sgemm128<<<gW, 256>>>(x, Wk, pK, MTOT, LDIM, DIM);
    sgemm128<<<gW, 256>>>(x, Wv, pV, MTOT, LDIM, DIM);

    // scores + softmax(over q) + attn@V
    scores64<<<dim3(SEQ / 64, SEQ / 64, BHTOT), 256>>>(pQ, pK);
    softmax_q<<<BHTOT * SEQ, 256>>>();
    att_out<<<dim3(SEQ / 64, BHTOT), 256>>>(pV);

    // out proj -> normalize -> FFN -> normalize+gelu
    sgemm128<<<dim3(DIM / 128, MTOT / 128), 256>>>(pZ, Wo, pZ2, MTOT, DIM, LDIM);
    l2norm_rows<<<MTOT, 256>>>(pZ2, pZ);
    sgemm128<<<dim3(DIM / 128, MTOT / 128), 256>>>(pZ, Wff, pZ2, MTOT, DIM, DIM);
    l2norm_gelu<<<MTOT, 256>>>(pZ2, outp);
}

// round 2
// speedup vs baseline: 1.1352x; 1.1352x over previous
#include <cuda_runtime.h>
#include <math.h>

#define NBATCH 2
#define SEQ    2048
#define DIM    1024
#define LDIM   1024
#define NH     16
#define DH     64
#define MTOT   (NBATCH*SEQ)   /* 4096 */
#define BHTOT  (NBATCH*NH)    /* 32   */

typedef unsigned long long ull;

// ---------------- f32x2 packed-FMA helpers (FFMA2 SASS; fp32 bit-exact) ----------------
__device__ __forceinline__ ull pack2(float lo, float hi) {
    ull r; asm("mov.b64 %0, {%1, %2};" : "=l"(r) : "f"(lo), "f"(hi)); return r;
}
__device__ __forceinline__ ull dup2(float v) { return pack2(v, v); }
__device__ __forceinline__ float2 unpack2(ull v) {
    float2 f; asm("mov.b64 {%0, %1}, %2;" : "=f"(f.x), "=f"(f.y) : "l"(v)); return f;
}
__device__ __forceinline__ void fma2(ull& d, ull a, ull b) {
    asm("fma.rn.f32x2 %0, %1, %2, %3;" : "=l"(d) : "l"(a), "l"(b), "l"(d));
}

// ---------------- scratch (static device globals; no allocation) ----------------
__device__ float g_Q [ (size_t)MTOT * LDIM ];
__device__ float g_Kb[ (size_t)MTOT * LDIM ];
__device__ float g_V [ (size_t)MTOT * LDIM ];
__device__ float g_Sc[ (size_t)BHTOT * SEQ * SEQ ];   // 512 MB scores [bh][k][q]
__device__ float g_Z [ (size_t)MTOT * LDIM ];
__device__ float g_Z2[ (size_t)MTOT * LDIM ];

// ---------------- 128x128x8 SGEMM with FFMA2, row-major, dims % 128 == 0 ----------------
__global__ __launch_bounds__(256, 2) void sgemm128(const float* __restrict__ A,
                                                   const float* __restrict__ B,
                                                   float* __restrict__ C,
                                                   int M, int N, int K) {
    __shared__ float As[8][128];
    __shared__ float Bs[8][128];
    const int tid = threadIdx.x;
    const int bx = blockIdx.x, by = blockIdx.y;
    const float* Ab = A + (size_t)by * 128 * K;
    const float* Bb = B + bx * 128;
    float* Cb = C + (size_t)by * 128 * N + bx * 128;

    const int aRow = tid >> 1, aCol = (tid & 1) * 4;
    const int bRow = tid >> 5, bCol = (tid & 31) * 4;
    const int tr = (tid >> 4) * 8, tc = (tid & 15) * 8;

    ull acc[8][4];
#pragma unroll
    for (int i = 0; i < 8; i++)
#pragma unroll
        for (int j = 0; j < 4; j++) acc[i][j] = 0ull;

    for (int k0 = 0; k0 < K; k0 += 8) {
        float4 a4 = *(const float4*)(Ab + (size_t)aRow * K + k0 + aCol);
        As[aCol + 0][aRow] = a4.x;
        As[aCol + 1][aRow] = a4.y;
        As[aCol + 2][aRow] = a4.z;
        As[aCol + 3][aRow] = a4.w;
        *(float4*)(&Bs[bRow][bCol]) = *(const float4*)(Bb + (size_t)(k0 + bRow) * N + bCol);
        __syncthreads();
#pragma unroll
        for (int kk = 0; kk < 8; kk++) {
            float4 a0 = *(const float4*)(&As[kk][tr]);
            float4 a1 = *(const float4*)(&As[kk][tr + 4]);
            float4 b0 = *(const float4*)(&Bs[kk][tc]);
            float4 b1 = *(const float4*)(&Bs[kk][tc + 4]);
            ull n[4];
            n[0] = pack2(b0.x, b0.y); n[1] = pack2(b0.z, b0.w);
            n[2] = pack2(b1.x, b1.y); n[3] = pack2(b1.z, b1.w);
            ull m[8];
            m[0] = dup2(a0.x); m[1] = dup2(a0.y); m[2] = dup2(a0.z); m[3] = dup2(a0.w);
            m[4] = dup2(a1.x); m[5] = dup2(a1.y); m[6] = dup2(a1.z); m[7] = dup2(a1.w);
#pragma unroll
            for (int i = 0; i < 8; i++)
#pragma unroll
                for (int j = 0; j < 4; j++) fma2(acc[i][j], m[i], n[j]);
        }
        __syncthreads();
    }
#pragma unroll
    for (int i = 0; i < 8; i++) {
        float2 u0 = unpack2(acc[i][0]), u1 = unpack2(acc[i][1]);
        float2 u2 = unpack2(acc[i][2]), u3 = unpack2(acc[i][3]);
        float4 o0; o0.x = u0.x; o0.y = u0.y; o0.z = u1.x; o0.w = u1.y;
        float4 o1; o1.x = u2.x; o1.y = u2.y; o1.z = u3.x; o1.w = u3.y;
        *(float4*)(Cb + (size_t)(tr + i) * N + tc)     = o0;
        *(float4*)(Cb + (size_t)(tr + i) * N + tc + 4) = o1;
    }
}

// ---------------- scores[bh][k][q] = (K_k . Q_q)/32 ; 128x128 tile, d=64 contraction ----------------
__global__ __launch_bounds__(256, 2) void scores128(const float* __restrict__ Qm,
                                                    const float* __restrict__ Km) {
    // grid: (qtile=16, ktile=16, bh=32)
    __shared__ float Ks[32][128];  // [d][k_local]
    __shared__ float Qs[32][128];  // [d][q_local] (pre-scaled by 1/32)
    const int tid = threadIdx.x;
    const int bh = blockIdx.z;
    const int b = bh >> 4, h = bh & 15;
    const int kt = blockIdx.y * 128;
    const int qt = blockIdx.x * 128;

    const float* Kbp = Km + ((size_t)b * SEQ + kt) * LDIM + h * DH;
    const float* Qbp = Qm + ((size_t)b * SEQ + qt) * LDIM + h * DH;

    const int row = tid >> 1;              // 0..127
    const int half = (tid & 1) * 16;       // d-offset within 32-chunk
    const int tr = (tid >> 4) * 8;         // k_local base
    const int tc = (tid & 15) * 8;         // q_local base

    ull acc[8][4];
#pragma unroll
    for (int i = 0; i < 8; i++)
#pragma unroll
        for (int j = 0; j < 4; j++) acc[i][j] = 0ull;

#pragma unroll
    for (int chunk = 0; chunk < 2; chunk++) {
        const int dbase = chunk * 32;
#pragma unroll
        for (int it = 0; it < 4; it++) {
            int d0 = half + it * 4;
            float4 kv = *(const float4*)(Kbp + (size_t)row * LDIM + dbase + d0);
            float4 qv = *(const float4*)(Qbp + (size_t)row * LDIM + dbase + d0);
            Ks[d0 + 0][row] = kv.x; Ks[d0 + 1][row] = kv.y;
            Ks[d0 + 2][row] = kv.z; Ks[d0 + 3][row] = kv.w;
            Qs[d0 + 0][row] = qv.x * 0.03125f; Qs[d0 + 1][row] = qv.y * 0.03125f;
            Qs[d0 + 2][row] = qv.z * 0.03125f; Qs[d0 + 3][row] = qv.w * 0.03125f;
        }
        __syncthreads();
#pragma unroll
        for (int kk = 0; kk < 32; kk++) {
            float4 a0 = *(const float4*)(&Ks[kk][tr]);
            float4 a1 = *(const float4*)(&Ks[kk][tr + 4]);
            float4 b0 = *(const float4*)(&Qs[kk][tc]);
            float4 b1 = *(const float4*)(&Qs[kk][tc + 4]);
            ull n[4];
            n[0] = pack2(b0.x, b0.y); n[1] = pack2(b0.z, b0.w);
            n[2] = pack2(b1.x, b1.y); n[3] = pack2(b1.z, b1.w);
            ull m[8];
            m[0] = dup2(a0.x); m[1] = dup2(a0.y); m[2] = dup2(a0.z); m[3] = dup2(a0.w);
            m[4] = dup2(a1.x); m[5] = dup2(a1.y); m[6] = dup2(a1.z); m[7] = dup2(a1.w);
#pragma unroll
            for (int i = 0; i < 8; i++)
#pragma unroll
                for (int j = 0; j < 4; j++) fma2(acc[i][j], m[i], n[j]);
        }
        __syncthreads();
    }

    float* outp = g_Sc + (size_t)bh * SEQ * SEQ + (size_t)kt * SEQ + qt;
#pragma unroll
    for (int i = 0; i < 8; i++) {
        float2 u0 = unpack2(acc[i][0]), u1 = unpack2(acc[i][1]);
        float2 u2 = unpack2(acc[i][2]), u3 = unpack2(acc[i][3]);
        float4 o0; o0.x = u0.x; o0.y = u0.y; o0.z = u1.x; o0.w = u1.y;
        float4 o1; o1.x = u2.x; o1.y = u2.y; o1.z = u3.x; o1.w = u3.y;
        *(float4*)(outp + (size_t)(tr + i) * SEQ + tc)     = o0;
        *(float4*)(outp + (size_t)(tr + i) * SEQ + tc + 4) = o1;
    }
}

// ---------------- softmax over q (last axis) per [bh][k] row of length 2048 ----------------
__global__ __launch_bounds__(256) void softmax_q() {
    const size_t rowi = blockIdx.x;
    float* p = g_Sc + rowi * SEQ;
    const int t = threadIdx.x;
    float v[8];
    float mx = -3.402823e38f;
#pragma unroll
    for (int i = 0; i < 8; i++) { v[i] = p[t + 256 * i]; mx = fmaxf(mx, v[i]); }

    __shared__ float red[256];
    red[t] = mx; __syncthreads();
    for (int s = 128; s > 0; s >>= 1) {
        if (t < s) red[t] = fmaxf(red[t], red[t + s]);
        __syncthreads();
    }
    mx = red[0];
    __syncthreads();

    float sum = 0.f;
#pragma unroll
    for (int i = 0; i < 8; i++) { v[i] = expf(v[i] - mx); sum += v[i]; }
    red[t] = sum; __syncthreads();
    for (int s = 128; s > 0; s >>= 1) {
        if (t < s) red[t] = red[t] + red[t + s];
        __syncthreads();
    }
    const float inv = 1.f / red[0];
#pragma unroll
    for (int i = 0; i < 8; i++) p[t + 256 * i] = v[i] * inv;
}

// ---------------- Z[b, q, h*64+d] = sum_k attn[bh][k][q] * V[b, k, h*64+d] ----------------
// tile: q=128, d=64 (full), micro 8(q)x4(d) packed over q-pairs
__global__ __launch_bounds__(256, 2) void att_out(const float* __restrict__ Vm) {
    // grid: (qtile=16, bh=32)
    __shared__ float As[16][128];  // [k][q]
    __shared__ float Vs[16][64];   // [k][d]
    const int tid = threadIdx.x;
    const int bh = blockIdx.y;
    const int b = bh >> 4, h = bh & 15;
    const int qt = blockIdx.x * 128;

    const float* Ab = g_Sc + (size_t)bh * SEQ * SEQ + qt;
    const float* Vb = Vm + ((size_t)b * SEQ) * LDIM + h * DH;

    const int lr = tid >> 4;          // 0..15 (k)
    const int lc = (tid & 15) * 8;    // attn cols
    const int vc = (tid & 15) * 4;    // V cols
    const int tr = (tid >> 4) * 8;    // q_local base
    const int tc = (tid & 15) * 4;    // d base

    ull acc[4][4];   // [q-pair][d]
#pragma unroll
    for (int i = 0; i < 4; i++)
#pragma unroll
        for (int j = 0; j < 4; j++) acc[i][j] = 0ull;

    for (int k0 = 0; k0 < SEQ; k0 += 16) {
        *(float4*)(&As[lr][lc])     = *(const float4*)(Ab + (size_t)(k0 + lr) * SEQ + lc);
        *(float4*)(&As[lr][lc + 4]) = *(const float4*)(Ab + (size_t)(k0 + lr) * SEQ + lc + 4);
        *(float4*)(&Vs[lr][vc])     = *(const float4*)(Vb + (size_t)(k0 + lr) * LDIM + vc);
        __syncthreads();
#pragma unroll
        for (int kk = 0; kk < 16; kk++) {
            float4 a0 = *(const float4*)(&As[kk][tr]);
            float4 a1 = *(const float4*)(&As[kk][tr + 4]);
            float4 v0 = *(const float4*)(&Vs[kk][tc]);
            ull m[4];   // packed q-pairs
            m[0] = pack2(a0.x, a0.y); m[1] = pack2(a0.z, a0.w);
            m[2] = pack2(a1.x, a1.y); m[3] = pack2(a1.z, a1.w);
            ull n[4];   // duplicated d values
            n[0] = dup2(v0.x); n[1] = dup2(v0.y); n[2] = dup2(v0.z); n[3] = dup2(v0.w);
#pragma unroll
            for (int i = 0; i < 4; i++)
#pragma unroll
                for (int j = 0; j < 4; j++) fma2(acc[i][j], m[i], n[j]);
        }
        __syncthreads();
    }
#pragma unroll
    for (int i = 0; i < 4; i++) {
        float2 u0 = unpack2(acc[i][0]), u1 = unpack2(acc[i][1]);
        float2 u2 = unpack2(acc[i][2]), u3 = unpack2(acc[i][3]);
        float4 lo; lo.x = u0.x; lo.y = u1.x; lo.z = u2.x; lo.w = u3.x;  // q row tr+2i
        float4 hi; hi.x = u0.y; hi.y = u1.y; hi.z = u2.y; hi.w = u3.y;  // q row tr+2i+1
        *(float4*)(g_Z + ((size_t)b * SEQ + qt + tr + 2*i    ) * LDIM + h * DH + tc) = lo;
        *(float4*)(g_Z + ((size_t)b * SEQ + qt + tr + 2*i + 1) * LDIM + h * DH + tc) = hi;
    }
}

// ---------------- row L2 normalize (1024 cols) ----------------
__global__ __launch_bounds__(256) void l2norm_rows(const float* __restrict__ in,
                                                   float* __restrict__ out) {
    const size_t rowi = blockIdx.x;
    const float* p = in + rowi * DIM;
    float* o = out + rowi * DIM;
    const int t = threadIdx.x;
    float v[4];
    float ss = 0.f;
#pragma unroll
    for (int i = 0; i < 4; i++) { v[i] = p[t + 256 * i]; ss += v[i] * v[i]; }
    __shared__ float red[256];
    red[t] = ss; __syncthreads();
    for (int s = 128; s > 0; s >>= 1) {
        if (t < s) red[t] = red[t] + red[t + s];
        __syncthreads();
    }
    const float n = sqrtf(red[0]);
    const float sc = 1.f / fmaxf(n, 1e-12f);
#pragma unroll
    for (int i = 0; i < 4; i++) o[t + 256 * i] = v[i] * sc;
}

// ---------------- row L2 normalize + exact GELU ----------------
__global__ __launch_bounds__(256) void l2norm_gelu(const float* __restrict__ in,
                                                   float* __restrict__ out) {
    const size_t rowi = blockIdx.x;
    const float* p = in + rowi * DIM;
    float* o = out + rowi * DIM;
    const int t = threadIdx.x;
    float v[4];
    float ss = 0.f;
#pragma unroll
    for (int i = 0; i < 4; i++) { v[i] = p[t + 256 * i]; ss += v[i] * v[i]; }
    __shared__ float red[256];
    red[t] = ss; __syncthreads();
    for (int s = 128; s > 0; s >>= 1) {
        if (t < s) red[t] = red[t] + red[t + s];
        __syncthreads();
    }
    const float n = sqrtf(red[0]);
    const float sc = 1.f / fmaxf(n, 1e-12f);
#pragma unroll
    for (int i = 0; i < 4; i++) {
        float y = v[i] * sc;
        o[t + 256 * i] = 0.5f * y * (1.f + erff(y * 0.70710678118654752f));
    }
}

// ---------------- host launcher ----------------
extern "C" void kernel_launch(void* const* d_in, const int* in_sizes, int n_in,
                              void* d_out, int out_size) {
    const float* x   = (const float*)d_in[0];
    const float* Wq  = (const float*)d_in[1];
    const float* Wk  = (const float*)d_in[2];
    const float* Wv  = (const float*)d_in[3];
    const float* Wo  = (const float*)d_in[4];
    const float* Wff = (const float*)d_in[5];
    float* outp = (float*)d_out;

    float *pQ, *pK, *pV, *pZ, *pZ2;
    cudaGetSymbolAddress((void**)&pQ,  g_Q);
    cudaGetSymbolAddress((void**)&pK,  g_Kb);
    cudaGetSymbolAddress((void**)&pV,  g_V);
    cudaGetSymbolAddress((void**)&pZ,  g_Z);
    cudaGetSymbolAddress((void**)&pZ2, g_Z2);

    dim3 gW(LDIM / 128, MTOT / 128);

    // QKV projections
    sgemm128<<<gW, 256>>>(x, Wq, pQ, MTOT, LDIM, DIM);
    sgemm128<<<gW, 256>>>(x, Wk, pK, MTOT, LDIM, DIM);
    sgemm128<<<gW, 256>>>(x, Wv, pV, MTOT, LDIM, DIM);

    // scores + softmax(over q) + attn@V
    scores128<<<dim3(SEQ / 128, SEQ / 128, BHTOT), 256>>>(pQ, pK);
    softmax_q<<<BHTOT * SEQ, 256>>>();
    att_out<<<dim3(SEQ / 128, BHTOT), 256>>>(pV);

    // out proj -> normalize -> FFN -> normalize+gelu
    sgemm128<<<dim3(DIM / 128, MTOT / 128), 256>>>(pZ, Wo, pZ2, MTOT, DIM, LDIM);
    l2norm_rows<<<MTOT, 256>>>(pZ2, pZ);
    sgemm128<<<dim3(DIM / 128, MTOT / 128), 256>>>(pZ, Wff, pZ2, MTOT, DIM, DIM);
    l2norm_gelu<<<MTOT, 256>>>(pZ2, outp);
}

// round 4
// speedup vs baseline: 1.6214x; 1.4283x over previous
#include <cuda_runtime.h>
#include <cuda_bf16.h>
#include <math.h>
#include <cstdint>

#define NBATCH 2
#define SEQ    2048
#define DIM    1024
#define LDIM   1024
#define NH     16
#define DH     64
#define MTOT   (NBATCH*SEQ)   /* 4096 */
#define BHTOT  (NBATCH*NH)    /* 32   */

typedef unsigned long long ull;

// ================= f32x2 packed-FMA helpers (FFMA2; fp32 bit-exact) =================
__device__ __forceinline__ ull pack2(float lo, float hi) {
    ull r; asm("mov.b64 %0, {%1, %2};" : "=l"(r) : "f"(lo), "f"(hi)); return r;
}
__device__ __forceinline__ ull dup2(float v) { return pack2(v, v); }
__device__ __forceinline__ float2 unpack2(ull v) {
    float2 f; asm("mov.b64 {%0, %1}, %2;" : "=f"(f.x), "=f"(f.y) : "l"(v)); return f;
}
__device__ __forceinline__ void fma2(ull& d, ull a, ull b) {
    asm("fma.rn.f32x2 %0, %1, %2, %3;" : "=l"(d) : "l"(a), "l"(b), "l"(d));
}

__device__ __forceinline__ uint32_t smem_u32(const void* p) {
    uint32_t a;
    asm("{ .reg .u64 t; cvta.to.shared.u64 t, %1; cvt.u32.u64 %0, t; }" : "=r"(a) : "l"(p));
    return a;
}

// ================= scratch (static device globals; no allocation) =================
__device__ float g_Q [ (size_t)MTOT * LDIM ];
__device__ float g_Kb[ (size_t)MTOT * LDIM ];
__device__ float g_V [ (size_t)MTOT * LDIM ];
__device__ float g_Sc[ (size_t)BHTOT * SEQ * SEQ ];   // 512 MB scores [bh][k][q]
__device__ float g_Z [ (size_t)MTOT * LDIM ];
__device__ float g_Z2[ (size_t)MTOT * LDIM ];
__device__ __nv_bfloat16 g_Ahi[ (size_t)MTOT * DIM ];
__device__ __nv_bfloat16 g_Alo[ (size_t)MTOT * DIM ];
__device__ __nv_bfloat16 g_Whi[ (size_t)DIM * DIM ];   // transposed [N][K]
__device__ __nv_bfloat16 g_Wlo[ (size_t)DIM * DIM ];

// ================= bf16 split (elementwise): X -> hi, lo =================
__global__ __launch_bounds__(256) void split_bf16(const float* __restrict__ X,
                                                  __nv_bfloat16* __restrict__ hi,
                                                  __nv_bfloat16* __restrict__ lo) {
    const size_t i = ((size_t)blockIdx.x * 256 + threadIdx.x) * 4;
    float4 v = *(const float4*)(X + i);
    __nv_bfloat16 h0 = __float2bfloat16(v.x);
    __nv_bfloat16 h1 = __float2bfloat16(v.y);
    __nv_bfloat16 h2 = __float2bfloat16(v.z);
    __nv_bfloat16 h3 = __float2bfloat16(v.w);
    __nv_bfloat16 l0 = __float2bfloat16(v.x - __bfloat162float(h0));
    __nv_bfloat16 l1 = __float2bfloat16(v.y - __bfloat162float(h1));
    __nv_bfloat16 l2 = __float2bfloat16(v.z - __bfloat162float(h2));
    __nv_bfloat16 l3 = __float2bfloat16(v.w - __bfloat162float(h3));
    __nv_bfloat162* hp = (__nv_bfloat162*)(hi + i);
    __nv_bfloat162* lp = (__nv_bfloat162*)(lo + i);
    hp[0] = __nv_bfloat162(h0, h1); hp[1] = __nv_bfloat162(h2, h3);
    lp[0] = __nv_bfloat162(l0, l1); lp[1] = __nv_bfloat162(l2, l3);
}

// ================= transpose + split: W[K][N] -> Thi/Tlo [N][K] =================
__global__ __launch_bounds__(256) void tsplit(const float* __restrict__ W,
                                              __nv_bfloat16* __restrict__ Thi,
                                              __nv_bfloat16* __restrict__ Tlo) {
    __shared__ float tile[32][33];
    const int tx = threadIdx.x & 31, ty = threadIdx.x >> 5;
    const int k0 = blockIdx.y * 32, n0 = blockIdx.x * 32;
#pragma unroll
    for (int j = 0; j < 4; j++)
        tile[ty + j * 8][tx] = W[(size_t)(k0 + ty + j * 8) * DIM + n0 + tx];
    __syncthreads();
#pragma unroll
    for (int j = 0; j < 4; j++) {
        const int n = n0 + ty + j * 8, k = k0 + tx;
        float v = tile[tx][ty + j * 8];
        __nv_bfloat16 h = __float2bfloat16(v);
        Thi[(size_t)n * DIM + k] = h;
        Tlo[(size_t)n * DIM + k] = __float2bfloat16(v - __bfloat162float(h));
    }
}

// ================= HMMA bf16-split GEMM =================
// C[M][N] = A[M][K] x B[N][K]^T  (M=4096, N=1024, K=1024 fixed)
// CTA: 128x128 tile, 8 warps of 64x32. K chunked by 32, cp.async double-buffered.
// smem row stride 80B (32 data bf16 + 8 pad) -> conflict-free ldmatrix.
#define GK 1024
#define GN 1024
#define ROWB 80                       /* bytes per smem row */
#define BUFB (128 * ROWB)             /* 10240 B per operand buffer */
#define STAGEB (4 * BUFB)             /* 40960 B per stage */
#define SMEM_GEMM (2 * STAGEB)        /* 81920 B */

__device__ __forceinline__ void cp16(uint32_t dst, const void* src) {
    asm volatile("cp.async.cg.shared.global [%0], [%1], 16;" :: "r"(dst), "l"(src));
}
__device__ __forceinline__ void ldm_x4(uint32_t* r, uint32_t addr) {
    asm volatile("ldmatrix.sync.aligned.m8n8.x4.shared.b16 {%0,%1,%2,%3}, [%4];"
                 : "=r"(r[0]), "=r"(r[1]), "=r"(r[2]), "=r"(r[3]) : "r"(addr));
}
__device__ __forceinline__ void mma16816(float* c, const uint32_t* a, const uint32_t* b) {
    asm volatile(
        "mma.sync.aligned.m16n8k16.row.col.f32.bf16.bf16.f32 "
        "{%0,%1,%2,%3}, {%4,%5,%6,%7}, {%8,%9}, {%0,%1,%2,%3};"
        : "+f"(c[0]), "+f"(c[1]), "+f"(c[2]), "+f"(c[3])
        : "r"(a[0]), "r"(a[1]), "r"(a[2]), "r"(a[3]), "r"(b[0]), "r"(b[1]));
}

__global__ __launch_bounds__(256, 1)
void gemm_hmma(const __nv_bfloat16* __restrict__ Ahi, const __nv_bfloat16* __restrict__ Alo,
               const __nv_bfloat16* __restrict__ Bhi, const __nv_bfloat16* __restrict__ Blo,
               float* __restrict__ C) {
    extern __shared__ char sm[];
    const uint32_t sb = smem_u32(sm);
    const int tid = threadIdx.x;
    const int lane = tid & 31;
    const int wid = tid >> 5;
    const int m0 = blockIdx.y * 128, n0 = blockIdx.x * 128;
    const int wm = (wid & 1) * 64;    // warp m offset in tile
    const int wn = (wid >> 1) * 32;   // warp n offset in tile

    // global-load mapping: 2 iters, cid = tid + i*256; row=cid>>2, seg=cid&3 (16B)
    const int r0g = tid >> 2, s0g = tid & 3;           // iter 0
    const int r1g = (tid + 256) >> 2, s1g = tid & 3;   // iter 1 (seg same, row +64)

    // ldmatrix per-thread smem byte offsets (within an operand buffer, before kk)
    const uint32_t a_off = (uint32_t)((wm + (lane & 15)) * ROWB + ((lane >> 4) << 3) * 2);
    const uint32_t b_off = (uint32_t)((wn + ((lane >> 4) << 3) + (lane & 7)) * ROWB + (lane & 8) * 2);

    float acc[4][4][4];
#pragma unroll
    for (int i = 0; i < 4; i++)
#pragma unroll
        for (int j = 0; j < 4; j++)
#pragma unroll
            for (int e = 0; e < 4; e++) acc[i][j][e] = 0.f;

    const int NC = GK / 32;

    // ---- prologue: stage 0 loads chunk 0 ----
    {
        const int kc = 0;
        uint32_t st = sb;
        cp16(st + 0*BUFB + r0g*ROWB + s0g*16, Ahi + (size_t)(m0 + r0g)*GK + kc + s0g*8);
        cp16(st + 0*BUFB + r1g*ROWB + s1g*16, Ahi + (size_t)(m0 + r1g)*GK + kc + s1g*8);
        cp16(st + 1*BUFB + r0g*ROWB + s0g*16, Alo + (size_t)(m0 + r0g)*GK + kc + s0g*8);
        cp16(st + 1*BUFB + r1g*ROWB + s1g*16, Alo + (size_t)(m0 + r1g)*GK + kc + s1g*8);
        cp16(st + 2*BUFB + r0g*ROWB + s0g*16, Bhi + (size_t)(n0 + r0g)*GK + kc + s0g*8);
        cp16(st + 2*BUFB + r1g*ROWB + s1g*16, Bhi + (size_t)(n0 + r1g)*GK + kc + s1g*8);
        cp16(st + 3*BUFB + r0g*ROWB + s0g*16, Blo + (size_t)(n0 + r0g)*GK + kc + s0g*8);
        cp16(st + 3*BUFB + r1g*ROWB + s1g*16, Blo + (size_t)(n0 + r1g)*GK + kc + s1g*8);
        asm volatile("cp.async.commit_group;" ::: "memory");
    }

    for (int c = 0; c < NC; c++) {
        if (c + 1 < NC) {
            const int kc = (c + 1) * 32;
            uint32_t st = sb + ((c + 1) & 1) * STAGEB;
            cp16(st + 0*BUFB + r0g*ROWB + s0g*16, Ahi + (size_t)(m0 + r0g)*GK + kc + s0g*8);
            cp16(st + 0*BUFB + r1g*ROWB + s1g*16, Ahi + (size_t)(m0 + r1g)*GK + kc + s1g*8);
            cp16(st + 1*BUFB + r0g*ROWB + s0g*16, Alo + (size_t)(m0 + r0g)*GK + kc + s0g*8);
            cp16(st + 1*BUFB + r1g*ROWB + s1g*16, Alo + (size_t)(m0 + r1g)*GK + kc + s1g*8);
            cp16(st + 2*BUFB + r0g*ROWB + s0g*16, Bhi + (size_t)(n0 + r0g)*GK + kc + s0g*8);
            cp16(st + 2*BUFB + r1g*ROWB + s1g*16, Bhi + (size_t)(n0 + r1g)*GK + kc + s1g*8);
            cp16(st + 3*BUFB + r0g*ROWB + s0g*16, Blo + (size_t)(n0 + r0g)*GK + kc + s0g*8);
            cp16(st + 3*BUFB + r1g*ROWB + s1g*16, Blo + (size_t)(n0 + r1g)*GK + kc + s1g*8);
            asm volatile("cp.async.commit_group;" ::: "memory");
            asm volatile("cp.async.wait_group 1;" ::: "memory");
        } else {
            asm volatile("cp.async.wait_group 0;" ::: "memory");
        }
        __syncthreads();

        const uint32_t st = sb + (c & 1) * STAGEB;
#pragma unroll
        for (int kk = 0; kk < 2; kk++) {
            const uint32_t kb = kk * 32;  // 16 bf16 = 32 bytes
            uint32_t ahi[4][4], alo[4][4];
#pragma unroll
            for (int mt = 0; mt < 4; mt++) {
                ldm_x4(ahi[mt], st + 0*BUFB + a_off + mt * (16 * ROWB) + kb);
                ldm_x4(alo[mt], st + 1*BUFB + a_off + mt * (16 * ROWB) + kb);
            }
            uint32_t bhi[4][2], blo[4][2];
#pragma unroll
            for (int np = 0; np < 2; np++) {
                uint32_t r[4];
                ldm_x4(r, st + 2*BUFB + b_off + np * (16 * ROWB) + kb);
                bhi[2*np][0] = r[0]; bhi[2*np][1] = r[1];
                bhi[2*np+1][0] = r[2]; bhi[2*np+1][1] = r[3];
                ldm_x4(r, st + 3*BUFB + b_off + np * (16 * ROWB) + kb);
                blo[2*np][0] = r[0]; blo[2*np][1] = r[1];
                blo[2*np+1][0] = r[2]; blo[2*np+1][1] = r[3];
            }
#pragma unroll
            for (int mt = 0; mt < 4; mt++)
#pragma unroll
                for (int nt = 0; nt < 4; nt++) {
                    mma16816(acc[mt][nt], ahi[mt], bhi[nt]);
                    mma16816(acc[mt][nt], ahi[mt], blo[nt]);
                    mma16816(acc[mt][nt], alo[mt], bhi[nt]);
                }
        }
        __syncthreads();
    }

    // ---- epilogue ----
    const int g = lane >> 2, cpr = (lane & 3) * 2;
#pragma unroll
    for (int mt = 0; mt < 4; mt++)
#pragma unroll
        for (int nt = 0; nt < 4; nt++) {
            const int row = m0 + wm + mt * 16 + g;
            const int col = n0 + wn + nt * 8 + cpr;
            float2 lo_pair; lo_pair.x = acc[mt][nt][0]; lo_pair.y = acc[mt][nt][1];
            float2 hi_pair; hi_pair.x = acc[mt][nt][2]; hi_pair.y = acc[mt][nt][3];
            *(float2*)(C + (size_t)row * GN + col)       = lo_pair;
            *(float2*)(C + (size_t)(row + 8) * GN + col) = hi_pair;
        }
}

// ================= scores[bh][k][q] = (K_k . Q_q)/32 ; 128x128 tile, FFMA2 =================
__global__ __launch_bounds__(256, 2) void scores128(const float* __restrict__ Qm,
                                                    const float* __restrict__ Km) {
    __shared__ float Ks[32][128];
    __shared__ float Qs[32][128];
    const int tid = threadIdx.x;
    const int bh = blockIdx.z;
    const int b = bh >> 4, h = bh & 15;
    const int kt = blockIdx.y * 128;
    const int qt = blockIdx.x * 128;

    const float* Kbp = Km + ((size_t)b * SEQ + kt) * LDIM + h * DH;
    const float* Qbp = Qm + ((size_t)b * SEQ + qt) * LDIM + h * DH;

    const int row = tid >> 1;
    const int half = (tid & 1) * 16;
    const int tr = (tid >> 4) * 8;
    const int tc = (tid & 15) * 8;

    ull acc[8][4];
#pragma unroll
    for (int i = 0; i < 8; i++)
#pragma unroll
        for (int j = 0; j < 4; j++) acc[i][j] = 0ull;

#pragma unroll
    for (int chunk = 0; chunk < 2; chunk++) {
        const int dbase = chunk * 32;
#pragma unroll
        for (int it = 0; it < 4; it++) {
            int d0 = half + it * 4;
            float4 kv = *(const float4*)(Kbp + (size_t)row * LDIM + dbase + d0);
            float4 qv = *(const float4*)(Qbp + (size_t)row * LDIM + dbase + d0);
            Ks[d0 + 0][row] = kv.x; Ks[d0 + 1][row] = kv.y;
            Ks[d0 + 2][row] = kv.z; Ks[d0 + 3][row] = kv.w;
            Qs[d0 + 0][row] = qv.x * 0.03125f; Qs[d0 + 1][row] = qv.y * 0.03125f;
            Qs[d0 + 2][row] = qv.z * 0.03125f; Qs[d0 + 3][row] = qv.w * 0.03125f;
        }
        __syncthreads();
#pragma unroll
        for (int kk = 0; kk < 32; kk++) {
            float4 a0 = *(const float4*)(&Ks[kk][tr]);
            float4 a1 = *(const float4*)(&Ks[kk][tr + 4]);
            float4 b0 = *(const float4*)(&Qs[kk][tc]);
            float4 b1 = *(const float4*)(&Qs[kk][tc + 4]);
            ull n[4];
            n[0] = pack2(b0.x, b0.y); n[1] = pack2(b0.z, b0.w);
            n[2] = pack2(b1.x, b1.y); n[3] = pack2(b1.z, b1.w);
            ull m[8];
            m[0] = dup2(a0.x); m[1] = dup2(a0.y); m[2] = dup2(a0.z); m[3] = dup2(a0.w);
            m[4] = dup2(a1.x); m[5] = dup2(a1.y); m[6] = dup2(a1.z); m[7] = dup2(a1.w);
#pragma unroll
            for (int i = 0; i < 8; i++)
#pragma unroll
                for (int j = 0; j < 4; j++) fma2(acc[i][j], m[i], n[j]);
        }
        __syncthreads();
    }

    float* outp = g_Sc + (size_t)bh * SEQ * SEQ + (size_t)kt * SEQ + qt;
#pragma unroll
    for (int i = 0; i < 8; i++) {
        float2 u0 = unpack2(acc[i][0]), u1 = unpack2(acc[i][1]);
        float2 u2 = unpack2(acc[i][2]), u3 = unpack2(acc[i][3]);
        float4 o0; o0.x = u0.x; o0.y = u0.y; o0.z = u1.x; o0.w = u1.y;
        float4 o1; o1.x = u2.x; o1.y = u2.y; o1.z = u3.x; o1.w = u3.y;
        *(float4*)(outp + (size_t)(tr + i) * SEQ + tc)     = o0;
        *(float4*)(outp + (size_t)(tr + i) * SEQ + tc + 4) = o1;
    }
}

// ================= softmax over q (last axis) per [bh][k] row =================
__global__ __launch_bounds__(256) void softmax_q() {
    const size_t rowi = blockIdx.x;
    float* p = g_Sc + rowi * SEQ;
    const int t = threadIdx.x;
    float v[8];
    float mx = -3.402823e38f;
#pragma unroll
    for (int i = 0; i < 8; i++) { v[i] = p[t + 256 * i]; mx = fmaxf(mx, v[i]); }

    __shared__ float red[256];
    red[t] = mx; __syncthreads();
    for (int s = 128; s > 0; s >>= 1) {
        if (t < s) red[t] = fmaxf(red[t], red[t + s]);
        __syncthreads();
    }
    mx = red[0];
    __syncthreads();

    float sum = 0.f;
#pragma unroll
    for (int i = 0; i < 8; i++) { v[i] = expf(v[i] - mx); sum += v[i]; }
    red[t] = sum; __syncthreads();
    for (int s = 128; s > 0; s >>= 1) {
        if (t < s) red[t] = red[t] + red[t + s];
        __syncthreads();
    }
    const float inv = 1.f / red[0];
#pragma unroll
    for (int i = 0; i < 8; i++) p[t + 256 * i] = v[i] * inv;
}

// ================= Z[b,q,h*64+d] = sum_k attn[bh][k][q] * V[b,k,h*64+d] =================
__global__ __launch_bounds__(256, 2) void att_out(const float* __restrict__ Vm) {
    __shared__ float As[16][128];
    __shared__ float Vs[16][64];
    const int tid = threadIdx.x;
    const int bh = blockIdx.y;
    const int b = bh >> 4, h = bh & 15;
    const int qt = blockIdx.x * 128;

    const float* Ab = g_Sc + (size_t)bh * SEQ * SEQ + qt;
    const float* Vb = Vm + ((size_t)b * SEQ) * LDIM + h * DH;

    const int lr = tid >> 4;
    const int lc = (tid & 15) * 8;
    const int vc = (tid & 15) * 4;
    const int tr = (tid >> 4) * 8;
    const int tc = (tid & 15) * 4;

    ull acc[4][4];
#pragma unroll
    for (int i = 0; i < 4; i++)
#pragma unroll
        for (int j = 0; j < 4; j++) acc[i][j] = 0ull;

    for (int k0 = 0; k0 < SEQ; k0 += 16) {
        *(float4*)(&As[lr][lc])     = *(const float4*)(Ab + (size_t)(k0 + lr) * SEQ + lc);
        *(float4*)(&As[lr][lc + 4]) = *(const float4*)(Ab + (size_t)(k0 + lr) * SEQ + lc + 4);
        *(float4*)(&Vs[lr][vc])     = *(const float4*)(Vb + (size_t)(k0 + lr) * LDIM + vc);
        __syncthreads();
#pragma unroll
        for (int kk = 0; kk < 16; kk++) {
            float4 a0 = *(const float4*)(&As[kk][tr]);
            float4 a1 = *(const float4*)(&As[kk][tr + 4]);
            float4 v0 = *(const float4*)(&Vs[kk][tc]);
            ull m[4];
            m[0] = pack2(a0.x, a0.y); m[1] = pack2(a0.z, a0.w);
            m[2] = pack2(a1.x, a1.y); m[3] = pack2(a1.z, a1.w);
            ull n[4];
            n[0] = dup2(v0.x); n[1] = dup2(v0.y); n[2] = dup2(v0.z); n[3] = dup2(v0.w);
#pragma unroll
            for (int i = 0; i < 4; i++)
#pragma unroll
                for (int j = 0; j < 4; j++) fma2(acc[i][j], m[i], n[j]);
        }
        __syncthreads();
    }
#pragma unroll
    for (int i = 0; i < 4; i++) {
        float2 u0 = unpack2(acc[i][0]), u1 = unpack2(acc[i][1]);
        float2 u2 = unpack2(acc[i][2]), u3 = unpack2(acc[i][3]);
        float4 lo; lo.x = u0.x; lo.y = u1.x; lo.z = u2.x; lo.w = u3.x;
        float4 hi; hi.x = u0.y; hi.y = u1.y; hi.z = u2.y; hi.w = u3.y;
        *(float4*)(g_Z + ((size_t)b * SEQ + qt + tr + 2*i    ) * LDIM + h * DH + tc) = lo;
        *(float4*)(g_Z + ((size_t)b * SEQ + qt + tr + 2*i + 1) * LDIM + h * DH + tc) = hi;
    }
}

// ================= row L2 normalize =================
__global__ __launch_bounds__(256) void l2norm_rows(const float* __restrict__ in,
                                                   float* __restrict__ out) {
    const size_t rowi = blockIdx.x;
    const float* p = in + rowi * DIM;
    float* o = out + rowi * DIM;
    const int t = threadIdx.x;
    float v[4];
    float ss = 0.f;
#pragma unroll
    for (int i = 0; i < 4; i++) { v[i] = p[t + 256 * i]; ss += v[i] * v[i]; }
    __shared__ float red[256];
    red[t] = ss; __syncthreads();
    for (int s = 128; s > 0; s >>= 1) {
        if (t < s) red[t] = red[t] + red[t + s];
        __syncthreads();
    }
    const float n = sqrtf(red[0]);
    const float sc = 1.f / fmaxf(n, 1e-12f);
#pragma unroll
    for (int i = 0; i < 4; i++) o[t + 256 * i] = v[i] * sc;
}

// ================= row L2 normalize + exact GELU =================
__global__ __launch_bounds__(256) void l2norm_gelu(const float* __restrict__ in,
                                                   float* __restrict__ out) {
    const size_t rowi = blockIdx.x;
    const float* p = in + rowi * DIM;
    float* o = out + rowi * DIM;
    const int t = threadIdx.x;
    float v[4];
    float ss = 0.f;
#pragma unroll
    for (int i = 0; i < 4; i++) { v[i] = p[t + 256 * i]; ss += v[i] * v[i]; }
    __shared__ float red[256];
    red[t] = ss; __syncthreads();
    for (int s = 128; s > 0; s >>= 1) {
        if (t < s) red[t] = red[t] + red[t + s];
        __syncthreads();
    }
    const float n = sqrtf(red[0]);
    const float sc = 1.f / fmaxf(n, 1e-12f);
#pragma unroll
    for (int i = 0; i < 4; i++) {
        float y = v[i] * sc;
        o[t + 256 * i] = 0.5f * y * (1.f + erff(y * 0.70710678118654752f));
    }
}

// ================= host launcher =================
extern "C" void kernel_launch(void* const* d_in, const int* in_sizes, int n_in,
                              void* d_out, int out_size) {
    const float* x   = (const float*)d_in[0];
    const float* Wq  = (const float*)d_in[1];
    const float* Wk  = (const float*)d_in[2];
    const float* Wv  = (const float*)d_in[3];
    const float* Wo  = (const float*)d_in[4];
    const float* Wff = (const float*)d_in[5];
    float* outp = (float*)d_out;

    float *pQ, *pK, *pV, *pZ, *pZ2;
    __nv_bfloat16 *pAhi, *pAlo, *pWhi, *pWlo;
    cudaGetSymbolAddress((void**)&pQ,  g_Q);
    cudaGetSymbolAddress((void**)&pK,  g_Kb);
    cudaGetSymbolAddress((void**)&pV,  g_V);
    cudaGetSymbolAddress((void**)&pZ,  g_Z);
    cudaGetSymbolAddress((void**)&pZ2, g_Z2);
    cudaGetSymbolAddress((void**)&pAhi, g_Ahi);
    cudaGetSymbolAddress((void**)&pAlo, g_Alo);
    cudaGetSymbolAddress((void**)&pWhi, g_Whi);
    cudaGetSymbolAddress((void**)&pWlo, g_Wlo);

    cudaFuncSetAttribute(gemm_hmma, cudaFuncAttributeMaxDynamicSharedMemorySize, SMEM_GEMM);

    const dim3 gG(GN / 128, MTOT / 128);    // (8, 32)
    const dim3 gT(DIM / 32, DIM / 32);      // (32, 32)
    const int  splitBlocksX = (MTOT * DIM) / (256 * 4);

    // --- QKV projections on HMMA tensor path ---
    split_bf16<<<splitBlocksX, 256>>>(x, pAhi, pAlo);
    tsplit<<<gT, 256>>>(Wq, pWhi, pWlo);
    gemm_hmma<<<gG, 256, SMEM_GEMM>>>(pAhi, pAlo, pWhi, pWlo, pQ);
    tsplit<<<gT, 256>>>(Wk, pWhi, pWlo);
    gemm_hmma<<<gG, 256, SMEM_GEMM>>>(pAhi, pAlo, pWhi, pWlo, pK);
    tsplit<<<gT, 256>>>(Wv, pWhi, pWlo);
    gemm_hmma<<<gG, 256, SMEM_GEMM>>>(pAhi, pAlo, pWhi, pWlo, pV);

    // --- attention (FFMA2 path) ---
    scores128<<<dim3(SEQ / 128, SEQ / 128, BHTOT), 256>>>(pQ, pK);
    softmax_q<<<BHTOT * SEQ, 256>>>();
    att_out<<<dim3(SEQ / 128, BHTOT), 256>>>(pV);

    // --- out projection ---
    split_bf16<<<splitBlocksX, 256>>>(pZ, pAhi, pAlo);
    tsplit<<<gT, 256>>>(Wo, pWhi, pWlo);
    gemm_hmma<<<gG, 256, SMEM_GEMM>>>(pAhi, pAlo, pWhi, pWlo, pZ2);

    // --- normalize -> FFN -> normalize+gelu ---
    l2norm_rows<<<MTOT, 256>>>(pZ2, pZ);
    split_bf16<<<splitBlocksX, 256>>>(pZ, pAhi, pAlo);
    tsplit<<<gT, 256>>>(Wff, pWhi, pWlo);
    gemm_hmma<<<gG, 256, SMEM_GEMM>>>(pAhi, pAlo, pWhi, pWlo, pZ2);
    l2norm_gelu<<<MTOT, 256>>>(pZ2, outp);
}

// round 5
// speedup vs baseline: 2.2904x; 1.4126x over previous
#include <cuda_runtime.h>
#include <cuda_bf16.h>
#include <math.h>
#include <cstdint>

#define NBATCH 2
#define SEQ    2048
#define DIM    1024
#define LDIM   1024
#define NH     16
#define DH     64
#define MTOT   (NBATCH*SEQ)   /* 4096 */
#define BHTOT  (NBATCH*NH)    /* 32   */

typedef unsigned long long ull;

__device__ __forceinline__ uint32_t smem_u32(const void* p) {
    uint32_t a;
    asm("{ .reg .u64 t; cvta.to.shared.u64 t, %1; cvt.u32.u64 %0, t; }" : "=r"(a) : "l"(p));
    return a;
}

// ================= scratch (static device globals; no allocation) =================
__device__ float g_Q [ (size_t)MTOT * LDIM ];
__device__ float g_Kb[ (size_t)MTOT * LDIM ];
__device__ float g_V [ (size_t)MTOT * LDIM ];
__device__ float g_Sc[ (size_t)BHTOT * SEQ * SEQ ];   // 512 MB scores [bh][k][q] fp32
__device__ float g_Z [ (size_t)MTOT * LDIM ];
__device__ float g_Z2[ (size_t)MTOT * LDIM ];
__device__ __nv_bfloat16 g_Ahi[ (size_t)MTOT * DIM ];
__device__ __nv_bfloat16 g_Alo[ (size_t)MTOT * DIM ];
__device__ __nv_bfloat16 g_Whi[ (size_t)DIM * DIM ];
__device__ __nv_bfloat16 g_Wlo[ (size_t)DIM * DIM ];
// attention operand splits
__device__ __nv_bfloat16 g_Qhi[ (size_t)MTOT * LDIM ];
__device__ __nv_bfloat16 g_Qlo[ (size_t)MTOT * LDIM ];
__device__ __nv_bfloat16 g_Khi[ (size_t)MTOT * LDIM ];
__device__ __nv_bfloat16 g_Klo[ (size_t)MTOT * LDIM ];
__device__ __nv_bfloat16 g_Vhi[ (size_t)MTOT * LDIM ];
__device__ __nv_bfloat16 g_Vlo[ (size_t)MTOT * LDIM ];
// attn probabilities split [bh][k][q]
__device__ __nv_bfloat16 g_Phi[ (size_t)BHTOT * SEQ * SEQ ];
__device__ __nv_bfloat16 g_Plo[ (size_t)BHTOT * SEQ * SEQ ];

// ================= HMMA primitives =================
__device__ __forceinline__ void cp16(uint32_t dst, const void* src) {
    asm volatile("cp.async.cg.shared.global [%0], [%1], 16;" :: "r"(dst), "l"(src));
}
__device__ __forceinline__ void ldm_x4(uint32_t* r, uint32_t addr) {
    asm volatile("ldmatrix.sync.aligned.m8n8.x4.shared.b16 {%0,%1,%2,%3}, [%4];"
                 : "=r"(r[0]), "=r"(r[1]), "=r"(r[2]), "=r"(r[3]) : "r"(addr));
}
__device__ __forceinline__ void ldm_x4t(uint32_t* r, uint32_t addr) {
    asm volatile("ldmatrix.sync.aligned.m8n8.x4.trans.shared.b16 {%0,%1,%2,%3}, [%4];"
                 : "=r"(r[0]), "=r"(r[1]), "=r"(r[2]), "=r"(r[3]) : "r"(addr));
}
__device__ __forceinline__ void mma16816(float* c, const uint32_t* a, const uint32_t* b) {
    asm volatile(
        "mma.sync.aligned.m16n8k16.row.col.f32.bf16.bf16.f32 "
        "{%0,%1,%2,%3}, {%4,%5,%6,%7}, {%8,%9}, {%0,%1,%2,%3};"
        : "+f"(c[0]), "+f"(c[1]), "+f"(c[2]), "+f"(c[3])
        : "r"(a[0]), "r"(a[1]), "r"(a[2]), "r"(a[3]), "r"(b[0]), "r"(b[1]));
}

// ================= bf16 split (elementwise, optional scale) =================
__global__ __launch_bounds__(256) void split_bf16(const float* __restrict__ X,
                                                  __nv_bfloat16* __restrict__ hi,
                                                  __nv_bfloat16* __restrict__ lo,
                                                  float scale) {
    const size_t i = ((size_t)blockIdx.x * 256 + threadIdx.x) * 4;
    float4 v = *(const float4*)(X + i);
    v.x *= scale; v.y *= scale; v.z *= scale; v.w *= scale;
    __nv_bfloat16 h0 = __float2bfloat16(v.x);
    __nv_bfloat16 h1 = __float2bfloat16(v.y);
    __nv_bfloat16 h2 = __float2bfloat16(v.z);
    __nv_bfloat16 h3 = __float2bfloat16(v.w);
    __nv_bfloat16 l0 = __float2bfloat16(v.x - __bfloat162float(h0));
    __nv_bfloat16 l1 = __float2bfloat16(v.y - __bfloat162float(h1));
    __nv_bfloat16 l2 = __float2bfloat16(v.z - __bfloat162float(h2));
    __nv_bfloat16 l3 = __float2bfloat16(v.w - __bfloat162float(h3));
    __nv_bfloat162* hp = (__nv_bfloat162*)(hi + i);
    __nv_bfloat162* lp = (__nv_bfloat162*)(lo + i);
    hp[0] = __nv_bfloat162(h0, h1); hp[1] = __nv_bfloat162(h2, h3);
    lp[0] = __nv_bfloat162(l0, l1); lp[1] = __nv_bfloat162(l2, l3);
}

// ================= transpose + split: W[K][N] -> Thi/Tlo [N][K] =================
__global__ __launch_bounds__(256) void tsplit(const float* __restrict__ W,
                                              __nv_bfloat16* __restrict__ Thi,
                                              __nv_bfloat16* __restrict__ Tlo) {
    __shared__ float tile[32][33];
    const int tx = threadIdx.x & 31, ty = threadIdx.x >> 5;
    const int k0 = blockIdx.y * 32, n0 = blockIdx.x * 32;
#pragma unroll
    for (int j = 0; j < 4; j++)
        tile[ty + j * 8][tx] = W[(size_t)(k0 + ty + j * 8) * DIM + n0 + tx];
    __syncthreads();
#pragma unroll
    for (int j = 0; j < 4; j++) {
        const int n = n0 + ty + j * 8, k = k0 + tx;
        float v = tile[tx][ty + j * 8];
        __nv_bfloat16 h = __float2bfloat16(v);
        Thi[(size_t)n * DIM + k] = h;
        Tlo[(size_t)n * DIM + k] = __float2bfloat16(v - __bfloat162float(h));
    }
}

// ================= HMMA bf16-split dense GEMM (unchanged from R4) =================
#define GK 1024
#define GN 1024
#define ROWB 80
#define BUFB (128 * ROWB)
#define STAGEB (4 * BUFB)
#define SMEM_GEMM (2 * STAGEB)

__global__ __launch_bounds__(256, 1)
void gemm_hmma(const __nv_bfloat16* __restrict__ Ahi, const __nv_bfloat16* __restrict__ Alo,
               const __nv_bfloat16* __restrict__ Bhi, const __nv_bfloat16* __restrict__ Blo,
               float* __restrict__ C) {
    extern __shared__ char sm[];
    const uint32_t sb = smem_u32(sm);
    const int tid = threadIdx.x;
    const int lane = tid & 31;
    const int wid = tid >> 5;
    const int m0 = blockIdx.y * 128, n0 = blockIdx.x * 128;
    const int wm = (wid & 1) * 64;
    const int wn = (wid >> 1) * 32;

    const int r0g = tid >> 2, s0g = tid & 3;
    const int r1g = (tid + 256) >> 2, s1g = tid & 3;

    const uint32_t a_off = (uint32_t)((wm + (lane & 15)) * ROWB + ((lane >> 4) << 3) * 2);
    const uint32_t b_off = (uint32_t)((wn + ((lane >> 4) << 3) + (lane & 7)) * ROWB + (lane & 8) * 2);

    float acc[4][4][4];
#pragma unroll
    for (int i = 0; i < 4; i++)
#pragma unroll
        for (int j = 0; j < 4; j++)
#pragma unroll
            for (int e = 0; e < 4; e++) acc[i][j][e] = 0.f;

    const int NC = GK / 32;
    {
        uint32_t st = sb;
        cp16(st + 0*BUFB + r0g*ROWB + s0g*16, Ahi + (size_t)(m0 + r0g)*GK + s0g*8);
        cp16(st + 0*BUFB + r1g*ROWB + s1g*16, Ahi + (size_t)(m0 + r1g)*GK + s1g*8);
        cp16(st + 1*BUFB + r0g*ROWB + s0g*16, Alo + (size_t)(m0 + r0g)*GK + s0g*8);
        cp16(st + 1*BUFB + r1g*ROWB + s1g*16, Alo + (size_t)(m0 + r1g)*GK + s1g*8);
        cp16(st + 2*BUFB + r0g*ROWB + s0g*16, Bhi + (size_t)(n0 + r0g)*GK + s0g*8);
        cp16(st + 2*BUFB + r1g*ROWB + s1g*16, Bhi + (size_t)(n0 + r1g)*GK + s1g*8);
        cp16(st + 3*BUFB + r0g*ROWB + s0g*16, Blo + (size_t)(n0 + r0g)*GK + s0g*8);
        cp16(st + 3*BUFB + r1g*ROWB + s1g*16, Blo + (size_t)(n0 + r1g)*GK + s1g*8);
        asm volatile("cp.async.commit_group;" ::: "memory");
    }

    for (int c = 0; c < NC; c++) {
        if (c + 1 < NC) {
            const int kc = (c + 1) * 32;
            uint32_t st = sb + ((c + 1) & 1) * STAGEB;
            cp16(st + 0*BUFB + r0g*ROWB + s0g*16, Ahi + (size_t)(m0 + r0g)*GK + kc + s0g*8);
            cp16(st + 0*BUFB + r1g*ROWB + s1g*16, Ahi + (size_t)(m0 + r1g)*GK + kc + s1g*8);
            cp16(st + 1*BUFB + r0g*ROWB + s0g*16, Alo + (size_t)(m0 + r0g)*GK + kc + s0g*8);
            cp16(st + 1*BUFB + r1g*ROWB + s1g*16, Alo + (size_t)(m0 + r1g)*GK + kc + s1g*8);
            cp16(st + 2*BUFB + r0g*ROWB + s0g*16, Bhi + (size_t)(n0 + r0g)*GK + kc + s0g*8);
            cp16(st + 2*BUFB + r1g*ROWB + s1g*16, Bhi + (size_t)(n0 + r1g)*GK + kc + s1g*8);
            cp16(st + 3*BUFB + r0g*ROWB + s0g*16, Blo + (size_t)(n0 + r0g)*GK + kc + s0g*8);
            cp16(st + 3*BUFB + r1g*ROWB + s1g*16, Blo + (size_t)(n0 + r1g)*GK + kc + s1g*8);
            asm volatile("cp.async.commit_group;" ::: "memory");
            asm volatile("cp.async.wait_group 1;" ::: "memory");
        } else {
            asm volatile("cp.async.wait_group 0;" ::: "memory");
        }
        __syncthreads();

        const uint32_t st = sb + (c & 1) * STAGEB;
#pragma unroll
        for (int kk = 0; kk < 2; kk++) {
            const uint32_t kb = kk * 32;
            uint32_t ahi[4][4], alo[4][4];
#pragma unroll
            for (int mt = 0; mt < 4; mt++) {
                ldm_x4(ahi[mt], st + 0*BUFB + a_off + mt * (16 * ROWB) + kb);
                ldm_x4(alo[mt], st + 1*BUFB + a_off + mt * (16 * ROWB) + kb);
            }
            uint32_t bhi[4][2], blo[4][2];
#pragma unroll
            for (int np = 0; np < 2; np++) {
                uint32_t r[4];
                ldm_x4(r, st + 2*BUFB + b_off + np * (16 * ROWB) + kb);
                bhi[2*np][0] = r[0]; bhi[2*np][1] = r[1];
                bhi[2*np+1][0] = r[2]; bhi[2*np+1][1] = r[3];
                ldm_x4(r, st + 3*BUFB + b_off + np * (16 * ROWB) + kb);
                blo[2*np][0] = r[0]; blo[2*np][1] = r[1];
                blo[2*np+1][0] = r[2]; blo[2*np+1][1] = r[3];
            }
#pragma unroll
            for (int mt = 0; mt < 4; mt++)
#pragma unroll
                for (int nt = 0; nt < 4; nt++) {
                    mma16816(acc[mt][nt], ahi[mt], bhi[nt]);
                    mma16816(acc[mt][nt], ahi[mt], blo[nt]);
                    mma16816(acc[mt][nt], alo[mt], bhi[nt]);
                }
        }
        __syncthreads();
    }

    const int g = lane >> 2, cpr = (lane & 3) * 2;
#pragma unroll
    for (int mt = 0; mt < 4; mt++)
#pragma unroll
        for (int nt = 0; nt < 4; nt++) {
            const int row = m0 + wm + mt * 16 + g;
            const int col = n0 + wn + nt * 8 + cpr;
            float2 lo_pair; lo_pair.x = acc[mt][nt][0]; lo_pair.y = acc[mt][nt][1];
            float2 hi_pair; hi_pair.x = acc[mt][nt][2]; hi_pair.y = acc[mt][nt][3];
            *(float2*)(C + (size_t)row * GN + col)       = lo_pair;
            *(float2*)(C + (size_t)(row + 8) * GN + col) = hi_pair;
        }
}

// ================= HMMA scores: S[bh][k][q] = K_k . (Q/32)_q over d=64 =================
#define SC_ROWB 144
#define SC_BUF  (128 * SC_ROWB)   /* 18432 */
#define SC_TOTAL (4 * SC_BUF)     /* 73728 */

__global__ __launch_bounds__(256)
void scores_hmma(const __nv_bfloat16* __restrict__ Khi, const __nv_bfloat16* __restrict__ Klo,
                 const __nv_bfloat16* __restrict__ Qhi, const __nv_bfloat16* __restrict__ Qlo) {
    extern __shared__ char sm[];
    const uint32_t sb = smem_u32(sm);
    const int tid = threadIdx.x;
    const int lane = tid & 31;
    const int wid = tid >> 5;
    const int bh = blockIdx.z;
    const int b = bh >> 4, h = bh & 15;
    const int kt = blockIdx.y * 128;
    const int qt = blockIdx.x * 128;

    const __nv_bfloat16* Ah = Khi + ((size_t)(b * SEQ + kt)) * LDIM + h * DH;
    const __nv_bfloat16* Al = Klo + ((size_t)(b * SEQ + kt)) * LDIM + h * DH;
    const __nv_bfloat16* Bh = Qhi + ((size_t)(b * SEQ + qt)) * LDIM + h * DH;
    const __nv_bfloat16* Bl = Qlo + ((size_t)(b * SEQ + qt)) * LDIM + h * DH;

    // load all 64 contraction elems for the 4 operand buffers
#pragma unroll
    for (int i = 0; i < 4; i++) {
        const int cid = tid + i * 256;
        const int row = cid >> 3, seg = cid & 7;
        const uint32_t d = row * SC_ROWB + seg * 16;
        const size_t goff = (size_t)row * LDIM + seg * 8;
        cp16(sb + 0*SC_BUF + d, Ah + goff);
        cp16(sb + 1*SC_BUF + d, Al + goff);
        cp16(sb + 2*SC_BUF + d, Bh + goff);
        cp16(sb + 3*SC_BUF + d, Bl + goff);
    }
    asm volatile("cp.async.commit_group;" ::: "memory");
    asm volatile("cp.async.wait_group 0;" ::: "memory");
    __syncthreads();

    const int wm = (wid & 1) * 64;
    const int wn = (wid >> 1) * 32;
    const uint32_t a_off = (uint32_t)((wm + (lane & 15)) * SC_ROWB + ((lane >> 4) << 3) * 2);
    const uint32_t b_off = (uint32_t)((wn + ((lane >> 4) << 3) + (lane & 7)) * SC_ROWB + (lane & 8) * 2);

    float acc[4][4][4];
#pragma unroll
    for (int i = 0; i < 4; i++)
#pragma unroll
        for (int j = 0; j < 4; j++)
#pragma unroll
            for (int e = 0; e < 4; e++) acc[i][j][e] = 0.f;

#pragma unroll
    for (int kk = 0; kk < 4; kk++) {
        const uint32_t kb = kk * 32;
        uint32_t ahi[4][4], alo[4][4];
#pragma unroll
        for (int mt = 0; mt < 4; mt++) {
            ldm_x4(ahi[mt], sb + 0*SC_BUF + a_off + mt * (16 * SC_ROWB) + kb);
            ldm_x4(alo[mt], sb + 1*SC_BUF + a_off + mt * (16 * SC_ROWB) + kb);
        }
        uint32_t bhi[4][2], blo[4][2];
#pragma unroll
        for (int np = 0; np < 2; np++) {
            uint32_t r[4];
            ldm_x4(r, sb + 2*SC_BUF + b_off + np * (16 * SC_ROWB) + kb);
            bhi[2*np][0] = r[0]; bhi[2*np][1] = r[1];
            bhi[2*np+1][0] = r[2]; bhi[2*np+1][1] = r[3];
            ldm_x4(r, sb + 3*SC_BUF + b_off + np * (16 * SC_ROWB) + kb);
            blo[2*np][0] = r[0]; blo[2*np][1] = r[1];
            blo[2*np+1][0] = r[2]; blo[2*np+1][1] = r[3];
        }
#pragma unroll
        for (int mt = 0; mt < 4; mt++)
#pragma unroll
            for (int nt = 0; nt < 4; nt++) {
                mma16816(acc[mt][nt], ahi[mt], bhi[nt]);
                mma16816(acc[mt][nt], ahi[mt], blo[nt]);
                mma16816(acc[mt][nt], alo[mt], bhi[nt]);
            }
    }

    float* outp = g_Sc + (size_t)bh * SEQ * SEQ;
    const int g = lane >> 2, cpr = (lane & 3) * 2;
#pragma unroll
    for (int mt = 0; mt < 4; mt++)
#pragma unroll
        for (int nt = 0; nt < 4; nt++) {
            const int row = kt + wm + mt * 16 + g;
            const int col = qt + wn + nt * 8 + cpr;
            float2 p0; p0.x = acc[mt][nt][0]; p0.y = acc[mt][nt][1];
            float2 p1; p1.x = acc[mt][nt][2]; p1.y = acc[mt][nt][3];
            *(float2*)(outp + (size_t)row * SEQ + col)       = p0;
            *(float2*)(outp + (size_t)(row + 8) * SEQ + col) = p1;
        }
}

// ================= softmax over q; writes attn as bf16 hi/lo =================
__global__ __launch_bounds__(256) void softmax_q(__nv_bfloat16* __restrict__ Phi,
                                                 __nv_bfloat16* __restrict__ Plo) {
    const size_t rowi = blockIdx.x;
    const float* p = g_Sc + rowi * SEQ;
    const int t = threadIdx.x;
    float v[8];
    float mx = -3.402823e38f;
#pragma unroll
    for (int i = 0; i < 8; i++) { v[i] = p[t + 256 * i]; mx = fmaxf(mx, v[i]); }

    __shared__ float red[256];
    red[t] = mx; __syncthreads();
    for (int s = 128; s > 0; s >>= 1) {
        if (t < s) red[t] = fmaxf(red[t], red[t + s]);
        __syncthreads();
    }
    mx = red[0];
    __syncthreads();

    float sum = 0.f;
#pragma unroll
    for (int i = 0; i < 8; i++) { v[i] = expf(v[i] - mx); sum += v[i]; }
    red[t] = sum; __syncthreads();
    for (int s = 128; s > 0; s >>= 1) {
        if (t < s) red[t] = red[t] + red[t + s];
        __syncthreads();
    }
    const float inv = 1.f / red[0];
#pragma unroll
    for (int i = 0; i < 8; i++) {
        const float w = v[i] * inv;
        const __nv_bfloat16 h = __float2bfloat16(w);
        Phi[rowi * SEQ + t + 256 * i] = h;
        Plo[rowi * SEQ + t + 256 * i] = __float2bfloat16(w - __bfloat162float(h));
    }
}

// ================= HMMA att_out: Z[b,q,h*64+d] = sum_k P[bh][k][q] * V[b,k,h*64+d] =================
// A = P^T via ldmatrix.trans, B = V^T via ldmatrix.trans. k chunks of 32, double-buffered.
#define AO_AROW 272
#define AO_ABUF (32 * AO_AROW)   /* 8704  */
#define AO_VROW 144
#define AO_VBUF (32 * AO_VROW)   /* 4608  */
#define AO_PHI 0
#define AO_PLO AO_ABUF
#define AO_VHI (2 * AO_ABUF)
#define AO_VLO (2 * AO_ABUF + AO_VBUF)
#define AO_STAGE (2 * AO_ABUF + 2 * AO_VBUF)  /* 26624 */
#define AO_TOTAL (2 * AO_STAGE)               /* 53248 */

__global__ __launch_bounds__(256)
void att_out_hmma(const __nv_bfloat16* __restrict__ Phi, const __nv_bfloat16* __restrict__ Plo,
                  const __nv_bfloat16* __restrict__ Vhi, const __nv_bfloat16* __restrict__ Vlo) {
    extern __shared__ char sm[];
    const uint32_t sb = smem_u32(sm);
    const int tid = threadIdx.x;
    const int lane = tid & 31;
    const int wid = tid >> 5;
    const int qt = blockIdx.x * 128;
    const int bh = blockIdx.y;
    const int b = bh >> 4, h = bh & 15;

    const __nv_bfloat16* Pbh = Phi + (size_t)bh * SEQ * SEQ + qt;
    const __nv_bfloat16* Pbl = Plo + (size_t)bh * SEQ * SEQ + qt;
    const __nv_bfloat16* Vbh = Vhi + ((size_t)b * SEQ) * LDIM + h * DH;
    const __nv_bfloat16* Vbl = Vlo + ((size_t)b * SEQ) * LDIM + h * DH;

    // global-load thread mapping
    const int pr0 = tid >> 4, ps0 = tid & 15;               // P iter 0: rows 0..15
    const int pr1 = (tid + 256) >> 4, ps1 = tid & 15;       // P iter 1: rows 16..31
    const int vr = tid >> 3, vs = tid & 7;                  // V: rows 0..31

    // warp tiling: 4 warps in q (32 each), 2 warps in d (32 each)
    const int wm = (wid & 3) * 32;
    const int wn = (wid >> 2) * 32;

    // ldmatrix.trans address offsets
    const uint32_t a_tr = (uint32_t)(((lane & 7) + ((lane >> 4) << 3)) * AO_AROW + (wm + (lane & 8)) * 2);
    const uint32_t b_tr = (uint32_t)(((lane & 7) + (lane & 8)) * AO_VROW + (wn + ((lane >> 4) << 3)) * 2);

    float acc[2][4][4];
#pragma unroll
    for (int i = 0; i < 2; i++)
#pragma unroll
        for (int j = 0; j < 4; j++)
#pragma unroll
            for (int e = 0; e < 4; e++) acc[i][j][e] = 0.f;

    const int NC = SEQ / 32;   // 64

    // prologue: chunk 0 -> stage 0
    {
        const int k0 = 0;
        const uint32_t st = sb;
        cp16(st + AO_PHI + pr0*AO_AROW + ps0*16, Pbh + (size_t)(k0 + pr0) * SEQ + ps0*8);
        cp16(st + AO_PHI + pr1*AO_AROW + ps1*16, Pbh + (size_t)(k0 + pr1) * SEQ + ps1*8);
        cp16(st + AO_PLO + pr0*AO_AROW + ps0*16, Pbl + (size_t)(k0 + pr0) * SEQ + ps0*8);
        cp16(st + AO_PLO + pr1*AO_AROW + ps1*16, Pbl + (size_t)(k0 + pr1) * SEQ + ps1*8);
        cp16(st + AO_VHI + vr*AO_VROW + vs*16,   Vbh + (size_t)(k0 + vr) * LDIM + vs*8);
        cp16(st + AO_VLO + vr*AO_VROW + vs*16,   Vbl + (size_t)(k0 + vr) * LDIM + vs*8);
        asm volatile("cp.async.commit_group;" ::: "memory");
    }

    for (int c = 0; c < NC; c++) {
        if (c + 1 < NC) {
            const int k0 = (c + 1) * 32;
            const uint32_t st = sb + ((c + 1) & 1) * AO_STAGE;
            cp16(st + AO_PHI + pr0*AO_AROW + ps0*16, Pbh + (size_t)(k0 + pr0) * SEQ + ps0*8);
            cp16(st + AO_PHI + pr1*AO_AROW + ps1*16, Pbh + (size_t)(k0 + pr1) * SEQ + ps1*8);
            cp16(st + AO_PLO + pr0*AO_AROW + ps0*16, Pbl + (size_t)(k0 + pr0) * SEQ + ps0*8);
            cp16(st + AO_PLO + pr1*AO_AROW + ps1*16, Pbl + (size_t)(k0 + pr1) * SEQ + ps1*8);
            cp16(st + AO_VHI + vr*AO_VROW + vs*16,   Vbh + (size_t)(k0 + vr) * LDIM + vs*8);
            cp16(st + AO_VLO + vr*AO_VROW + vs*16,   Vbl + (size_t)(k0 + vr) * LDIM + vs*8);
            asm volatile("cp.async.commit_group;" ::: "memory");
            asm volatile("cp.async.wait_group 1;" ::: "memory");
        } else {
            asm volatile("cp.async.wait_group 0;" ::: "memory");
        }
        __syncthreads();

        const uint32_t st = sb + (c & 1) * AO_STAGE;
#pragma unroll
        for (int kk = 0; kk < 2; kk++) {
            uint32_t ah[2][4], al[2][4];
#pragma unroll
            for (int mt = 0; mt < 2; mt++) {
                ldm_x4t(ah[mt], st + AO_PHI + a_tr + kk * (16 * AO_AROW) + mt * 32);
                ldm_x4t(al[mt], st + AO_PLO + a_tr + kk * (16 * AO_AROW) + mt * 32);
            }
            uint32_t bh_[4][2], bl_[4][2];
#pragma unroll
            for (int np = 0; np < 2; np++) {
                uint32_t r[4];
                ldm_x4t(r, st + AO_VHI + b_tr + kk * (16 * AO_VROW) + np * 32);
                bh_[2*np][0] = r[0]; bh_[2*np][1] = r[1];
                bh_[2*np+1][0] = r[2]; bh_[2*np+1][1] = r[3];
                ldm_x4t(r, st + AO_VLO + b_tr + kk * (16 * AO_VROW) + np * 32);
                bl_[2*np][0] = r[0]; bl_[2*np][1] = r[1];
                bl_[2*np+1][0] = r[2]; bl_[2*np+1][1] = r[3];
            }
#pragma unroll
            for (int mt = 0; mt < 2; mt++)
#pragma unroll
                for (int nt = 0; nt < 4; nt++) {
                    mma16816(acc[mt][nt], ah[mt], bh_[nt]);
                    mma16816(acc[mt][nt], ah[mt], bl_[nt]);
                    mma16816(acc[mt][nt], al[mt], bh_[nt]);
                }
        }
        __syncthreads();
    }

    const int g = lane >> 2, cpr = (lane & 3) * 2;
#pragma unroll
    for (int mt = 0; mt < 2; mt++)
#pragma unroll
        for (int nt = 0; nt < 4; nt++) {
            const int q = qt + wm + mt * 16 + g;
            const int col = wn + nt * 8 + cpr;
            float2 p0; p0.x = acc[mt][nt][0]; p0.y = acc[mt][nt][1];
            float2 p1; p1.x = acc[mt][nt][2]; p1.y = acc[mt][nt][3];
            *(float2*)(g_Z + ((size_t)b * SEQ + q)     * LDIM + h * DH + col) = p0;
            *(float2*)(g_Z + ((size_t)b * SEQ + q + 8) * LDIM + h * DH + col) = p1;
        }
}

// ================= row L2 normalize =================
__global__ __launch_bounds__(256) void l2norm_rows(const float* __restrict__ in,
                                                   float* __restrict__ out) {
    const size_t rowi = blockIdx.x;
    const float* p = in + rowi * DIM;
    float* o = out + rowi * DIM;
    const int t = threadIdx.x;
    float v[4];
    float ss = 0.f;
#pragma unroll
    for (int i = 0; i < 4; i++) { v[i] = p[t + 256 * i]; ss += v[i] * v[i]; }
    __shared__ float red[256];
    red[t] = ss; __syncthreads();
    for (int s = 128; s > 0; s >>= 1) {
        if (t < s) red[t] = red[t] + red[t + s];
        __syncthreads();
    }
    const float n = sqrtf(red[0]);
    const float sc = 1.f / fmaxf(n, 1e-12f);
#pragma unroll
    for (int i = 0; i < 4; i++) o[t + 256 * i] = v[i] * sc;
}

// ================= row L2 normalize + exact GELU =================
__global__ __launch_bounds__(256) void l2norm_gelu(const float* __restrict__ in,
                                                   float* __restrict__ out) {
    const size_t rowi = blockIdx.x;
    const float* p = in + rowi * DIM;
    float* o = out + rowi * DIM;
    const int t = threadIdx.x;
    float v[4];
    float ss = 0.f;
#pragma unroll
    for (int i = 0; i < 4; i++) { v[i] = p[t + 256 * i]; ss += v[i] * v[i]; }
    __shared__ float red[256];
    red[t] = ss; __syncthreads();
    for (int s = 128; s > 0; s >>= 1) {
        if (t < s) red[t] = red[t] + red[t + s];
        __syncthreads();
    }
    const float n = sqrtf(red[0]);
    const float sc = 1.f / fmaxf(n, 1e-12f);
#pragma unroll
    for (int i = 0; i < 4; i++) {
        float y = v[i] * sc;
        o[t + 256 * i] = 0.5f * y * (1.f + erff(y * 0.70710678118654752f));
    }
}

// ================= host launcher =================
extern "C" void kernel_launch(void* const* d_in, const int* in_sizes, int n_in,
                              void* d_out, int out_size) {
    const float* x   = (const float*)d_in[0];
    const float* Wq  = (const float*)d_in[1];
    const float* Wk  = (const float*)d_in[2];
    const float* Wv  = (const float*)d_in[3];
    const float* Wo  = (const float*)d_in[4];
    const float* Wff = (const float*)d_in[5];
    float* outp = (float*)d_out;

    float *pQ, *pK, *pV, *pZ, *pZ2;
    __nv_bfloat16 *pAhi, *pAlo, *pWhi, *pWlo;
    __nv_bfloat16 *pQhi, *pQlo, *pKhi, *pKlo, *pVhi, *pVlo, *pPhi, *pPlo;
    cudaGetSymbolAddress((void**)&pQ,  g_Q);
    cudaGetSymbolAddress((void**)&pK,  g_Kb);
    cudaGetSymbolAddress((void**)&pV,  g_V);
    cudaGetSymbolAddress((void**)&pZ,  g_Z);
    cudaGetSymbolAddress((void**)&pZ2, g_Z2);
    cudaGetSymbolAddress((void**)&pAhi, g_Ahi);
    cudaGetSymbolAddress((void**)&pAlo, g_Alo);
    cudaGetSymbolAddress((void**)&pWhi, g_Whi);
    cudaGetSymbolAddress((void**)&pWlo, g_Wlo);
    cudaGetSymbolAddress((void**)&pQhi, g_Qhi);
    cudaGetSymbolAddress((void**)&pQlo, g_Qlo);
    cudaGetSymbolAddress((void**)&pKhi, g_Khi);
    cudaGetSymbolAddress((void**)&pKlo, g_Klo);
    cudaGetSymbolAddress((void**)&pVhi, g_Vhi);
    cudaGetSymbolAddress((void**)&pVlo, g_Vlo);
    cudaGetSymbolAddress((void**)&pPhi, g_Phi);
    cudaGetSymbolAddress((void**)&pPlo, g_Plo);

    cudaFuncSetAttribute(gemm_hmma,    cudaFuncAttributeMaxDynamicSharedMemorySize, SMEM_GEMM);
    cudaFuncSetAttribute(scores_hmma,  cudaFuncAttributeMaxDynamicSharedMemorySize, SC_TOTAL);
    cudaFuncSetAttribute(att_out_hmma, cudaFuncAttributeMaxDynamicSharedMemorySize, AO_TOTAL);

    const dim3 gG(GN / 128, MTOT / 128);    // (8, 32)
    const dim3 gT(DIM / 32, DIM / 32);      // (32, 32)
    const int  splitBlocksX = (MTOT * DIM) / (256 * 4);

    // --- QKV projections (HMMA) ---
    split_bf16<<<splitBlocksX, 256>>>(x, pAhi, pAlo, 1.0f);
    tsplit<<<gT, 256>>>(Wq, pWhi, pWlo);
    gemm_hmma<<<gG, 256, SMEM_GEMM>>>(pAhi, pAlo, pWhi, pWlo, pQ);
    tsplit<<<gT, 256>>>(Wk, pWhi, pWlo);
    gemm_hmma<<<gG, 256, SMEM_GEMM>>>(pAhi, pAlo, pWhi, pWlo, pK);
    tsplit<<<gT, 256>>>(Wv, pWhi, pWlo);
    gemm_hmma<<<gG, 256, SMEM_GEMM>>>(pAhi, pAlo, pWhi, pWlo, pV);

    // --- attention operand splits (Q pre-scaled by 1/32) ---
    split_bf16<<<splitBlocksX, 256>>>(pQ, pQhi, pQlo, 0.03125f);
    split_bf16<<<splitBlocksX, 256>>>(pK, pKhi, pKlo, 1.0f);
    split_bf16<<<splitBlocksX, 256>>>(pV, pVhi, pVlo, 1.0f);

    // --- attention (HMMA) ---
    scores_hmma<<<dim3(SEQ / 128, SEQ / 128, BHTOT), 256, SC_TOTAL>>>(pKhi, pKlo, pQhi, pQlo);
    softmax_q<<<BHTOT * SEQ, 256>>>(pPhi, pPlo);
    att_out_hmma<<<dim3(SEQ / 128, BHTOT), 256, AO_TOTAL>>>(pPhi, pPlo, pVhi, pVlo);

    // --- out projection ---
    split_bf16<<<splitBlocksX, 256>>>(pZ, pAhi, pAlo, 1.0f);
    tsplit<<<gT, 256>>>(Wo, pWhi, pWlo);
    gemm_hmma<<<gG, 256, SMEM_GEMM>>>(pAhi, pAlo, pWhi, pWlo, pZ2);

    // --- normalize -> FFN -> normalize+gelu ---
    l2norm_rows<<<MTOT, 256>>>(pZ2, pZ);
    split_bf16<<<splitBlocksX, 256>>>(pZ, pAhi, pAlo, 1.0f);
    tsplit<<<gT, 256>>>(Wff, pWhi, pWlo);
    gemm_hmma<<<gG, 256, SMEM_GEMM>>>(pAhi, pAlo, pWhi, pWlo, pZ2);
    l2norm_gelu<<<MTOT, 256>>>(pZ2, outp);
}

// round 6
// speedup vs baseline: 2.5328x; 1.1059x over previous
#include <cuda_runtime.h>
#include <cuda_bf16.h>
#include <math.h>
#include <cstdint>

#define NBATCH 2
#define SEQ    2048
#define DIM    1024
#define LDIM   1024
#define NH     16
#define DH     64
#define MTOT   (NBATCH*SEQ)   /* 4096 */
#define BHTOT  (NBATCH*NH)    /* 32   */

__device__ __forceinline__ uint32_t smem_u32(const void* p) {
    uint32_t a;
    asm("{ .reg .u64 t; cvta.to.shared.u64 t, %1; cvt.u32.u64 %0, t; }" : "=r"(a) : "l"(p));
    return a;
}

// ================= scratch (static device globals; no allocation) =================
__device__ float g_Q [ (size_t)MTOT * LDIM ];
__device__ float g_Kb[ (size_t)MTOT * LDIM ];
__device__ float g_V [ (size_t)MTOT * LDIM ];
__device__ float g_Z [ (size_t)MTOT * LDIM ];
__device__ float g_Z2[ (size_t)MTOT * LDIM ];
__device__ __nv_bfloat16 g_Ahi[ (size_t)MTOT * DIM ];
__device__ __nv_bfloat16 g_Alo[ (size_t)MTOT * DIM ];
__device__ __nv_bfloat16 g_Whi[ (size_t)DIM * DIM ];
__device__ __nv_bfloat16 g_Wlo[ (size_t)DIM * DIM ];
// attention operand splits
__device__ __nv_bfloat16 g_Qhi[ (size_t)MTOT * LDIM ];
__device__ __nv_bfloat16 g_Qlo[ (size_t)MTOT * LDIM ];
__device__ __nv_bfloat16 g_Khi[ (size_t)MTOT * LDIM ];
__device__ __nv_bfloat16 g_Klo[ (size_t)MTOT * LDIM ];
// unnormalized exp(scores), bf16 split [bh][k][q]
__device__ __nv_bfloat16 g_Ehi[ (size_t)BHTOT * SEQ * SEQ ];
__device__ __nv_bfloat16 g_Elo[ (size_t)BHTOT * SEQ * SEQ ];
// per-(bh, qtile) partial row sums, and inverse row sums
__device__ float g_Spart[ (size_t)BHTOT * (SEQ/128) * SEQ ];
__device__ float g_Sinv [ (size_t)BHTOT * SEQ ];
// V/S split, layout [bh][k][DH]
__device__ __nv_bfloat16 g_VShi[ (size_t)BHTOT * SEQ * DH ];
__device__ __nv_bfloat16 g_VSlo[ (size_t)BHTOT * SEQ * DH ];

// ================= HMMA primitives =================
__device__ __forceinline__ void cp16(uint32_t dst, const void* src) {
    asm volatile("cp.async.cg.shared.global [%0], [%1], 16;" :: "r"(dst), "l"(src));
}
__device__ __forceinline__ void ldm_x4(uint32_t* r, uint32_t addr) {
    asm volatile("ldmatrix.sync.aligned.m8n8.x4.shared.b16 {%0,%1,%2,%3}, [%4];"
                 : "=r"(r[0]), "=r"(r[1]), "=r"(r[2]), "=r"(r[3]) : "r"(addr));
}
__device__ __forceinline__ void ldm_x4t(uint32_t* r, uint32_t addr) {
    asm volatile("ldmatrix.sync.aligned.m8n8.x4.trans.shared.b16 {%0,%1,%2,%3}, [%4];"
                 : "=r"(r[0]), "=r"(r[1]), "=r"(r[2]), "=r"(r[3]) : "r"(addr));
}
__device__ __forceinline__ void mma16816(float* c, const uint32_t* a, const uint32_t* b) {
    asm volatile(
        "mma.sync.aligned.m16n8k16.row.col.f32.bf16.bf16.f32 "
        "{%0,%1,%2,%3}, {%4,%5,%6,%7}, {%8,%9}, {%0,%1,%2,%3};"
        : "+f"(c[0]), "+f"(c[1]), "+f"(c[2]), "+f"(c[3])
        : "r"(a[0]), "r"(a[1]), "r"(a[2]), "r"(a[3]), "r"(b[0]), "r"(b[1]));
}

// ================= bf16 split (elementwise, optional scale) =================
__global__ __launch_bounds__(256) void split_bf16(const float* __restrict__ X,
                                                  __nv_bfloat16* __restrict__ hi,
                                                  __nv_bfloat16* __restrict__ lo,
                                                  float scale) {
    const size_t i = ((size_t)blockIdx.x * 256 + threadIdx.x) * 4;
    float4 v = *(const float4*)(X + i);
    v.x *= scale; v.y *= scale; v.z *= scale; v.w *= scale;
    __nv_bfloat16 h0 = __float2bfloat16(v.x);
    __nv_bfloat16 h1 = __float2bfloat16(v.y);
    __nv_bfloat16 h2 = __float2bfloat16(v.z);
    __nv_bfloat16 h3 = __float2bfloat16(v.w);
    __nv_bfloat16 l0 = __float2bfloat16(v.x - __bfloat162float(h0));
    __nv_bfloat16 l1 = __float2bfloat16(v.y - __bfloat162float(h1));
    __nv_bfloat16 l2 = __float2bfloat16(v.z - __bfloat162float(h2));
    __nv_bfloat16 l3 = __float2bfloat16(v.w - __bfloat162float(h3));
    __nv_bfloat162* hp = (__nv_bfloat162*)(hi + i);
    __nv_bfloat162* lp = (__nv_bfloat162*)(lo + i);
    hp[0] = __nv_bfloat162(h0, h1); hp[1] = __nv_bfloat162(h2, h3);
    lp[0] = __nv_bfloat162(l0, l1); lp[1] = __nv_bfloat162(l2, l3);
}

// ================= transpose + split: W[K][N] -> Thi/Tlo [N][K] =================
__global__ __launch_bounds__(256) void tsplit(const float* __restrict__ W,
                                              __nv_bfloat16* __restrict__ Thi,
                                              __nv_bfloat16* __restrict__ Tlo) {
    __shared__ float tile[32][33];
    const int tx = threadIdx.x & 31, ty = threadIdx.x >> 5;
    const int k0 = blockIdx.y * 32, n0 = blockIdx.x * 32;
#pragma unroll
    for (int j = 0; j < 4; j++)
        tile[ty + j * 8][tx] = W[(size_t)(k0 + ty + j * 8) * DIM + n0 + tx];
    __syncthreads();
#pragma unroll
    for (int j = 0; j < 4; j++) {
        const int n = n0 + ty + j * 8, k = k0 + tx;
        float v = tile[tx][ty + j * 8];
        __nv_bfloat16 h = __float2bfloat16(v);
        Thi[(size_t)n * DIM + k] = h;
        Tlo[(size_t)n * DIM + k] = __float2bfloat16(v - __bfloat162float(h));
    }
}

// ================= HMMA bf16-split dense GEMM =================
#define GK 1024
#define GN 1024
#define ROWB 80
#define BUFB (128 * ROWB)
#define STAGEB (4 * BUFB)
#define SMEM_GEMM (2 * STAGEB)

__global__ __launch_bounds__(256, 1)
void gemm_hmma(const __nv_bfloat16* __restrict__ Ahi, const __nv_bfloat16* __restrict__ Alo,
               const __nv_bfloat16* __restrict__ Bhi, const __nv_bfloat16* __restrict__ Blo,
               float* __restrict__ C) {
    extern __shared__ char sm[];
    const uint32_t sb = smem_u32(sm);
    const int tid = threadIdx.x;
    const int lane = tid & 31;
    const int wid = tid >> 5;
    const int m0 = blockIdx.y * 128, n0 = blockIdx.x * 128;
    const int wm = (wid & 1) * 64;
    const int wn = (wid >> 1) * 32;

    const int r0g = tid >> 2, s0g = tid & 3;
    const int r1g = (tid + 256) >> 2, s1g = tid & 3;

    const uint32_t a_off = (uint32_t)((wm + (lane & 15)) * ROWB + ((lane >> 4) << 3) * 2);
    const uint32_t b_off = (uint32_t)((wn + ((lane >> 4) << 3) + (lane & 7)) * ROWB + (lane & 8) * 2);

    float acc[4][4][4];
#pragma unroll
    for (int i = 0; i < 4; i++)
#pragma unroll
        for (int j = 0; j < 4; j++)
#pragma unroll
            for (int e = 0; e < 4; e++) acc[i][j][e] = 0.f;

    const int NC = GK / 32;
    {
        uint32_t st = sb;
        cp16(st + 0*BUFB + r0g*ROWB + s0g*16, Ahi + (size_t)(m0 + r0g)*GK + s0g*8);
        cp16(st + 0*BUFB + r1g*ROWB + s1g*16, Ahi + (size_t)(m0 + r1g)*GK + s1g*8);
        cp16(st + 1*BUFB + r0g*ROWB + s0g*16, Alo + (size_t)(m0 + r0g)*GK + s0g*8);
        cp16(st + 1*BUFB + r1g*ROWB + s1g*16, Alo + (size_t)(m0 + r1g)*GK + s1g*8);
        cp16(st + 2*BUFB + r0g*ROWB + s0g*16, Bhi + (size_t)(n0 + r0g)*GK + s0g*8);
        cp16(st + 2*BUFB + r1g*ROWB + s1g*16, Bhi + (size_t)(n0 + r1g)*GK + s1g*8);
        cp16(st + 3*BUFB + r0g*ROWB + s0g*16, Blo + (size_t)(n0 + r0g)*GK + s0g*8);
        cp16(st + 3*BUFB + r1g*ROWB + s1g*16, Blo + (size_t)(n0 + r1g)*GK + s1g*8);
        asm volatile("cp.async.commit_group;" ::: "memory");
    }

    for (int c = 0; c < NC; c++) {
        if (c + 1 < NC) {
            const int kc = (c + 1) * 32;
            uint32_t st = sb + ((c + 1) & 1) * STAGEB;
            cp16(st + 0*BUFB + r0g*ROWB + s0g*16, Ahi + (size_t)(m0 + r0g)*GK + kc + s0g*8);
            cp16(st + 0*BUFB + r1g*ROWB + s1g*16, Ahi + (size_t)(m0 + r1g)*GK + kc + s1g*8);
            cp16(st + 1*BUFB + r0g*ROWB + s0g*16, Alo + (size_t)(m0 + r0g)*GK + kc + s0g*8);
            cp16(st + 1*BUFB + r1g*ROWB + s1g*16, Alo + (size_t)(m0 + r1g)*GK + kc + s1g*8);
            cp16(st + 2*BUFB + r0g*ROWB + s0g*16, Bhi + (size_t)(n0 + r0g)*GK + kc + s0g*8);
            cp16(st + 2*BUFB + r1g*ROWB + s1g*16, Bhi + (size_t)(n0 + r1g)*GK + kc + s1g*8);
            cp16(st + 3*BUFB + r0g*ROWB + s0g*16, Blo + (size_t)(n0 + r0g)*GK + kc + s0g*8);
            cp16(st + 3*BUFB + r1g*ROWB + s1g*16, Blo + (size_t)(n0 + r1g)*GK + kc + s1g*8);
            asm volatile("cp.async.commit_group;" ::: "memory");
            asm volatile("cp.async.wait_group 1;" ::: "memory");
        } else {
            asm volatile("cp.async.wait_group 0;" ::: "memory");
        }
        __syncthreads();

        const uint32_t st = sb + (c & 1) * STAGEB;
#pragma unroll
        for (int kk = 0; kk < 2; kk++) {
            const uint32_t kb = kk * 32;
            uint32_t ahi[4][4], alo[4][4];
#pragma unroll
            for (int mt = 0; mt < 4; mt++) {
                ldm_x4(ahi[mt], st + 0*BUFB + a_off + mt * (16 * ROWB) + kb);
                ldm_x4(alo[mt], st + 1*BUFB + a_off + mt * (16 * ROWB) + kb);
            }
            uint32_t bhi[4][2], blo[4][2];
#pragma unroll
            for (int np = 0; np < 2; np++) {
                uint32_t r[4];
                ldm_x4(r, st + 2*BUFB + b_off + np * (16 * ROWB) + kb);
                bhi[2*np][0] = r[0]; bhi[2*np][1] = r[1];
                bhi[2*np+1][0] = r[2]; bhi[2*np+1][1] = r[3];
                ldm_x4(r, st + 3*BUFB + b_off + np * (16 * ROWB) + kb);
                blo[2*np][0] = r[0]; blo[2*np][1] = r[1];
                blo[2*np+1][0] = r[2]; blo[2*np+1][1] = r[3];
            }
#pragma unroll
            for (int mt = 0; mt < 4; mt++)
#pragma unroll
                for (int nt = 0; nt < 4; nt++) {
                    mma16816(acc[mt][nt], ahi[mt], bhi[nt]);
                    mma16816(acc[mt][nt], ahi[mt], blo[nt]);
                    mma16816(acc[mt][nt], alo[mt], bhi[nt]);
                }
        }
        __syncthreads();
    }

    const int g = lane >> 2, cpr = (lane & 3) * 2;
#pragma unroll
    for (int mt = 0; mt < 4; mt++)
#pragma unroll
        for (int nt = 0; nt < 4; nt++) {
            const int row = m0 + wm + mt * 16 + g;
            const int col = n0 + wn + nt * 8 + cpr;
            float2 lo_pair; lo_pair.x = acc[mt][nt][0]; lo_pair.y = acc[mt][nt][1];
            float2 hi_pair; hi_pair.x = acc[mt][nt][2]; hi_pair.y = acc[mt][nt][3];
            *(float2*)(C + (size_t)row * GN + col)       = lo_pair;
            *(float2*)(C + (size_t)(row + 8) * GN + col) = hi_pair;
        }
}

// ================= HMMA scores + exp fused =================
// E[bh][k][q] = exp( K_k . (Q/32)_q )  as bf16 hi/lo, plus per-CTA partial row sums.
#define SC_ROWB 144
#define SC_BUF  (128 * SC_ROWB)   /* 18432 */
#define SC_TOTAL (4 * SC_BUF)     /* 73728 */

__global__ __launch_bounds__(256)
void scores_exp_hmma(const __nv_bfloat16* __restrict__ Khi, const __nv_bfloat16* __restrict__ Klo,
                     const __nv_bfloat16* __restrict__ Qhi, const __nv_bfloat16* __restrict__ Qlo,
                     __nv_bfloat16* __restrict__ Ehi, __nv_bfloat16* __restrict__ Elo,
                     float* __restrict__ Spart) {
    extern __shared__ char sm[];
    __shared__ float part[4][128];
    const uint32_t sb = smem_u32(sm);
    const int tid = threadIdx.x;
    const int lane = tid & 31;
    const int wid = tid >> 5;
    const int bh = blockIdx.z;
    const int b = bh >> 4, h = bh & 15;
    const int kt = blockIdx.y * 128;
    const int qt = blockIdx.x * 128;

    const __nv_bfloat16* Ah = Khi + ((size_t)(b * SEQ + kt)) * LDIM + h * DH;
    const __nv_bfloat16* Al = Klo + ((size_t)(b * SEQ + kt)) * LDIM + h * DH;
    const __nv_bfloat16* Bh = Qhi + ((size_t)(b * SEQ + qt)) * LDIM + h * DH;
    const __nv_bfloat16* Bl = Qlo + ((size_t)(b * SEQ + qt)) * LDIM + h * DH;

#pragma unroll
    for (int i = 0; i < 4; i++) {
        const int cid = tid + i * 256;
        const int row = cid >> 3, seg = cid & 7;
        const uint32_t d = row * SC_ROWB + seg * 16;
        const size_t goff = (size_t)row * LDIM + seg * 8;
        cp16(sb + 0*SC_BUF + d, Ah + goff);
        cp16(sb + 1*SC_BUF + d, Al + goff);
        cp16(sb + 2*SC_BUF + d, Bh + goff);
        cp16(sb + 3*SC_BUF + d, Bl + goff);
    }
    asm volatile("cp.async.commit_group;" ::: "memory");
    asm volatile("cp.async.wait_group 0;" ::: "memory");
    __syncthreads();

    const int wm = (wid & 1) * 64;
    const int wn = (wid >> 1) * 32;
    const int wc = wid >> 1;   // warp column index 0..3
    const uint32_t a_off = (uint32_t)((wm + (lane & 15)) * SC_ROWB + ((lane >> 4) << 3) * 2);
    const uint32_t b_off = (uint32_t)((wn + ((lane >> 4) << 3) + (lane & 7)) * SC_ROWB + (lane & 8) * 2);

    float acc[4][4][4];
#pragma unroll
    for (int i = 0; i < 4; i++)
#pragma unroll
        for (int j = 0; j < 4; j++)
#pragma unroll
            for (int e = 0; e < 4; e++) acc[i][j][e] = 0.f;

#pragma unroll
    for (int kk = 0; kk < 4; kk++) {
        const uint32_t kb = kk * 32;
        uint32_t ahi[4][4], alo[4][4];
#pragma unroll
        for (int mt = 0; mt < 4; mt++) {
            ldm_x4(ahi[mt], sb + 0*SC_BUF + a_off + mt * (16 * SC_ROWB) + kb);
            ldm_x4(alo[mt], sb + 1*SC_BUF + a_off + mt * (16 * SC_ROWB) + kb);
        }
        uint32_t bhi[4][2], blo[4][2];
#pragma unroll
        for (int np = 0; np < 2; np++) {
            uint32_t r[4];
            ldm_x4(r, sb + 2*SC_BUF + b_off + np * (16 * SC_ROWB) + kb);
            bhi[2*np][0] = r[0]; bhi[2*np][1] = r[1];
            bhi[2*np+1][0] = r[2]; bhi[2*np+1][1] = r[3];
            ldm_x4(r, sb + 3*SC_BUF + b_off + np * (16 * SC_ROWB) + kb);
            blo[2*np][0] = r[0]; blo[2*np][1] = r[1];
            blo[2*np+1][0] = r[2]; blo[2*np+1][1] = r[3];
        }
#pragma unroll
        for (int mt = 0; mt < 4; mt++)
#pragma unroll
            for (int nt = 0; nt < 4; nt++) {
                mma16816(acc[mt][nt], ahi[mt], bhi[nt]);
                mma16816(acc[mt][nt], ahi[mt], blo[nt]);
                mma16816(acc[mt][nt], alo[mt], bhi[nt]);
            }
    }

    // epilogue: exp, bf16 hi/lo store, row-sum partials
    const int g = lane >> 2, cpr = (lane & 3) * 2;
    __nv_bfloat16* EH = Ehi + (size_t)bh * SEQ * SEQ;
    __nv_bfloat16* EL = Elo + (size_t)bh * SEQ * SEQ;
    float rowsum[8];
#pragma unroll
    for (int i = 0; i < 8; i++) rowsum[i] = 0.f;

#pragma unroll
    for (int mt = 0; mt < 4; mt++)
#pragma unroll
        for (int nt = 0; nt < 4; nt++) {
            const int row = kt + wm + mt * 16 + g;
            const int col = qt + wn + nt * 8 + cpr;
            float e0 = __expf(acc[mt][nt][0]);
            float e1 = __expf(acc[mt][nt][1]);
            float e2 = __expf(acc[mt][nt][2]);
            float e3 = __expf(acc[mt][nt][3]);
            __nv_bfloat16 h0 = __float2bfloat16(e0), h1 = __float2bfloat16(e1);
            __nv_bfloat16 h2 = __float2bfloat16(e2), h3 = __float2bfloat16(e3);
            *(__nv_bfloat162*)(EH + (size_t)row * SEQ + col)       = __nv_bfloat162(h0, h1);
            *(__nv_bfloat162*)(EH + (size_t)(row + 8) * SEQ + col) = __nv_bfloat162(h2, h3);
            *(__nv_bfloat162*)(EL + (size_t)row * SEQ + col) =
                __nv_bfloat162(__float2bfloat16(e0 - __bfloat162float(h0)),
                               __float2bfloat16(e1 - __bfloat162float(h1)));
            *(__nv_bfloat162*)(EL + (size_t)(row + 8) * SEQ + col) =
                __nv_bfloat162(__float2bfloat16(e2 - __bfloat162float(h2)),
                               __float2bfloat16(e3 - __bfloat162float(h3)));
            rowsum[mt * 2 + 0] += e0 + e1;
            rowsum[mt * 2 + 1] += e2 + e3;
        }
    // reduce across the 4 lanes sharing a row (lane bits 0-1)
#pragma unroll
    for (int i = 0; i < 8; i++) {
        rowsum[i] += __shfl_xor_sync(0xffffffffu, rowsum[i], 1);
        rowsum[i] += __shfl_xor_sync(0xffffffffu, rowsum[i], 2);
    }
    if ((lane & 3) == 0) {
#pragma unroll
        for (int mt = 0; mt < 4; mt++) {
            part[wc][wm + mt * 16 + g]     = rowsum[mt * 2 + 0];
            part[wc][wm + mt * 16 + g + 8] = rowsum[mt * 2 + 1];
        }
    }
    __syncthreads();
    if (tid < 128) {
        const float s = part[0][tid] + part[1][tid] + part[2][tid] + part[3][tid];
        Spart[((size_t)bh * (SEQ/128) + blockIdx.x) * SEQ + kt + tid] = s;
    }
}

// ================= reduce partials -> 1/S =================
__global__ __launch_bounds__(256) void reduce_S(const float* __restrict__ Spart,
                                                float* __restrict__ Sinv) {
    const int idx = blockIdx.x * 256 + threadIdx.x;   // over BHTOT*SEQ
    const int bh = idx >> 11, k = idx & (SEQ - 1);
    float s = 0.f;
#pragma unroll
    for (int qt = 0; qt < SEQ/128; qt++)
        s += Spart[((size_t)bh * (SEQ/128) + qt) * SEQ + k];
    Sinv[idx] = 1.f / s;
}

// ================= V / S  -> bf16 hi/lo, layout [bh][k][DH] =================
__global__ __launch_bounds__(256) void vscale(const float* __restrict__ V,
                                              const float* __restrict__ Sinv,
                                              __nv_bfloat16* __restrict__ VShi,
                                              __nv_bfloat16* __restrict__ VSlo) {
    const int bh = blockIdx.y;
    const int b = bh >> 4, h = bh & 15;
    const int row = blockIdx.x * 4 + (threadIdx.x >> 6);
    const int d = threadIdx.x & 63;
    const float inv = Sinv[bh * SEQ + row];
    const float v = V[((size_t)b * SEQ + row) * LDIM + h * DH + d] * inv;
    const __nv_bfloat16 hv = __float2bfloat16(v);
    VShi[((size_t)bh * SEQ + row) * DH + d] = hv;
    VSlo[((size_t)bh * SEQ + row) * DH + d] = __float2bfloat16(v - __bfloat162float(hv));
}

// ================= HMMA att_out: Z[b,q,h*64+d] = sum_k E[bh][k][q] * Vs[bh][k][d] =================
#define AO_AROW 272
#define AO_ABUF (32 * AO_AROW)   /* 8704  */
#define AO_VROW 144
#define AO_VBUF (32 * AO_VROW)   /* 4608  */
#define AO_PHI 0
#define AO_PLO AO_ABUF
#define AO_VHI (2 * AO_ABUF)
#define AO_VLO (2 * AO_ABUF + AO_VBUF)
#define AO_STAGE (2 * AO_ABUF + 2 * AO_VBUF)  /* 26624 */
#define AO_TOTAL (2 * AO_STAGE)               /* 53248 */

__global__ __launch_bounds__(256)
void att_out_hmma(const __nv_bfloat16* __restrict__ Ehi, const __nv_bfloat16* __restrict__ Elo,
                  const __nv_bfloat16* __restrict__ VShi, const __nv_bfloat16* __restrict__ VSlo) {
    extern __shared__ char sm[];
    const uint32_t sb = smem_u32(sm);
    const int tid = threadIdx.x;
    const int lane = tid & 31;
    const int wid = tid >> 5;
    const int qt = blockIdx.x * 128;
    const int bh = blockIdx.y;
    const int b = bh >> 4, h = bh & 15;

    const __nv_bfloat16* Pbh = Ehi + (size_t)bh * SEQ * SEQ + qt;
    const __nv_bfloat16* Pbl = Elo + (size_t)bh * SEQ * SEQ + qt;
    const __nv_bfloat16* Vbh = VShi + (size_t)bh * SEQ * DH;
    const __nv_bfloat16* Vbl = VSlo + (size_t)bh * SEQ * DH;

    const int pr0 = tid >> 4, ps0 = tid & 15;
    const int pr1 = (tid + 256) >> 4, ps1 = tid & 15;
    const int vr = tid >> 3, vs = tid & 7;

    const int wm = (wid & 3) * 32;
    const int wn = (wid >> 2) * 32;

    const uint32_t a_tr = (uint32_t)(((lane & 7) + ((lane >> 4) << 3)) * AO_AROW + (wm + (lane & 8)) * 2);
    const uint32_t b_tr = (uint32_t)(((lane & 7) + (lane & 8)) * AO_VROW + (wn + ((lane >> 4) << 3)) * 2);

    float acc[2][4][4];
#pragma unroll
    for (int i = 0; i < 2; i++)
#pragma unroll
        for (int j = 0; j < 4; j++)
#pragma unroll
            for (int e = 0; e < 4; e++) acc[i][j][e] = 0.f;

    const int NC = SEQ / 32;   // 64

    {
        const int k0 = 0;
        const uint32_t st = sb;
        cp16(st + AO_PHI + pr0*AO_AROW + ps0*16, Pbh + (size_t)(k0 + pr0) * SEQ + ps0*8);
        cp16(st + AO_PHI + pr1*AO_AROW + ps1*16, Pbh + (size_t)(k0 + pr1) * SEQ + ps1*8);
        cp16(st + AO_PLO + pr0*AO_AROW + ps0*16, Pbl + (size_t)(k0 + pr0) * SEQ + ps0*8);
        cp16(st + AO_PLO + pr1*AO_AROW + ps1*16, Pbl + (size_t)(k0 + pr1) * SEQ + ps1*8);
        cp16(st + AO_VHI + vr*AO_VROW + vs*16,   Vbh + (size_t)(k0 + vr) * DH + vs*8);
        cp16(st + AO_VLO + vr*AO_VROW + vs*16,   Vbl + (size_t)(k0 + vr) * DH + vs*8);
        asm volatile("cp.async.commit_group;" ::: "memory");
    }

    for (int c = 0; c < NC; c++) {
        if (c + 1 < NC) {
            const int k0 = (c + 1) * 32;
            const uint32_t st = sb + ((c + 1) & 1) * AO_STAGE;
            cp16(st + AO_PHI + pr0*AO_AROW + ps0*16, Pbh + (size_t)(k0 + pr0) * SEQ + ps0*8);
            cp16(st + AO_PHI + pr1*AO_AROW + ps1*16, Pbh + (size_t)(k0 + pr1) * SEQ + ps1*8);
            cp16(st + AO_PLO + pr0*AO_AROW + ps0*16, Pbl + (size_t)(k0 + pr0) * SEQ + ps0*8);
            cp16(st + AO_PLO + pr1*AO_AROW + ps1*16, Pbl + (size_t)(k0 + pr1) * SEQ + ps1*8);
            cp16(st + AO_VHI + vr*AO_VROW + vs*16,   Vbh + (size_t)(k0 + vr) * DH + vs*8);
            cp16(st + AO_VLO + vr*AO_VROW + vs*16,   Vbl + (size_t)(k0 + vr) * DH + vs*8);
            asm volatile("cp.async.commit_group;" ::: "memory");
            asm volatile("cp.async.wait_group 1;" ::: "memory");
        } else {
            asm volatile("cp.async.wait_group 0;" ::: "memory");
        }
        __syncthreads();

        const uint32_t st = sb + (c & 1) * AO_STAGE;
#pragma unroll
        for (int kk = 0; kk < 2; kk++) {
            uint32_t ah[2][4], al[2][4];
#pragma unroll
            for (int mt = 0; mt < 2; mt++) {
                ldm_x4t(ah[mt], st + AO_PHI + a_tr + kk * (16 * AO_AROW) + mt * 32);
                ldm_x4t(al[mt], st + AO_PLO + a_tr + kk * (16 * AO_AROW) + mt * 32);
            }
            uint32_t bh_[4][2], bl_[4][2];
#pragma unroll
            for (int np = 0; np < 2; np++) {
                uint32_t r[4];
                ldm_x4t(r, st + AO_VHI + b_tr + kk * (16 * AO_VROW) + np * 32);
                bh_[2*np][0] = r[0]; bh_[2*np][1] = r[1];
                bh_[2*np+1][0] = r[2]; bh_[2*np+1][1] = r[3];
                ldm_x4t(r, st + AO_VLO + b_tr + kk * (16 * AO_VROW) + np * 32);
                bl_[2*np][0] = r[0]; bl_[2*np][1] = r[1];
                bl_[2*np+1][0] = r[2]; bl_[2*np+1][1] = r[3];
            }
#pragma unroll
            for (int mt = 0; mt < 2; mt++)
#pragma unroll
                for (int nt = 0; nt < 4; nt++) {
                    mma16816(acc[mt][nt], ah[mt], bh_[nt]);
                    mma16816(acc[mt][nt], ah[mt], bl_[nt]);
                    mma16816(acc[mt][nt], al[mt], bh_[nt]);
                }
        }
        __syncthreads();
    }

    const int g = lane >> 2, cpr = (lane & 3) * 2;
#pragma unroll
    for (int mt = 0; mt < 2; mt++)
#pragma unroll
        for (int nt = 0; nt < 4; nt++) {
            const int q = qt + wm + mt * 16 + g;
            const int col = wn + nt * 8 + cpr;
            float2 p0; p0.x = acc[mt][nt][0]; p0.y = acc[mt][nt][1];
            float2 p1; p1.x = acc[mt][nt][2]; p1.y = acc[mt][nt][3];
            *(float2*)(g_Z + ((size_t)b * SEQ + q)     * LDIM + h * DH + col) = p0;
            *(float2*)(g_Z + ((size_t)b * SEQ + q + 8) * LDIM + h * DH + col) = p1;
        }
}

// ================= row L2 normalize =================
__global__ __launch_bounds__(256) void l2norm_rows(const float* __restrict__ in,
                                                   float* __restrict__ out) {
    const size_t rowi = blockIdx.x;
    const float* p = in + rowi * DIM;
    float* o = out + rowi * DIM;
    const int t = threadIdx.x;
    float v[4];
    float ss = 0.f;
#pragma unroll
    for (int i = 0; i < 4; i++) { v[i] = p[t + 256 * i]; ss += v[i] * v[i]; }
    __shared__ float red[256];
    red[t] = ss; __syncthreads();
    for (int s = 128; s > 0; s >>= 1) {
        if (t < s) red[t] = red[t] + red[t + s];
        __syncthreads();
    }
    const float n = sqrtf(red[0]);
    const float sc = 1.f / fmaxf(n, 1e-12f);
#pragma unroll
    for (int i = 0; i < 4; i++) o[t + 256 * i] = v[i] * sc;
}

// ================= row L2 normalize + exact GELU =================
__global__ __launch_bounds__(256) void l2norm_gelu(const float* __restrict__ in,
                                                   float* __restrict__ out) {
    const size_t rowi = blockIdx.x;
    const float* p = in + rowi * DIM;
    float* o = out + rowi * DIM;
    const int t = threadIdx.x;
    float v[4];
    float ss = 0.f;
#pragma unroll
    for (int i = 0; i < 4; i++) { v[i] = p[t + 256 * i]; ss += v[i] * v[i]; }
    __shared__ float red[256];
    red[t] = ss; __syncthreads();
    for (int s = 128; s > 0; s >>= 1) {
        if (t < s) red[t] = red[t] + red[t + s];
        __syncthreads();
    }
    const float n = sqrtf(red[0]);
    const float sc = 1.f / fmaxf(n, 1e-12f);
#pragma unroll
    for (int i = 0; i < 4; i++) {
        float y = v[i] * sc;
        o[t + 256 * i] = 0.5f * y * (1.f + erff(y * 0.70710678118654752f));
    }
}

// ================= host launcher =================
extern "C" void kernel_launch(void* const* d_in, const int* in_sizes, int n_in,
                              void* d_out, int out_size) {
    const float* x   = (const float*)d_in[0];
    const float* Wq  = (const float*)d_in[1];
    const float* Wk  = (const float*)d_in[2];
    const float* Wv  = (const float*)d_in[3];
    const float* Wo  = (const float*)d_in[4];
    const float* Wff = (const float*)d_in[5];
    float* outp = (float*)d_out;

    float *pQ, *pK, *pV, *pZ, *pZ2, *pSpart, *pSinv;
    __nv_bfloat16 *pAhi, *pAlo, *pWhi, *pWlo;
    __nv_bfloat16 *pQhi, *pQlo, *pKhi, *pKlo, *pEhi, *pElo, *pVShi, *pVSlo;
    cudaGetSymbolAddress((void**)&pQ,  g_Q);
    cudaGetSymbolAddress((void**)&pK,  g_Kb);
    cudaGetSymbolAddress((void**)&pV,  g_V);
    cudaGetSymbolAddress((void**)&pZ,  g_Z);
    cudaGetSymbolAddress((void**)&pZ2, g_Z2);
    cudaGetSymbolAddress((void**)&pAhi, g_Ahi);
    cudaGetSymbolAddress((void**)&pAlo, g_Alo);
    cudaGetSymbolAddress((void**)&pWhi, g_Whi);
    cudaGetSymbolAddress((void**)&pWlo, g_Wlo);
    cudaGetSymbolAddress((void**)&pQhi, g_Qhi);
    cudaGetSymbolAddress((void**)&pQlo, g_Qlo);
    cudaGetSymbolAddress((void**)&pKhi, g_Khi);
    cudaGetSymbolAddress((void**)&pKlo, g_Klo);
    cudaGetSymbolAddress((void**)&pEhi, g_Ehi);
    cudaGetSymbolAddress((void**)&pElo, g_Elo);
    cudaGetSymbolAddress((void**)&pSpart, g_Spart);
    cudaGetSymbolAddress((void**)&pSinv,  g_Sinv);
    cudaGetSymbolAddress((void**)&pVShi, g_VShi);
    cudaGetSymbolAddress((void**)&pVSlo, g_VSlo);

    cudaFuncSetAttribute(gemm_hmma,       cudaFuncAttributeMaxDynamicSharedMemorySize, SMEM_GEMM);
    cudaFuncSetAttribute(scores_exp_hmma, cudaFuncAttributeMaxDynamicSharedMemorySize, SC_TOTAL);
    cudaFuncSetAttribute(att_out_hmma,    cudaFuncAttributeMaxDynamicSharedMemorySize, AO_TOTAL);

    const dim3 gG(GN / 128, MTOT / 128);    // (8, 32)
    const dim3 gT(DIM / 32, DIM / 32);      // (32, 32)
    const int  splitBlocksX = (MTOT * DIM) / (256 * 4);

    // --- QKV projections (HMMA) ---
    split_bf16<<<splitBlocksX, 256>>>(x, pAhi, pAlo, 1.0f);
    tsplit<<<gT, 256>>>(Wq, pWhi, pWlo);
    gemm_hmma<<<gG, 256, SMEM_GEMM>>>(pAhi, pAlo, pWhi, pWlo, pQ);
    tsplit<<<gT, 256>>>(Wk, pWhi, pWlo);
    gemm_hmma<<<gG, 256, SMEM_GEMM>>>(pAhi, pAlo, pWhi, pWlo, pK);
    tsplit<<<gT, 256>>>(Wv, pWhi, pWlo);
    gemm_hmma<<<gG, 256, SMEM_GEMM>>>(pAhi, pAlo, pWhi, pWlo, pV);

    // --- attention operand splits (Q pre-scaled by 1/32) ---
    split_bf16<<<splitBlocksX, 256>>>(pQ, pQhi, pQlo, 0.03125f);
    split_bf16<<<splitBlocksX, 256>>>(pK, pKhi, pKlo, 1.0f);

    // --- attention: fused scores+exp -> rowsum reduce -> V/S -> PV ---
    scores_exp_hmma<<<dim3(SEQ / 128, SEQ / 128, BHTOT), 256, SC_TOTAL>>>(
        pKhi, pKlo, pQhi, pQlo, pEhi, pElo, pSpart);
    reduce_S<<<(BHTOT * SEQ) / 256, 256>>>(pSpart, pSinv);
    vscale<<<dim3(SEQ / 4, BHTOT), 256>>>(pV, pSinv, pVShi, pVSlo);
    att_out_hmma<<<dim3(SEQ / 128, BHTOT), 256, AO_TOTAL>>>(pEhi, pElo, pVShi, pVSlo);

    // --- out projection ---
    split_bf16<<<splitBlocksX, 256>>>(pZ, pAhi, pAlo, 1.0f);
    tsplit<<<gT, 256>>>(Wo, pWhi, pWlo);
    gemm_hmma<<<gG, 256, SMEM_GEMM>>>(pAhi, pAlo, pWhi, pWlo, pZ2);

    // --- normalize -> FFN -> normalize+gelu ---
    l2norm_rows<<<MTOT, 256>>>(pZ2, pZ);
    split_bf16<<<splitBlocksX, 256>>>(pZ, pAhi, pAlo, 1.0f);
    tsplit<<<gT, 256>>>(Wff, pWhi, pWlo);
    gemm_hmma<<<gG, 256, SMEM_GEMM>>>(pAhi, pAlo, pWhi, pWlo, pZ2);
    l2norm_gelu<<<MTOT, 256>>>(pZ2, outp);
}

// round 7
// speedup vs baseline: 2.9647x; 1.1705x over previous
#include <cuda_runtime.h>
#include <cuda_bf16.h>
#include <cuda_fp16.h>
#include <math.h>
#include <cstdint>

#define NBATCH 2
#define SEQ    2048
#define DIM    1024
#define LDIM   1024
#define NH     16
#define DH     64
#define MTOT   (NBATCH*SEQ)   /* 4096 */
#define BHTOT  (NBATCH*NH)    /* 32   */

__device__ __forceinline__ uint32_t smem_u32(const void* p) {
    uint32_t a;
    asm("{ .reg .u64 t; cvta.to.shared.u64 t, %1; cvt.u32.u64 %0, t; }" : "=r"(a) : "l"(p));
    return a;
}

// ================= scratch (static device globals; no allocation) =================
__device__ float g_Q [ (size_t)MTOT * LDIM ];
__device__ float g_Kb[ (size_t)MTOT * LDIM ];
__device__ float g_V [ (size_t)MTOT * LDIM ];
__device__ float g_Z [ (size_t)MTOT * LDIM ];
__device__ float g_Z2[ (size_t)MTOT * LDIM ];
__device__ __nv_bfloat16 g_Ahi[ (size_t)MTOT * DIM ];
__device__ __nv_bfloat16 g_Alo[ (size_t)MTOT * DIM ];
__device__ __nv_bfloat16 g_Whi[ (size_t)DIM * DIM ];
__device__ __nv_bfloat16 g_Wlo[ (size_t)DIM * DIM ];
// attention operand splits (bf16, for scores)
__device__ __nv_bfloat16 g_Qhi[ (size_t)MTOT * LDIM ];
__device__ __nv_bfloat16 g_Qlo[ (size_t)MTOT * LDIM ];
__device__ __nv_bfloat16 g_Khi[ (size_t)MTOT * LDIM ];
__device__ __nv_bfloat16 g_Klo[ (size_t)MTOT * LDIM ];
// unnormalized exp(scores) as fp16, [bh][k][q]
__device__ __half g_Eh[ (size_t)BHTOT * SEQ * SEQ ];
// per-(bh, qtile) partial row sums, and inverse row sums
__device__ float g_Spart[ (size_t)BHTOT * (SEQ/128) * SEQ ];
__device__ float g_Sinv [ (size_t)BHTOT * SEQ ];
// (V * 4096 / S) fp16 hi/lo, layout [bh][k][DH]
__device__ __half g_VShi[ (size_t)BHTOT * SEQ * DH ];
__device__ __half g_VSlo[ (size_t)BHTOT * SEQ * DH ];

// ================= HMMA primitives =================
__device__ __forceinline__ void cp16(uint32_t dst, const void* src) {
    asm volatile("cp.async.cg.shared.global [%0], [%1], 16;" :: "r"(dst), "l"(src));
}
__device__ __forceinline__ void ldm_x4(uint32_t* r, uint32_t addr) {
    asm volatile("ldmatrix.sync.aligned.m8n8.x4.shared.b16 {%0,%1,%2,%3}, [%4];"
                 : "=r"(r[0]), "=r"(r[1]), "=r"(r[2]), "=r"(r[3]) : "r"(addr));
}
__device__ __forceinline__ void ldm_x4t(uint32_t* r, uint32_t addr) {
    asm volatile("ldmatrix.sync.aligned.m8n8.x4.trans.shared.b16 {%0,%1,%2,%3}, [%4];"
                 : "=r"(r[0]), "=r"(r[1]), "=r"(r[2]), "=r"(r[3]) : "r"(addr));
}
__device__ __forceinline__ void mma16816(float* c, const uint32_t* a, const uint32_t* b) {
    asm volatile(
        "mma.sync.aligned.m16n8k16.row.col.f32.bf16.bf16.f32 "
        "{%0,%1,%2,%3}, {%4,%5,%6,%7}, {%8,%9}, {%0,%1,%2,%3};"
        : "+f"(c[0]), "+f"(c[1]), "+f"(c[2]), "+f"(c[3])
        : "r"(a[0]), "r"(a[1]), "r"(a[2]), "r"(a[3]), "r"(b[0]), "r"(b[1]));
}
__device__ __forceinline__ void mma16816_f16(float* c, const uint32_t* a, const uint32_t* b) {
    asm volatile(
        "mma.sync.aligned.m16n8k16.row.col.f32.f16.f16.f32 "
        "{%0,%1,%2,%3}, {%4,%5,%6,%7}, {%8,%9}, {%0,%1,%2,%3};"
        : "+f"(c[0]), "+f"(c[1]), "+f"(c[2]), "+f"(c[3])
        : "r"(a[0]), "r"(a[1]), "r"(a[2]), "r"(a[3]), "r"(b[0]), "r"(b[1]));
}

// ================= bf16 split (elementwise, optional scale) =================
__global__ __launch_bounds__(256) void split_bf16(const float* __restrict__ X,
                                                  __nv_bfloat16* __restrict__ hi,
                                                  __nv_bfloat16* __restrict__ lo,
                                                  float scale) {
    const size_t i = ((size_t)blockIdx.x * 256 + threadIdx.x) * 4;
    float4 v = *(const float4*)(X + i);
    v.x *= scale; v.y *= scale; v.z *= scale; v.w *= scale;
    __nv_bfloat16 h0 = __float2bfloat16(v.x);
    __nv_bfloat16 h1 = __float2bfloat16(v.y);
    __nv_bfloat16 h2 = __float2bfloat16(v.z);
    __nv_bfloat16 h3 = __float2bfloat16(v.w);
    __nv_bfloat16 l0 = __float2bfloat16(v.x - __bfloat162float(h0));
    __nv_bfloat16 l1 = __float2bfloat16(v.y - __bfloat162float(h1));
    __nv_bfloat16 l2 = __float2bfloat16(v.z - __bfloat162float(h2));
    __nv_bfloat16 l3 = __float2bfloat16(v.w - __bfloat162float(h3));
    __nv_bfloat162* hp = (__nv_bfloat162*)(hi + i);
    __nv_bfloat162* lp = (__nv_bfloat162*)(lo + i);
    hp[0] = __nv_bfloat162(h0, h1); hp[1] = __nv_bfloat162(h2, h3);
    lp[0] = __nv_bfloat162(l0, l1); lp[1] = __nv_bfloat162(l2, l3);
}

// ================= transpose + split: W[K][N] -> Thi/Tlo [N][K] =================
__global__ __launch_bounds__(256) void tsplit(const float* __restrict__ W,
                                              __nv_bfloat16* __restrict__ Thi,
                                              __nv_bfloat16* __restrict__ Tlo) {
    __shared__ float tile[32][33];
    const int tx = threadIdx.x & 31, ty = threadIdx.x >> 5;
    const int k0 = blockIdx.y * 32, n0 = blockIdx.x * 32;
#pragma unroll
    for (int j = 0; j < 4; j++)
        tile[ty + j * 8][tx] = W[(size_t)(k0 + ty + j * 8) * DIM + n0 + tx];
    __syncthreads();
#pragma unroll
    for (int j = 0; j < 4; j++) {
        const int n = n0 + ty + j * 8, k = k0 + tx;
        float v = tile[tx][ty + j * 8];
        __nv_bfloat16 h = __float2bfloat16(v);
        Thi[(size_t)n * DIM + k] = h;
        Tlo[(size_t)n * DIM + k] = __float2bfloat16(v - __bfloat162float(h));
    }
}

// ================= HMMA bf16-split dense GEMM =================
#define GK 1024
#define GN 1024
#define ROWB 80
#define BUFB (128 * ROWB)
#define STAGEB (4 * BUFB)
#define SMEM_GEMM (2 * STAGEB)

__global__ __launch_bounds__(256, 1)
void gemm_hmma(const __nv_bfloat16* __restrict__ Ahi, const __nv_bfloat16* __restrict__ Alo,
               const __nv_bfloat16* __restrict__ Bhi, const __nv_bfloat16* __restrict__ Blo,
               float* __restrict__ C) {
    extern __shared__ char sm[];
    const uint32_t sb = smem_u32(sm);
    const int tid = threadIdx.x;
    const int lane = tid & 31;
    const int wid = tid >> 5;
    const int m0 = blockIdx.y * 128, n0 = blockIdx.x * 128;
    const int wm = (wid & 1) * 64;
    const int wn = (wid >> 1) * 32;

    const int r0g = tid >> 2, s0g = tid & 3;
    const int r1g = (tid + 256) >> 2, s1g = tid & 3;

    const uint32_t a_off = (uint32_t)((wm + (lane & 15)) * ROWB + ((lane >> 4) << 3) * 2);
    const uint32_t b_off = (uint32_t)((wn + ((lane >> 4) << 3) + (lane & 7)) * ROWB + (lane & 8) * 2);

    float acc[4][4][4];
#pragma unroll
    for (int i = 0; i < 4; i++)
#pragma unroll
        for (int j = 0; j < 4; j++)
#pragma unroll
            for (int e = 0; e < 4; e++) acc[i][j][e] = 0.f;

    const int NC = GK / 32;
    {
        uint32_t st = sb;
        cp16(st + 0*BUFB + r0g*ROWB + s0g*16, Ahi + (size_t)(m0 + r0g)*GK + s0g*8);
        cp16(st + 0*BUFB + r1g*ROWB + s1g*16, Ahi + (size_t)(m0 + r1g)*GK + s1g*8);
        cp16(st + 1*BUFB + r0g*ROWB + s0g*16, Alo + (size_t)(m0 + r0g)*GK + s0g*8);
        cp16(st + 1*BUFB + r1g*ROWB + s1g*16, Alo + (size_t)(m0 + r1g)*GK + s1g*8);
        cp16(st + 2*BUFB + r0g*ROWB + s0g*16, Bhi + (size_t)(n0 + r0g)*GK + s0g*8);
        cp16(st + 2*BUFB + r1g*ROWB + s1g*16, Bhi + (size_t)(n0 + r1g)*GK + s1g*8);
        cp16(st + 3*BUFB + r0g*ROWB + s0g*16, Blo + (size_t)(n0 + r0g)*GK + s0g*8);
        cp16(st + 3*BUFB + r1g*ROWB + s1g*16, Blo + (size_t)(n0 + r1g)*GK + s1g*8);
        asm volatile("cp.async.commit_group;" ::: "memory");
    }

    for (int c = 0; c < NC; c++) {
        if (c + 1 < NC) {
            const int kc = (c + 1) * 32;
            uint32_t st = sb + ((c + 1) & 1) * STAGEB;
            cp16(st + 0*BUFB + r0g*ROWB + s0g*16, Ahi + (size_t)(m0 + r0g)*GK + kc + s0g*8);
            cp16(st + 0*BUFB + r1g*ROWB + s1g*16, Ahi + (size_t)(m0 + r1g)*GK + kc + s1g*8);
            cp16(st + 1*BUFB + r0g*ROWB + s0g*16, Alo + (size_t)(m0 + r0g)*GK + kc + s0g*8);
            cp16(st + 1*BUFB + r1g*ROWB + s1g*16, Alo + (size_t)(m0 + r1g)*GK + kc + s1g*8);
            cp16(st + 2*BUFB + r0g*ROWB + s0g*16, Bhi + (size_t)(n0 + r0g)*GK + kc + s0g*8);
            cp16(st + 2*BUFB + r1g*ROWB + s1g*16, Bhi + (size_t)(n0 + r1g)*GK + kc + s1g*8);
            cp16(st + 3*BUFB + r0g*ROWB + s0g*16, Blo + (size_t)(n0 + r0g)*GK + kc + s0g*8);
            cp16(st + 3*BUFB + r1g*ROWB + s1g*16, Blo + (size_t)(n0 + r1g)*GK + kc + s1g*8);
            asm volatile("cp.async.commit_group;" ::: "memory");
            asm volatile("cp.async.wait_group 1;" ::: "memory");
        } else {
            asm volatile("cp.async.wait_group 0;" ::: "memory");
        }
        __syncthreads();

        const uint32_t st = sb + (c & 1) * STAGEB;
#pragma unroll
        for (int kk = 0; kk < 2; kk++) {
            const uint32_t kb = kk * 32;
            uint32_t ahi[4][4], alo[4][4];
#pragma unroll
            for (int mt = 0; mt < 4; mt++) {
                ldm_x4(ahi[mt], st + 0*BUFB + a_off + mt * (16 * ROWB) + kb);
                ldm_x4(alo[mt], st + 1*BUFB + a_off + mt * (16 * ROWB) + kb);
            }
            uint32_t bhi[4][2], blo[4][2];
#pragma unroll
            for (int np = 0; np < 2; np++) {
                uint32_t r[4];
                ldm_x4(r, st + 2*BUFB + b_off + np * (16 * ROWB) + kb);
                bhi[2*np][0] = r[0]; bhi[2*np][1] = r[1];
                bhi[2*np+1][0] = r[2]; bhi[2*np+1][1] = r[3];
                ldm_x4(r, st + 3*BUFB + b_off + np * (16 * ROWB) + kb);
                blo[2*np][0] = r[0]; blo[2*np][1] = r[1];
                blo[2*np+1][0] = r[2]; blo[2*np+1][1] = r[3];
            }
#pragma unroll
            for (int mt = 0; mt < 4; mt++)
#pragma unroll
                for (int nt = 0; nt < 4; nt++) {
                    mma16816(acc[mt][nt], ahi[mt], bhi[nt]);
                    mma16816(acc[mt][nt], ahi[mt], blo[nt]);
                    mma16816(acc[mt][nt], alo[mt], bhi[nt]);
                }
        }
        __syncthreads();
    }

    const int g = lane >> 2, cpr = (lane & 3) * 2;
#pragma unroll
    for (int mt = 0; mt < 4; mt++)
#pragma unroll
        for (int nt = 0; nt < 4; nt++) {
            const int row = m0 + wm + mt * 16 + g;
            const int col = n0 + wn + nt * 8 + cpr;
            float2 lo_pair; lo_pair.x = acc[mt][nt][0]; lo_pair.y = acc[mt][nt][1];
            float2 hi_pair; hi_pair.x = acc[mt][nt][2]; hi_pair.y = acc[mt][nt][3];
            *(float2*)(C + (size_t)row * GN + col)       = lo_pair;
            *(float2*)(C + (size_t)(row + 8) * GN + col) = hi_pair;
        }
}

// ================= HMMA scores + exp fused; E stored fp16 =================
#define SC_ROWB 144
#define SC_BUF  (128 * SC_ROWB)   /* 18432 */
#define SC_TOTAL (4 * SC_BUF)     /* 73728 */

__global__ __launch_bounds__(256)
void scores_exp_hmma(const __nv_bfloat16* __restrict__ Khi, const __nv_bfloat16* __restrict__ Klo,
                     const __nv_bfloat16* __restrict__ Qhi, const __nv_bfloat16* __restrict__ Qlo,
                     __half* __restrict__ Eh, float* __restrict__ Spart) {
    extern __shared__ char sm[];
    __shared__ float part[4][128];
    const uint32_t sb = smem_u32(sm);
    const int tid = threadIdx.x;
    const int lane = tid & 31;
    const int wid = tid >> 5;
    const int bh = blockIdx.z;
    const int b = bh >> 4, h = bh & 15;
    const int kt = blockIdx.y * 128;
    const int qt = blockIdx.x * 128;

    const __nv_bfloat16* Ah = Khi + ((size_t)(b * SEQ + kt)) * LDIM + h * DH;
    const __nv_bfloat16* Al = Klo + ((size_t)(b * SEQ + kt)) * LDIM + h * DH;
    const __nv_bfloat16* Bh = Qhi + ((size_t)(b * SEQ + qt)) * LDIM + h * DH;
    const __nv_bfloat16* Bl = Qlo + ((size_t)(b * SEQ + qt)) * LDIM + h * DH;

#pragma unroll
    for (int i = 0; i < 4; i++) {
        const int cid = tid + i * 256;
        const int row = cid >> 3, seg = cid & 7;
        const uint32_t d = row * SC_ROWB + seg * 16;
        const size_t goff = (size_t)row * LDIM + seg * 8;
        cp16(sb + 0*SC_BUF + d, Ah + goff);
        cp16(sb + 1*SC_BUF + d, Al + goff);
        cp16(sb + 2*SC_BUF + d, Bh + goff);
        cp16(sb + 3*SC_BUF + d, Bl + goff);
    }
    asm volatile("cp.async.commit_group;" ::: "memory");
    asm volatile("cp.async.wait_group 0;" ::: "memory");
    __syncthreads();

    const int wm = (wid & 1) * 64;
    const int wn = (wid >> 1) * 32;
    const int wc = wid >> 1;
    const uint32_t a_off = (uint32_t)((wm + (lane & 15)) * SC_ROWB + ((lane >> 4) << 3) * 2);
    const uint32_t b_off = (uint32_t)((wn + ((lane >> 4) << 3) + (lane & 7)) * SC_ROWB + (lane & 8) * 2);

    float acc[4][4][4];
#pragma unroll
    for (int i = 0; i < 4; i++)
#pragma unroll
        for (int j = 0; j < 4; j++)
#pragma unroll
            for (int e = 0; e < 4; e++) acc[i][j][e] = 0.f;

#pragma unroll
    for (int kk = 0; kk < 4; kk++) {
        const uint32_t kb = kk * 32;
        uint32_t ahi[4][4], alo[4][4];
#pragma unroll
        for (int mt = 0; mt < 4; mt++) {
            ldm_x4(ahi[mt], sb + 0*SC_BUF + a_off + mt * (16 * SC_ROWB) + kb);
            ldm_x4(alo[mt], sb + 1*SC_BUF + a_off + mt * (16 * SC_ROWB) + kb);
        }
        uint32_t bhi[4][2], blo[4][2];
#pragma unroll
        for (int np = 0; np < 2; np++) {
            uint32_t r[4];
            ldm_x4(r, sb + 2*SC_BUF + b_off + np * (16 * SC_ROWB) + kb);
            bhi[2*np][0] = r[0]; bhi[2*np][1] = r[1];
            bhi[2*np+1][0] = r[2]; bhi[2*np+1][1] = r[3];
            ldm_x4(r, sb + 3*SC_BUF + b_off + np * (16 * SC_ROWB) + kb);
            blo[2*np][0] = r[0]; blo[2*np][1] = r[1];
            blo[2*np+1][0] = r[2]; blo[2*np+1][1] = r[3];
        }
#pragma unroll
        for (int mt = 0; mt < 4; mt++)
#pragma unroll
            for (int nt = 0; nt < 4; nt++) {
                mma16816(acc[mt][nt], ahi[mt], bhi[nt]);
                mma16816(acc[mt][nt], ahi[mt], blo[nt]);
                mma16816(acc[mt][nt], alo[mt], bhi[nt]);
            }
    }

    // epilogue: exp, fp16 store, row-sum partials (fp32)
    const int g = lane >> 2, cpr = (lane & 3) * 2;
    __half* EH = Eh + (size_t)bh * SEQ * SEQ;
    float rowsum[8];
#pragma unroll
    for (int i = 0; i < 8; i++) rowsum[i] = 0.f;

#pragma unroll
    for (int mt = 0; mt < 4; mt++)
#pragma unroll
        for (int nt = 0; nt < 4; nt++) {
            const int row = kt + wm + mt * 16 + g;
            const int col = qt + wn + nt * 8 + cpr;
            float e0 = __expf(acc[mt][nt][0]);
            float e1 = __expf(acc[mt][nt][1]);
            float e2 = __expf(acc[mt][nt][2]);
            float e3 = __expf(acc[mt][nt][3]);
            *(__half2*)(EH + (size_t)row * SEQ + col)       = __floats2half2_rn(e0, e1);
            *(__half2*)(EH + (size_t)(row + 8) * SEQ + col) = __floats2half2_rn(e2, e3);
            rowsum[mt * 2 + 0] += e0 + e1;
            rowsum[mt * 2 + 1] += e2 + e3;
        }
#pragma unroll
    for (int i = 0; i < 8; i++) {
        rowsum[i] += __shfl_xor_sync(0xffffffffu, rowsum[i], 1);
        rowsum[i] += __shfl_xor_sync(0xffffffffu, rowsum[i], 2);
    }
    if ((lane & 3) == 0) {
#pragma unroll
        for (int mt = 0; mt < 4; mt++) {
            part[wc][wm + mt * 16 + g]     = rowsum[mt * 2 + 0];
            part[wc][wm + mt * 16 + g + 8] = rowsum[mt * 2 + 1];
        }
    }
    __syncthreads();
    if (tid < 128) {
        const float s = part[0][tid] + part[1][tid] + part[2][tid] + part[3][tid];
        Spart[((size_t)bh * (SEQ/128) + blockIdx.x) * SEQ + kt + tid] = s;
    }
}

// ================= reduce partials -> 1/S =================
__global__ __launch_bounds__(256) void reduce_S(const float* __restrict__ Spart,
                                                float* __restrict__ Sinv) {
    const int idx = blockIdx.x * 256 + threadIdx.x;
    const int bh = idx >> 11, k = idx & (SEQ - 1);
    float s = 0.f;
#pragma unroll
    for (int qt = 0; qt < SEQ/128; qt++)
        s += Spart[((size_t)bh * (SEQ/128) + qt) * SEQ + k];
    Sinv[idx] = 1.f / s;
}

// ================= V * (4096/S) -> fp16 hi/lo, layout [bh][k][DH] =================
__global__ __launch_bounds__(256) void vscale(const float* __restrict__ V,
                                              const float* __restrict__ Sinv,
                                              __half* __restrict__ VShi,
                                              __half* __restrict__ VSlo) {
    const int bh = blockIdx.y;
    const int b = bh >> 4, h = bh & 15;
    const int row = blockIdx.x * 4 + (threadIdx.x >> 6);
    const int d = threadIdx.x & 63;
    const float inv = Sinv[bh * SEQ + row] * 4096.f;
    const float v = V[((size_t)b * SEQ + row) * LDIM + h * DH + d] * inv;
    const __half hv = __float2half_rn(v);
    VShi[((size_t)bh * SEQ + row) * DH + d] = hv;
    VSlo[((size_t)bh * SEQ + row) * DH + d] = __float2half_rn(v - __half2float(hv));
}

// ================= HMMA att_out (fp16): Z = (sum_k E[k][q] * Vs[k][d]) / 4096 =================
#define AO_AROW 272
#define AO_ABUF (32 * AO_AROW)   /* 8704 */
#define AO_VROW 144
#define AO_VBUF (32 * AO_VROW)   /* 4608 */
#define AO_EH  0
#define AO_VHI AO_ABUF
#define AO_VLO (AO_ABUF + AO_VBUF)
#define AO_STAGE (AO_ABUF + 2 * AO_VBUF)   /* 17920 */
#define AO_TOTAL (2 * AO_STAGE)            /* 35840 */

__global__ __launch_bounds__(256)
void att_out_hmma(const __half* __restrict__ Eh,
                  const __half* __restrict__ VShi, const __half* __restrict__ VSlo) {
    extern __shared__ char sm[];
    const uint32_t sb = smem_u32(sm);
    const int tid = threadIdx.x;
    const int lane = tid & 31;
    const int wid = tid >> 5;
    const int qt = blockIdx.x * 128;
    const int bh = blockIdx.y;
    const int b = bh >> 4, h = bh & 15;

    const __half* Pb = Eh + (size_t)bh * SEQ * SEQ + qt;
    const __half* Vbh = VShi + (size_t)bh * SEQ * DH;
    const __half* Vbl = VSlo + (size_t)bh * SEQ * DH;

    const int pr0 = tid >> 4, ps0 = tid & 15;
    const int pr1 = (tid + 256) >> 4, ps1 = tid & 15;
    const int vr = tid >> 3, vs = tid & 7;

    const int wm = (wid & 3) * 32;
    const int wn = (wid >> 2) * 32;

    const uint32_t a_tr = (uint32_t)(((lane & 7) + ((lane >> 4) << 3)) * AO_AROW + (wm + (lane & 8)) * 2);
    const uint32_t b_tr = (uint32_t)(((lane & 7) + (lane & 8)) * AO_VROW + (wn + ((lane >> 4) << 3)) * 2);

    float acc[2][4][4];
#pragma unroll
    for (int i = 0; i < 2; i++)
#pragma unroll
        for (int j = 0; j < 4; j++)
#pragma unroll
            for (int e = 0; e < 4; e++) acc[i][j][e] = 0.f;

    const int NC = SEQ / 32;   // 64

    {
        const int k0 = 0;
        const uint32_t st = sb;
        cp16(st + AO_EH + pr0*AO_AROW + ps0*16, Pb + (size_t)(k0 + pr0) * SEQ + ps0*8);
        cp16(st + AO_EH + pr1*AO_AROW + ps1*16, Pb + (size_t)(k0 + pr1) * SEQ + ps1*8);
        cp16(st + AO_VHI + vr*AO_VROW + vs*16,  Vbh + (size_t)(k0 + vr) * DH + vs*8);
        cp16(st + AO_VLO + vr*AO_VROW + vs*16,  Vbl + (size_t)(k0 + vr) * DH + vs*8);
        asm volatile("cp.async.commit_group;" ::: "memory");
    }

    for (int c = 0; c < NC; c++) {
        if (c + 1 < NC) {
            const int k0 = (c + 1) * 32;
            const uint32_t st = sb + ((c + 1) & 1) * AO_STAGE;
            cp16(st + AO_EH + pr0*AO_AROW + ps0*16, Pb + (size_t)(k0 + pr0) * SEQ + ps0*8);
            cp16(st + AO_EH + pr1*AO_AROW + ps1*16, Pb + (size_t)(k0 + pr1) * SEQ + ps1*8);
            cp16(st + AO_VHI + vr*AO_VROW + vs*16,  Vbh + (size_t)(k0 + vr) * DH + vs*8);
            cp16(st + AO_VLO + vr*AO_VROW + vs*16,  Vbl + (size_t)(k0 + vr) * DH + vs*8);
            asm volatile("cp.async.commit_group;" ::: "memory");
            asm volatile("cp.async.wait_group 1;" ::: "memory");
        } else {
            asm volatile("cp.async.wait_group 0;" ::: "memory");
        }
        __syncthreads();

        const uint32_t st = sb + (c & 1) * AO_STAGE;
#pragma unroll
        for (int kk = 0; kk < 2; kk++) {
            uint32_t ah[2][4];
#pragma unroll
            for (int mt = 0; mt < 2; mt++)
                ldm_x4t(ah[mt], st + AO_EH + a_tr + kk * (16 * AO_AROW) + mt * 32);
            uint32_t bh_[4][2], bl_[4][2];
#pragma unroll
            for (int np = 0; np < 2; np++) {
                uint32_t r[4];
                ldm_x4t(r, st + AO_VHI + b_tr + kk * (16 * AO_VROW) + np * 32);
                bh_[2*np][0] = r[0]; bh_[2*np][1] = r[1];
                bh_[2*np+1][0] = r[2]; bh_[2*np+1][1] = r[3];
                ldm_x4t(r, st + AO_VLO + b_tr + kk * (16 * AO_VROW) + np * 32);
                bl_[2*np][0] = r[0]; bl_[2*np][1] = r[1];
                bl_[2*np+1][0] = r[2]; bl_[2*np+1][1] = r[3];
            }
#pragma unroll
            for (int mt = 0; mt < 2; mt++)
#pragma unroll
                for (int nt = 0; nt < 4; nt++) {
                    mma16816_f16(acc[mt][nt], ah[mt], bh_[nt]);
                    mma16816_f16(acc[mt][nt], ah[mt], bl_[nt]);
                }
        }
        __syncthreads();
    }

    const float dsc = 1.f / 4096.f;
    const int g = lane >> 2, cpr = (lane & 3) * 2;
#pragma unroll
    for (int mt = 0; mt < 2; mt++)
#pragma unroll
        for (int nt = 0; nt < 4; nt++) {
            const int q = qt + wm + mt * 16 + g;
            const int col = wn + nt * 8 + cpr;
            float2 p0; p0.x = acc[mt][nt][0] * dsc; p0.y = acc[mt][nt][1] * dsc;
            float2 p1; p1.x = acc[mt][nt][2] * dsc; p1.y = acc[mt][nt][3] * dsc;
            *(float2*)(g_Z + ((size_t)b * SEQ + q)     * LDIM + h * DH + col) = p0;
            *(float2*)(g_Z + ((size_t)b * SEQ + q + 8) * LDIM + h * DH + col) = p1;
        }
}

// ================= row L2 normalize =================
__global__ __launch_bounds__(256) void l2norm_rows(const float* __restrict__ in,
                                                   float* __restrict__ out) {
    const size_t rowi = blockIdx.x;
    const float* p = in + rowi * DIM;
    float* o = out + rowi * DIM;
    const int t = threadIdx.x;
    float v[4];
    float ss = 0.f;
#pragma unroll
    for (int i = 0; i < 4; i++) { v[i] = p[t + 256 * i]; ss += v[i] * v[i]; }
    __shared__ float red[256];
    red[t] = ss; __syncthreads();
    for (int s = 128; s > 0; s >>= 1) {
        if (t < s) red[t] = red[t] + red[t + s];
        __syncthreads();
    }
    const float n = sqrtf(red[0]);
    const float sc = 1.f / fmaxf(n, 1e-12f);
#pragma unroll
    for (int i = 0; i < 4; i++) o[t + 256 * i] = v[i] * sc;
}

// ================= row L2 normalize + exact GELU =================
__global__ __launch_bounds__(256) void l2norm_gelu(const float* __restrict__ in,
                                                   float* __restrict__ out) {
    const size_t rowi = blockIdx.x;
    const float* p = in + rowi * DIM;
    float* o = out + rowi * DIM;
    const int t = threadIdx.x;
    float v[4];
    float ss = 0.f;
#pragma unroll
    for (int i = 0; i < 4; i++) { v[i] = p[t + 256 * i]; ss += v[i] * v[i]; }
    __shared__ float red[256];
    red[t] = ss; __syncthreads();
    for (int s = 128; s > 0; s >>= 1) {
        if (t < s) red[t] = red[t] + red[t + s];
        __syncthreads();
    }
    const float n = sqrtf(red[0]);
    const float sc = 1.f / fmaxf(n, 1e-12f);
#pragma unroll
    for (int i = 0; i < 4; i++) {
        float y = v[i] * sc;
        o[t + 256 * i] = 0.5f * y * (1.f + erff(y * 0.70710678118654752f));
    }
}

// ================= host launcher =================
extern "C" void kernel_launch(void* const* d_in, const int* in_sizes, int n_in,
                              void* d_out, int out_size) {
    const float* x   = (const float*)d_in[0];
    const float* Wq  = (const float*)d_in[1];
    const float* Wk  = (const float*)d_in[2];
    const float* Wv  = (const float*)d_in[3];
    const float* Wo  = (const float*)d_in[4];
    const float* Wff = (const float*)d_in[5];
    float* outp = (float*)d_out;

    float *pQ, *pK, *pV, *pZ, *pZ2, *pSpart, *pSinv;
    __nv_bfloat16 *pAhi, *pAlo, *pWhi, *pWlo;
    __nv_bfloat16 *pQhi, *pQlo, *pKhi, *pKlo;
    __half *pEh, *pVShi, *pVSlo;
    cudaGetSymbolAddress((void**)&pQ,  g_Q);
    cudaGetSymbolAddress((void**)&pK,  g_Kb);
    cudaGetSymbolAddress((void**)&pV,  g_V);
    cudaGetSymbolAddress((void**)&pZ,  g_Z);
    cudaGetSymbolAddress((void**)&pZ2, g_Z2);
    cudaGetSymbolAddress((void**)&pAhi, g_Ahi);
    cudaGetSymbolAddress((void**)&pAlo, g_Alo);
    cudaGetSymbolAddress((void**)&pWhi, g_Whi);
    cudaGetSymbolAddress((void**)&pWlo, g_Wlo);
    cudaGetSymbolAddress((void**)&pQhi, g_Qhi);
    cudaGetSymbolAddress((void**)&pQlo, g_Qlo);
    cudaGetSymbolAddress((void**)&pKhi, g_Khi);
    cudaGetSymbolAddress((void**)&pKlo, g_Klo);
    cudaGetSymbolAddress((void**)&pEh,  g_Eh);
    cudaGetSymbolAddress((void**)&pSpart, g_Spart);
    cudaGetSymbolAddress((void**)&pSinv,  g_Sinv);
    cudaGetSymbolAddress((void**)&pVShi, g_VShi);
    cudaGetSymbolAddress((void**)&pVSlo, g_VSlo);

    cudaFuncSetAttribute(gemm_hmma,       cudaFuncAttributeMaxDynamicSharedMemorySize, SMEM_GEMM);
    cudaFuncSetAttribute(scores_exp_hmma, cudaFuncAttributeMaxDynamicSharedMemorySize, SC_TOTAL);
    cudaFuncSetAttribute(att_out_hmma,    cudaFuncAttributeMaxDynamicSharedMemorySize, AO_TOTAL);

    const dim3 gG(GN / 128, MTOT / 128);    // (8, 32)
    const dim3 gT(DIM / 32, DIM / 32);      // (32, 32)
    const int  splitBlocksX = (MTOT * DIM) / (256 * 4);

    // --- QKV projections (HMMA) ---
    split_bf16<<<splitBlocksX, 256>>>(x, pAhi, pAlo, 1.0f);
    tsplit<<<gT, 256>>>(Wq, pWhi, pWlo);
    gemm_hmma<<<gG, 256, SMEM_GEMM>>>(pAhi, pAlo, pWhi, pWlo, pQ);
    tsplit<<<gT, 256>>>(Wk, pWhi, pWlo);
    gemm_hmma<<<gG, 256, SMEM_GEMM>>>(pAhi, pAlo, pWhi, pWlo, pK);
    tsplit<<<gT, 256>>>(Wv, pWhi, pWlo);
    gemm_hmma<<<gG, 256, SMEM_GEMM>>>(pAhi, pAlo, pWhi, pWlo, pV);

    // --- attention operand splits (Q pre-scaled by 1/32) ---
    split_bf16<<<splitBlocksX, 256>>>(pQ, pQhi, pQlo, 0.03125f);
    split_bf16<<<splitBlocksX, 256>>>(pK, pKhi, pKlo, 1.0f);

    // --- attention: fused scores+exp -> rowsum reduce -> V*4096/S -> PV ---
    scores_exp_hmma<<<dim3(SEQ / 128, SEQ / 128, BHTOT), 256, SC_TOTAL>>>(
        pKhi, pKlo, pQhi, pQlo, pEh, pSpart);
    reduce_S<<<(BHTOT * SEQ) / 256, 256>>>(pSpart, pSinv);
    vscale<<<dim3(SEQ / 4, BHTOT), 256>>>(pV, pSinv, pVShi, pVSlo);
    att_out_hmma<<<dim3(SEQ / 128, BHTOT), 256, AO_TOTAL>>>(pEh, pVShi, pVSlo);

    // --- out projection ---
    split_bf16<<<splitBlocksX, 256>>>(pZ, pAhi, pAlo, 1.0f);
    tsplit<<<gT, 256>>>(Wo, pWhi, pWlo);
    gemm_hmma<<<gG, 256, SMEM_GEMM>>>(pAhi, pAlo, pWhi, pWlo, pZ2);

    // --- normalize -> FFN -> normalize+gelu ---
    l2norm_rows<<<MTOT, 256>>>(pZ2, pZ);
    split_bf16<<<splitBlocksX, 256>>>(pZ, pAhi, pAlo, 1.0f);
    tsplit<<<gT, 256>>>(Wff, pWhi, pWlo);
    gemm_hmma<<<gG, 256, SMEM_GEMM>>>(pAhi, pAlo, pWhi, pWlo, pZ2);
    l2norm_gelu<<<MTOT, 256>>>(pZ2, outp);
}

// round 8
// speedup vs baseline: 3.1523x; 1.0633x over previous
#include <cuda_runtime.h>
#include <cuda_bf16.h>
#include <cuda_fp16.h>
#include <math.h>
#include <cstdint>

#define NBATCH 2
#define SEQ    2048
#define DIM    1024
#define LDIM   1024
#define NH     16
#define DH     64
#define MTOT   (NBATCH*SEQ)   /* 4096 */
#define BHTOT  (NBATCH*NH)    /* 32   */

__device__ __forceinline__ uint32_t smem_u32(const void* p) {
    uint32_t a;
    asm("{ .reg .u64 t; cvta.to.shared.u64 t, %1; cvt.u32.u64 %0, t; }" : "=r"(a) : "l"(p));
    return a;
}

// ================= scratch (static device globals; no allocation) =================
__device__ float g_V [ (size_t)MTOT * LDIM ];
__device__ float g_Z2[ (size_t)MTOT * LDIM ];
__device__ __nv_bfloat16 g_Ahi[ (size_t)MTOT * DIM ];
__device__ __nv_bfloat16 g_Alo[ (size_t)MTOT * DIM ];
__device__ __nv_bfloat16 g_Whi[ (size_t)DIM * DIM ];
__device__ __nv_bfloat16 g_Wlo[ (size_t)DIM * DIM ];
// attention operand splits (bf16, for scores)
__device__ __nv_bfloat16 g_Qhi[ (size_t)MTOT * LDIM ];
__device__ __nv_bfloat16 g_Qlo[ (size_t)MTOT * LDIM ];
__device__ __nv_bfloat16 g_Khi[ (size_t)MTOT * LDIM ];
__device__ __nv_bfloat16 g_Klo[ (size_t)MTOT * LDIM ];
// unnormalized exp(scores) as fp16, [bh][k][q]
__device__ __half g_Eh[ (size_t)BHTOT * SEQ * SEQ ];
// per-(bh, qtile) partial row sums, and inverse row sums
__device__ float g_Spart[ (size_t)BHTOT * (SEQ/128) * SEQ ];
__device__ float g_Sinv [ (size_t)BHTOT * SEQ ];
// (V * 4096 / S) fp16 hi/lo, layout [bh][k][DH]
__device__ __half g_VShi[ (size_t)BHTOT * SEQ * DH ];
__device__ __half g_VSlo[ (size_t)BHTOT * SEQ * DH ];

// ================= HMMA primitives =================
__device__ __forceinline__ void cp16(uint32_t dst, const void* src) {
    asm volatile("cp.async.cg.shared.global [%0], [%1], 16;" :: "r"(dst), "l"(src));
}
__device__ __forceinline__ void ldm_x4(uint32_t* r, uint32_t addr) {
    asm volatile("ldmatrix.sync.aligned.m8n8.x4.shared.b16 {%0,%1,%2,%3}, [%4];"
                 : "=r"(r[0]), "=r"(r[1]), "=r"(r[2]), "=r"(r[3]) : "r"(addr));
}
__device__ __forceinline__ void ldm_x4t(uint32_t* r, uint32_t addr) {
    asm volatile("ldmatrix.sync.aligned.m8n8.x4.trans.shared.b16 {%0,%1,%2,%3}, [%4];"
                 : "=r"(r[0]), "=r"(r[1]), "=r"(r[2]), "=r"(r[3]) : "r"(addr));
}
__device__ __forceinline__ void mma16816(float* c, const uint32_t* a, const uint32_t* b) {
    asm volatile(
        "mma.sync.aligned.m16n8k16.row.col.f32.bf16.bf16.f32 "
        "{%0,%1,%2,%3}, {%4,%5,%6,%7}, {%8,%9}, {%0,%1,%2,%3};"
        : "+f"(c[0]), "+f"(c[1]), "+f"(c[2]), "+f"(c[3])
        : "r"(a[0]), "r"(a[1]), "r"(a[2]), "r"(a[3]), "r"(b[0]), "r"(b[1]));
}
__device__ __forceinline__ void mma16816_f16(float* c, const uint32_t* a, const uint32_t* b) {
    asm volatile(
        "mma.sync.aligned.m16n8k16.row.col.f32.f16.f16.f32 "
        "{%0,%1,%2,%3}, {%4,%5,%6,%7}, {%8,%9}, {%0,%1,%2,%3};"
        : "+f"(c[0]), "+f"(c[1]), "+f"(c[2]), "+f"(c[3])
        : "r"(a[0]), "r"(a[1]), "r"(a[2]), "r"(a[3]), "r"(b[0]), "r"(b[1]));
}

// ================= bf16 split (elementwise, optional scale) =================
__global__ __launch_bounds__(256) void split_bf16(const float* __restrict__ X,
                                                  __nv_bfloat16* __restrict__ hi,
                                                  __nv_bfloat16* __restrict__ lo,
                                                  float scale) {
    const size_t i = ((size_t)blockIdx.x * 256 + threadIdx.x) * 4;
    float4 v = *(const float4*)(X + i);
    v.x *= scale; v.y *= scale; v.z *= scale; v.w *= scale;
    __nv_bfloat16 h0 = __float2bfloat16(v.x);
    __nv_bfloat16 h1 = __float2bfloat16(v.y);
    __nv_bfloat16 h2 = __float2bfloat16(v.z);
    __nv_bfloat16 h3 = __float2bfloat16(v.w);
    __nv_bfloat16 l0 = __float2bfloat16(v.x - __bfloat162float(h0));
    __nv_bfloat16 l1 = __float2bfloat16(v.y - __bfloat162float(h1));
    __nv_bfloat16 l2 = __float2bfloat16(v.z - __bfloat162float(h2));
    __nv_bfloat16 l3 = __float2bfloat16(v.w - __bfloat162float(h3));
    __nv_bfloat162* hp = (__nv_bfloat162*)(hi + i);
    __nv_bfloat162* lp = (__nv_bfloat162*)(lo + i);
    hp[0] = __nv_bfloat162(h0, h1); hp[1] = __nv_bfloat162(h2, h3);
    lp[0] = __nv_bfloat162(l0, l1); lp[1] = __nv_bfloat162(l2, l3);
}

// ================= transpose + split: W[K][N] -> Thi/Tlo [N][K] =================
__global__ __launch_bounds__(256) void tsplit(const float* __restrict__ W,
                                              __nv_bfloat16* __restrict__ Thi,
                                              __nv_bfloat16* __restrict__ Tlo) {
    __shared__ float tile[32][33];
    const int tx = threadIdx.x & 31, ty = threadIdx.x >> 5;
    const int k0 = blockIdx.y * 32, n0 = blockIdx.x * 32;
#pragma unroll
    for (int j = 0; j < 4; j++)
        tile[ty + j * 8][tx] = W[(size_t)(k0 + ty + j * 8) * DIM + n0 + tx];
    __syncthreads();
#pragma unroll
    for (int j = 0; j < 4; j++) {
        const int n = n0 + ty + j * 8, k = k0 + tx;
        float v = tile[tx][ty + j * 8];
        __nv_bfloat16 h = __float2bfloat16(v);
        Thi[(size_t)n * DIM + k] = h;
        Tlo[(size_t)n * DIM + k] = __float2bfloat16(v - __bfloat162float(h));
    }
}

// ================= HMMA bf16-split dense GEMM (templated epilogue) =================
// SPLIT=false: C fp32.  SPLIT=true: write (acc*scale) as bf16 hi/lo to Chi/Clo.
#define GK 1024
#define GN 1024
#define ROWB 80
#define BUFB (128 * ROWB)
#define STAGEB (4 * BUFB)
#define SMEM_GEMM (2 * STAGEB)

template<bool SPLIT>
__global__ __launch_bounds__(256, 2)
void gemm_hmma_t(const __nv_bfloat16* __restrict__ Ahi, const __nv_bfloat16* __restrict__ Alo,
                 const __nv_bfloat16* __restrict__ Bhi, const __nv_bfloat16* __restrict__ Blo,
                 float* __restrict__ C,
                 __nv_bfloat16* __restrict__ Chi, __nv_bfloat16* __restrict__ Clo,
                 float scale) {
    extern __shared__ char sm[];
    const uint32_t sb = smem_u32(sm);
    const int tid = threadIdx.x;
    const int lane = tid & 31;
    const int wid = tid >> 5;
    const int m0 = blockIdx.y * 128, n0 = blockIdx.x * 128;
    const int wm = (wid & 1) * 64;
    const int wn = (wid >> 1) * 32;

    const int r0g = tid >> 2, s0g = tid & 3;
    const int r1g = (tid + 256) >> 2, s1g = tid & 3;

    const uint32_t a_off = (uint32_t)((wm + (lane & 15)) * ROWB + ((lane >> 4) << 3) * 2);
    const uint32_t b_off = (uint32_t)((wn + ((lane >> 4) << 3) + (lane & 7)) * ROWB + (lane & 8) * 2);

    float acc[4][4][4];
#pragma unroll
    for (int i = 0; i < 4; i++)
#pragma unroll
        for (int j = 0; j < 4; j++)
#pragma unroll
            for (int e = 0; e < 4; e++) acc[i][j][e] = 0.f;

    const int NC = GK / 32;
    {
        uint32_t st = sb;
        cp16(st + 0*BUFB + r0g*ROWB + s0g*16, Ahi + (size_t)(m0 + r0g)*GK + s0g*8);
        cp16(st + 0*BUFB + r1g*ROWB + s1g*16, Ahi + (size_t)(m0 + r1g)*GK + s1g*8);
        cp16(st + 1*BUFB + r0g*ROWB + s0g*16, Alo + (size_t)(m0 + r0g)*GK + s0g*8);
        cp16(st + 1*BUFB + r1g*ROWB + s1g*16, Alo + (size_t)(m0 + r1g)*GK + s1g*8);
        cp16(st + 2*BUFB + r0g*ROWB + s0g*16, Bhi + (size_t)(n0 + r0g)*GK + s0g*8);
        cp16(st + 2*BUFB + r1g*ROWB + s1g*16, Bhi + (size_t)(n0 + r1g)*GK + s1g*8);
        cp16(st + 3*BUFB + r0g*ROWB + s0g*16, Blo + (size_t)(n0 + r0g)*GK + s0g*8);
        cp16(st + 3*BUFB + r1g*ROWB + s1g*16, Blo + (size_t)(n0 + r1g)*GK + s1g*8);
        asm volatile("cp.async.commit_group;" ::: "memory");
    }

    for (int c = 0; c < NC; c++) {
        if (c + 1 < NC) {
            const int kc = (c + 1) * 32;
            uint32_t st = sb + ((c + 1) & 1) * STAGEB;
            cp16(st + 0*BUFB + r0g*ROWB + s0g*16, Ahi + (size_t)(m0 + r0g)*GK + kc + s0g*8);
            cp16(st + 0*BUFB + r1g*ROWB + s1g*16, Ahi + (size_t)(m0 + r1g)*GK + kc + s1g*8);
            cp16(st + 1*BUFB + r0g*ROWB + s0g*16, Alo + (size_t)(m0 + r0g)*GK + kc + s0g*8);
            cp16(st + 1*BUFB + r1g*ROWB + s1g*16, Alo + (size_t)(m0 + r1g)*GK + kc + s1g*8);
            cp16(st + 2*BUFB + r0g*ROWB + s0g*16, Bhi + (size_t)(n0 + r0g)*GK + kc + s0g*8);
            cp16(st + 2*BUFB + r1g*ROWB + s1g*16, Bhi + (size_t)(n0 + r1g)*GK + kc + s1g*8);
            cp16(st + 3*BUFB + r0g*ROWB + s0g*16, Blo + (size_t)(n0 + r0g)*GK + kc + s0g*8);
            cp16(st + 3*BUFB + r1g*ROWB + s1g*16, Blo + (size_t)(n0 + r1g)*GK + kc + s1g*8);
            asm volatile("cp.async.commit_group;" ::: "memory");
            asm volatile("cp.async.wait_group 1;" ::: "memory");
        } else {
            asm volatile("cp.async.wait_group 0;" ::: "memory");
        }
        __syncthreads();

        const uint32_t st = sb + (c & 1) * STAGEB;
#pragma unroll
        for (int kk = 0; kk < 2; kk++) {
            const uint32_t kb = kk * 32;
            uint32_t ahi[4][4], alo[4][4];
#pragma unroll
            for (int mt = 0; mt < 4; mt++) {
                ldm_x4(ahi[mt], st + 0*BUFB + a_off + mt * (16 * ROWB) + kb);
                ldm_x4(alo[mt], st + 1*BUFB + a_off + mt * (16 * ROWB) + kb);
            }
            uint32_t bhi[4][2], blo[4][2];
#pragma unroll
            for (int np = 0; np < 2; np++) {
                uint32_t r[4];
                ldm_x4(r, st + 2*BUFB + b_off + np * (16 * ROWB) + kb);
                bhi[2*np][0] = r[0]; bhi[2*np][1] = r[1];
                bhi[2*np+1][0] = r[2]; bhi[2*np+1][1] = r[3];
                ldm_x4(r, st + 3*BUFB + b_off + np * (16 * ROWB) + kb);
                blo[2*np][0] = r[0]; blo[2*np][1] = r[1];
                blo[2*np+1][0] = r[2]; blo[2*np+1][1] = r[3];
            }
#pragma unroll
            for (int mt = 0; mt < 4; mt++)
#pragma unroll
                for (int nt = 0; nt < 4; nt++) {
                    mma16816(acc[mt][nt], ahi[mt], bhi[nt]);
                    mma16816(acc[mt][nt], ahi[mt], blo[nt]);
                    mma16816(acc[mt][nt], alo[mt], bhi[nt]);
                }
        }
        __syncthreads();
    }

    const int g = lane >> 2, cpr = (lane & 3) * 2;
#pragma unroll
    for (int mt = 0; mt < 4; mt++)
#pragma unroll
        for (int nt = 0; nt < 4; nt++) {
            const int row = m0 + wm + mt * 16 + g;
            const int col = n0 + wn + nt * 8 + cpr;
            if (SPLIT) {
                float v0 = acc[mt][nt][0] * scale, v1 = acc[mt][nt][1] * scale;
                float v2 = acc[mt][nt][2] * scale, v3 = acc[mt][nt][3] * scale;
                __nv_bfloat16 h0 = __float2bfloat16(v0), h1 = __float2bfloat16(v1);
                __nv_bfloat16 h2 = __float2bfloat16(v2), h3 = __float2bfloat16(v3);
                *(__nv_bfloat162*)(Chi + (size_t)row * GN + col)       = __nv_bfloat162(h0, h1);
                *(__nv_bfloat162*)(Chi + (size_t)(row + 8) * GN + col) = __nv_bfloat162(h2, h3);
                *(__nv_bfloat162*)(Clo + (size_t)row * GN + col) =
                    __nv_bfloat162(__float2bfloat16(v0 - __bfloat162float(h0)),
                                   __float2bfloat16(v1 - __bfloat162float(h1)));
                *(__nv_bfloat162*)(Clo + (size_t)(row + 8) * GN + col) =
                    __nv_bfloat162(__float2bfloat16(v2 - __bfloat162float(h2)),
                                   __float2bfloat16(v3 - __bfloat162float(h3)));
            } else {
                float2 lo_pair; lo_pair.x = acc[mt][nt][0]; lo_pair.y = acc[mt][nt][1];
                float2 hi_pair; hi_pair.x = acc[mt][nt][2]; hi_pair.y = acc[mt][nt][3];
                *(float2*)(C + (size_t)row * GN + col)       = lo_pair;
                *(float2*)(C + (size_t)(row + 8) * GN + col) = hi_pair;
            }
        }
}

// ================= HMMA scores + exp fused; E stored fp16 =================
#define SC_ROWB 144
#define SC_BUF  (128 * SC_ROWB)   /* 18432 */
#define SC_TOTAL (4 * SC_BUF)     /* 73728 */

__global__ __launch_bounds__(256, 2)
void scores_exp_hmma(const __nv_bfloat16* __restrict__ Khi, const __nv_bfloat16* __restrict__ Klo,
                     const __nv_bfloat16* __restrict__ Qhi, const __nv_bfloat16* __restrict__ Qlo,
                     __half* __restrict__ Eh, float* __restrict__ Spart) {
    extern __shared__ char sm[];
    __shared__ float part[4][128];
    const uint32_t sb = smem_u32(sm);
    const int tid = threadIdx.x;
    const int lane = tid & 31;
    const int wid = tid >> 5;
    const int bh = blockIdx.z;
    const int b = bh >> 4, h = bh & 15;
    const int kt = blockIdx.y * 128;
    const int qt = blockIdx.x * 128;

    const __nv_bfloat16* Ah = Khi + ((size_t)(b * SEQ + kt)) * LDIM + h * DH;
    const __nv_bfloat16* Al = Klo + ((size_t)(b * SEQ + kt)) * LDIM + h * DH;
    const __nv_bfloat16* Bh = Qhi + ((size_t)(b * SEQ + qt)) * LDIM + h * DH;
    const __nv_bfloat16* Bl = Qlo + ((size_t)(b * SEQ + qt)) * LDIM + h * DH;

#pragma unroll
    for (int i = 0; i < 4; i++) {
        const int cid = tid + i * 256;
        const int row = cid >> 3, seg = cid & 7;
        const uint32_t d = row * SC_ROWB + seg * 16;
        const size_t goff = (size_t)row * LDIM + seg * 8;
        cp16(sb + 0*SC_BUF + d, Ah + goff);
        cp16(sb + 1*SC_BUF + d, Al + goff);
        cp16(sb + 2*SC_BUF + d, Bh + goff);
        cp16(sb + 3*SC_BUF + d, Bl + goff);
    }
    asm volatile("cp.async.commit_group;" ::: "memory");
    asm volatile("cp.async.wait_group 0;" ::: "memory");
    __syncthreads();

    const int wm = (wid & 1) * 64;
    const int wn = (wid >> 1) * 32;
    const int wc = wid >> 1;
    const uint32_t a_off = (uint32_t)((wm + (lane & 15)) * SC_ROWB + ((lane >> 4) << 3) * 2);
    const uint32_t b_off = (uint32_t)((wn + ((lane >> 4) << 3) + (lane & 7)) * SC_ROWB + (lane & 8) * 2);

    float acc[4][4][4];
#pragma unroll
    for (int i = 0; i < 4; i++)
#pragma unroll
        for (int j = 0; j < 4; j++)
#pragma unroll
            for (int e = 0; e < 4; e++) acc[i][j][e] = 0.f;

#pragma unroll
    for (int kk = 0; kk < 4; kk++) {
        const uint32_t kb = kk * 32;
        uint32_t ahi[4][4], alo[4][4];
#pragma unroll
        for (int mt = 0; mt < 4; mt++) {
            ldm_x4(ahi[mt], sb + 0*SC_BUF + a_off + mt * (16 * SC_ROWB) + kb);
            ldm_x4(alo[mt], sb + 1*SC_BUF + a_off + mt * (16 * SC_ROWB) + kb);
        }
        uint32_t bhi[4][2], blo[4][2];
#pragma unroll
        for (int np = 0; np < 2; np++) {
            uint32_t r[4];
            ldm_x4(r, sb + 2*SC_BUF + b_off + np * (16 * SC_ROWB) + kb);
            bhi[2*np][0] = r[0]; bhi[2*np][1] = r[1];
            bhi[2*np+1][0] = r[2]; bhi[2*np+1][1] = r[3];
            ldm_x4(r, sb + 3*SC_BUF + b_off + np * (16 * SC_ROWB) + kb);
            blo[2*np][0] = r[0]; blo[2*np][1] = r[1];
            blo[2*np+1][0] = r[2]; blo[2*np+1][1] = r[3];
        }
#pragma unroll
        for (int mt = 0; mt < 4; mt++)
#pragma unroll
            for (int nt = 0; nt < 4; nt++) {
                mma16816(acc[mt][nt], ahi[mt], bhi[nt]);
                mma16816(acc[mt][nt], ahi[mt], blo[nt]);
                mma16816(acc[mt][nt], alo[mt], bhi[nt]);
            }
    }

    // epilogue: exp, fp16 store, row-sum partials (fp32)
    const int g = lane >> 2, cpr = (lane & 3) * 2;
    __half* EH = Eh + (size_t)bh * SEQ * SEQ;
    float rowsum[8];
#pragma unroll
    for (int i = 0; i < 8; i++) rowsum[i] = 0.f;

#pragma unroll
    for (int mt = 0; mt < 4; mt++)
#pragma unroll
        for (int nt = 0; nt < 4; nt++) {
            const int row = kt + wm + mt * 16 + g;
            const int col = qt + wn + nt * 8 + cpr;
            float e0 = __expf(acc[mt][nt][0]);
            float e1 = __expf(acc[mt][nt][1]);
            float e2 = __expf(acc[mt][nt][2]);
            float e3 = __expf(acc[mt][nt][3]);
            *(__half2*)(EH + (size_t)row * SEQ + col)       = __floats2half2_rn(e0, e1);
            *(__half2*)(EH + (size_t)(row + 8) * SEQ + col) = __floats2half2_rn(e2, e3);
            rowsum[mt * 2 + 0] += e0 + e1;
            rowsum[mt * 2 + 1] += e2 + e3;
        }
#pragma unroll
    for (int i = 0; i < 8; i++) {
        rowsum[i] += __shfl_xor_sync(0xffffffffu, rowsum[i], 1);
        rowsum[i] += __shfl_xor_sync(0xffffffffu, rowsum[i], 2);
    }
    if ((lane & 3) == 0) {
#pragma unroll
        for (int mt = 0; mt < 4; mt++) {
            part[wc][wm + mt * 16 + g]     = rowsum[mt * 2 + 0];
            part[wc][wm + mt * 16 + g + 8] = rowsum[mt * 2 + 1];
        }
    }
    __syncthreads();
    if (tid < 128) {
        const float s = part[0][tid] + part[1][tid] + part[2][tid] + part[3][tid];
        Spart[((size_t)bh * (SEQ/128) + blockIdx.x) * SEQ + kt + tid] = s;
    }
}

// ================= reduce partials -> 1/S =================
__global__ __launch_bounds__(256) void reduce_S(const float* __restrict__ Spart,
                                                float* __restrict__ Sinv) {
    const int idx = blockIdx.x * 256 + threadIdx.x;
    const int bh = idx >> 11, k = idx & (SEQ - 1);
    float s = 0.f;
#pragma unroll
    for (int qt = 0; qt < SEQ/128; qt++)
        s += Spart[((size_t)bh * (SEQ/128) + qt) * SEQ + k];
    Sinv[idx] = 1.f / s;
}

// ================= V * (4096/S) -> fp16 hi/lo, layout [bh][k][DH] =================
__global__ __launch_bounds__(256) void vscale(const float* __restrict__ V,
                                              const float* __restrict__ Sinv,
                                              __half* __restrict__ VShi,
                                              __half* __restrict__ VSlo) {
    const int bh = blockIdx.y;
    const int b = bh >> 4, h = bh & 15;
    const int row = blockIdx.x * 4 + (threadIdx.x >> 6);
    const int d = threadIdx.x & 63;
    const float inv = Sinv[bh * SEQ + row] * 4096.f;
    const float v = V[((size_t)b * SEQ + row) * LDIM + h * DH + d] * inv;
    const __half hv = __float2half_rn(v);
    VShi[((size_t)bh * SEQ + row) * DH + d] = hv;
    VSlo[((size_t)bh * SEQ + row) * DH + d] = __float2half_rn(v - __half2float(hv));
}

// ================= HMMA att_out (fp16): Z split bf16 = (sum_k E*Vs)/4096 =================
#define AO_AROW 272
#define AO_ABUF (32 * AO_AROW)   /* 8704 */
#define AO_VROW 144
#define AO_VBUF (32 * AO_VROW)   /* 4608 */
#define AO_EH  0
#define AO_VHI AO_ABUF
#define AO_VLO (AO_ABUF + AO_VBUF)
#define AO_STAGE (AO_ABUF + 2 * AO_VBUF)   /* 17920 */
#define AO_TOTAL (2 * AO_STAGE)            /* 35840 */

__global__ __launch_bounds__(256, 2)
void att_out_hmma(const __half* __restrict__ Eh,
                  const __half* __restrict__ VShi, const __half* __restrict__ VSlo,
                  __nv_bfloat16* __restrict__ Zhi, __nv_bfloat16* __restrict__ Zlo) {
    extern __shared__ char sm[];
    const uint32_t sb = smem_u32(sm);
    const int tid = threadIdx.x;
    const int lane = tid & 31;
    const int wid = tid >> 5;
    const int qt = blockIdx.x * 128;
    const int bh = blockIdx.y;
    const int b = bh >> 4, h = bh & 15;

    const __half* Pb = Eh + (size_t)bh * SEQ * SEQ + qt;
    const __half* Vbh = VShi + (size_t)bh * SEQ * DH;
    const __half* Vbl = VSlo + (size_t)bh * SEQ * DH;

    const int pr0 = tid >> 4, ps0 = tid & 15;
    const int pr1 = (tid + 256) >> 4, ps1 = tid & 15;
    const int vr = tid >> 3, vs = tid & 7;

    const int wm = (wid & 3) * 32;
    const int wn = (wid >> 2) * 32;

    const uint32_t a_tr = (uint32_t)(((lane & 7) + ((lane >> 4) << 3)) * AO_AROW + (wm + (lane & 8)) * 2);
    const uint32_t b_tr = (uint32_t)(((lane & 7) + (lane & 8)) * AO_VROW + (wn + ((lane >> 4) << 3)) * 2);

    float acc[2][4][4];
#pragma unroll
    for (int i = 0; i < 2; i++)
#pragma unroll
        for (int j = 0; j < 4; j++)
#pragma unroll
            for (int e = 0; e < 4; e++) acc[i][j][e] = 0.f;

    const int NC = SEQ / 32;   // 64

    {
        const int k0 = 0;
        const uint32_t st = sb;
        cp16(st + AO_EH + pr0*AO_AROW + ps0*16, Pb + (size_t)(k0 + pr0) * SEQ + ps0*8);
        cp16(st + AO_EH + pr1*AO_AROW + ps1*16, Pb + (size_t)(k0 + pr1) * SEQ + ps1*8);
        cp16(st + AO_VHI + vr*AO_VROW + vs*16,  Vbh + (size_t)(k0 + vr) * DH + vs*8);
        cp16(st + AO_VLO + vr*AO_VROW + vs*16,  Vbl + (size_t)(k0 + vr) * DH + vs*8);
        asm volatile("cp.async.commit_group;" ::: "memory");
    }

    for (int c = 0; c < NC; c++) {
        if (c + 1 < NC) {
            const int k0 = (c + 1) * 32;
            const uint32_t st = sb + ((c + 1) & 1) * AO_STAGE;
            cp16(st + AO_EH + pr0*AO_AROW + ps0*16, Pb + (size_t)(k0 + pr0) * SEQ + ps0*8);
            cp16(st + AO_EH + pr1*AO_AROW + ps1*16, Pb + (size_t)(k0 + pr1) * SEQ + ps1*8);
            cp16(st + AO_VHI + vr*AO_VROW + vs*16,  Vbh + (size_t)(k0 + vr) * DH + vs*8);
            cp16(st + AO_VLO + vr*AO_VROW + vs*16,  Vbl + (size_t)(k0 + vr) * DH + vs*8);
            asm volatile("cp.async.commit_group;" ::: "memory");
            asm volatile("cp.async.wait_group 1;" ::: "memory");
        } else {
            asm volatile("cp.async.wait_group 0;" ::: "memory");
        }
        __syncthreads();

        const uint32_t st = sb + (c & 1) * AO_STAGE;
#pragma unroll
        for (int kk = 0; kk < 2; kk++) {
            uint32_t ah[2][4];
#pragma unroll
            for (int mt = 0; mt < 2; mt++)
                ldm_x4t(ah[mt], st + AO_EH + a_tr + kk * (16 * AO_AROW) + mt * 32);
            uint32_t bh_[4][2], bl_[4][2];
#pragma unroll
            for (int np = 0; np < 2; np++) {
                uint32_t r[4];
                ldm_x4t(r, st + AO_VHI + b_tr + kk * (16 * AO_VROW) + np * 32);
                bh_[2*np][0] = r[0]; bh_[2*np][1] = r[1];
                bh_[2*np+1][0] = r[2]; bh_[2*np+1][1] = r[3];
                ldm_x4t(r, st + AO_VLO + b_tr + kk * (16 * AO_VROW) + np * 32);
                bl_[2*np][0] = r[0]; bl_[2*np][1] = r[1];
                bl_[2*np+1][0] = r[2]; bl_[2*np+1][1] = r[3];
            }
#pragma unroll
            for (int mt = 0; mt < 2; mt++)
#pragma unroll
                for (int nt = 0; nt < 4; nt++) {
                    mma16816_f16(acc[mt][nt], ah[mt], bh_[nt]);
                    mma16816_f16(acc[mt][nt], ah[mt], bl_[nt]);
                }
        }
        __syncthreads();
    }

    const float dsc = 1.f / 4096.f;
    const int g = lane >> 2, cpr = (lane & 3) * 2;
#pragma unroll
    for (int mt = 0; mt < 2; mt++)
#pragma unroll
        for (int nt = 0; nt < 4; nt++) {
            const int q = qt + wm + mt * 16 + g;
            const int col = wn + nt * 8 + cpr;
            float v0 = acc[mt][nt][0] * dsc, v1 = acc[mt][nt][1] * dsc;
            float v2 = acc[mt][nt][2] * dsc, v3 = acc[mt][nt][3] * dsc;
            __nv_bfloat16 h0 = __float2bfloat16(v0), h1 = __float2bfloat16(v1);
            __nv_bfloat16 h2 = __float2bfloat16(v2), h3 = __float2bfloat16(v3);
            const size_t o0 = ((size_t)b * SEQ + q)     * LDIM + h * DH + col;
            const size_t o1 = ((size_t)b * SEQ + q + 8) * LDIM + h * DH + col;
            *(__nv_bfloat162*)(Zhi + o0) = __nv_bfloat162(h0, h1);
            *(__nv_bfloat162*)(Zhi + o1) = __nv_bfloat162(h2, h3);
            *(__nv_bfloat162*)(Zlo + o0) =
                __nv_bfloat162(__float2bfloat16(v0 - __bfloat162float(h0)),
                               __float2bfloat16(v1 - __bfloat162float(h1)));
            *(__nv_bfloat162*)(Zlo + o1) =
                __nv_bfloat162(__float2bfloat16(v2 - __bfloat162float(h2)),
                               __float2bfloat16(v3 - __bfloat162float(h3)));
        }
}

// ================= row L2 normalize -> bf16 hi/lo split =================
__global__ __launch_bounds__(256) void l2norm_split(const float* __restrict__ in,
                                                    __nv_bfloat16* __restrict__ hi,
                                                    __nv_bfloat16* __restrict__ lo) {
    const size_t rowi = blockIdx.x;
    const float* p = in + rowi * DIM;
    const int t = threadIdx.x;
    float v[4];
    float ss = 0.f;
#pragma unroll
    for (int i = 0; i < 4; i++) { v[i] = p[t + 256 * i]; ss += v[i] * v[i]; }
    __shared__ float red[256];
    red[t] = ss; __syncthreads();
    for (int s = 128; s > 0; s >>= 1) {
        if (t < s) red[t] = red[t] + red[t + s];
        __syncthreads();
    }
    const float n = sqrtf(red[0]);
    const float sc = 1.f / fmaxf(n, 1e-12f);
#pragma unroll
    for (int i = 0; i < 4; i++) {
        const float y = v[i] * sc;
        const __nv_bfloat16 hv = __float2bfloat16(y);
        hi[rowi * DIM + t + 256 * i] = hv;
        lo[rowi * DIM + t + 256 * i] = __float2bfloat16(y - __bfloat162float(hv));
    }
}

// ================= row L2 normalize + exact GELU =================
__global__ __launch_bounds__(256) void l2norm_gelu(const float* __restrict__ in,
                                                   float* __restrict__ out) {
    const size_t rowi = blockIdx.x;
    const float* p = in + rowi * DIM;
    float* o = out + rowi * DIM;
    const int t = threadIdx.x;
    float v[4];
    float ss = 0.f;
#pragma unroll
    for (int i = 0; i < 4; i++) { v[i] = p[t + 256 * i]; ss += v[i] * v[i]; }
    __shared__ float red[256];
    red[t] = ss; __syncthreads();
    for (int s = 128; s > 0; s >>= 1) {
        if (t < s) red[t] = red[t] + red[t + s];
        __syncthreads();
    }
    const float n = sqrtf(red[0]);
    const float sc = 1.f / fmaxf(n, 1e-12f);
#pragma unroll
    for (int i = 0; i < 4; i++) {
        float y = v[i] * sc;
        o[t + 256 * i] = 0.5f * y * (1.f + erff(y * 0.70710678118654752f));
    }
}

// ================= host launcher =================
extern "C" void kernel_launch(void* const* d_in, const int* in_sizes, int n_in,
                              void* d_out, int out_size) {
    const float* x   = (const float*)d_in[0];
    const float* Wq  = (const float*)d_in[1];
    const float* Wk  = (const float*)d_in[2];
    const float* Wv  = (const float*)d_in[3];
    const float* Wo  = (const float*)d_in[4];
    const float* Wff = (const float*)d_in[5];
    float* outp = (float*)d_out;

    float *pV, *pZ2, *pSpart, *pSinv;
    __nv_bfloat16 *pAhi, *pAlo, *pWhi, *pWlo;
    __nv_bfloat16 *pQhi, *pQlo, *pKhi, *pKlo;
    __half *pEh, *pVShi, *pVSlo;
    cudaGetSymbolAddress((void**)&pV,  g_V);
    cudaGetSymbolAddress((void**)&pZ2, g_Z2);
    cudaGetSymbolAddress((void**)&pAhi, g_Ahi);
    cudaGetSymbolAddress((void**)&pAlo, g_Alo);
    cudaGetSymbolAddress((void**)&pWhi, g_Whi);
    cudaGetSymbolAddress((void**)&pWlo, g_Wlo);
    cudaGetSymbolAddress((void**)&pQhi, g_Qhi);
    cudaGetSymbolAddress((void**)&pQlo, g_Qlo);
    cudaGetSymbolAddress((void**)&pKhi, g_Khi);
    cudaGetSymbolAddress((void**)&pKlo, g_Klo);
    cudaGetSymbolAddress((void**)&pEh,  g_Eh);
    cudaGetSymbolAddress((void**)&pSpart, g_Spart);
    cudaGetSymbolAddress((void**)&pSinv,  g_Sinv);
    cudaGetSymbolAddress((void**)&pVShi, g_VShi);
    cudaGetSymbolAddress((void**)&pVSlo, g_VSlo);

    cudaFuncSetAttribute(gemm_hmma_t<false>, cudaFuncAttributeMaxDynamicSharedMemorySize, SMEM_GEMM);
    cudaFuncSetAttribute(gemm_hmma_t<true>,  cudaFuncAttributeMaxDynamicSharedMemorySize, SMEM_GEMM);
    cudaFuncSetAttribute(scores_exp_hmma,    cudaFuncAttributeMaxDynamicSharedMemorySize, SC_TOTAL);
    cudaFuncSetAttribute(att_out_hmma,       cudaFuncAttributeMaxDynamicSharedMemorySize, AO_TOTAL);

    const dim3 gG(GN / 128, MTOT / 128);    // (8, 32)
    const dim3 gT(DIM / 32, DIM / 32);      // (32, 32)
    const int  splitBlocksX = (MTOT * DIM) / (256 * 4);

    // --- QKV projections (HMMA); Q/K write split directly (Q pre-scaled 1/32) ---
    split_bf16<<<splitBlocksX, 256>>>(x, pAhi, pAlo, 1.0f);
    tsplit<<<gT, 256>>>(Wq, pWhi, pWlo);
    gemm_hmma_t<true><<<gG, 256, SMEM_GEMM>>>(pAhi, pAlo, pWhi, pWlo, nullptr, pQhi, pQlo, 0.03125f);
    tsplit<<<gT, 256>>>(Wk, pWhi, pWlo);
    gemm_hmma_t<true><<<gG, 256, SMEM_GEMM>>>(pAhi, pAlo, pWhi, pWlo, nullptr, pKhi, pKlo, 1.0f);
    tsplit<<<gT, 256>>>(Wv, pWhi, pWlo);
    gemm_hmma_t<false><<<gG, 256, SMEM_GEMM>>>(pAhi, pAlo, pWhi, pWlo, pV, nullptr, nullptr, 1.0f);

    // --- attention: fused scores+exp -> rowsum reduce -> V*4096/S -> PV (Z split out) ---
    scores_exp_hmma<<<dim3(SEQ / 128, SEQ / 128, BHTOT), 256, SC_TOTAL>>>(
        pKhi, pKlo, pQhi, pQlo, pEh, pSpart);
    reduce_S<<<(BHTOT * SEQ) / 256, 256>>>(pSpart, pSinv);
    vscale<<<dim3(SEQ / 4, BHTOT), 256>>>(pV, pSinv, pVShi, pVSlo);
    att_out_hmma<<<dim3(SEQ / 128, BHTOT), 256, AO_TOTAL>>>(pEh, pVShi, pVSlo, pAhi, pAlo);

    // --- out projection (A = Z split from att_out) ---
    tsplit<<<gT, 256>>>(Wo, pWhi, pWlo);
    gemm_hmma_t<false><<<gG, 256, SMEM_GEMM>>>(pAhi, pAlo, pWhi, pWlo, pZ2, nullptr, nullptr, 1.0f);

    // --- normalize (split out) -> FFN -> normalize+gelu ---
    l2norm_split<<<MTOT, 256>>>(pZ2, pAhi, pAlo);
    tsplit<<<gT, 256>>>(Wff, pWhi, pWlo);
    gemm_hmma_t<false><<<gG, 256, SMEM_GEMM>>>(pAhi, pAlo, pWhi, pWlo, pZ2, nullptr, nullptr, 1.0f);
    l2norm_gelu<<<MTOT, 256>>>(pZ2, outp);
}

// round 11
// speedup vs baseline: 3.6978x; 1.1731x over previous
#include <cuda_runtime.h>
#include <cuda_bf16.h>
#include <cuda_fp16.h>
#include <math.h>
#include <cstdint>

#define NBATCH 2
#define SEQ    2048
#define DIM    1024
#define LDIM   1024
#define NH     16
#define DH     64
#define MTOT   (NBATCH*SEQ)   /* 4096 */
#define BHTOT  (NBATCH*NH)    /* 32   */

__device__ __forceinline__ uint32_t smem_u32(const void* p) {
    uint32_t a;
    asm("{ .reg .u64 t; cvta.to.shared.u64 t, %1; cvt.u32.u64 %0, t; }" : "=r"(a) : "l"(p));
    return a;
}

// ================= scratch (static device globals; no allocation) =================
__device__ float g_V [ (size_t)MTOT * LDIM ];          // V projection fp32
__device__ float g_Z2[ (size_t)MTOT * LDIM ];          // fp32 staging (Wo out, Wff out)
// x split (bf16) for QKV GEMMs
__device__ __nv_bfloat16 g_Ahi[ (size_t)MTOT * DIM ];
__device__ __nv_bfloat16 g_Alo[ (size_t)MTOT * DIM ];
// weight splits: QKV bf16 pairs; Wo/Wff fp16 pairs (all [N][K] transposed)
__device__ __nv_bfloat16 g_Wqh[ (size_t)DIM * DIM ];
__device__ __nv_bfloat16 g_Wql[ (size_t)DIM * DIM ];
__device__ __nv_bfloat16 g_Wkh[ (size_t)DIM * DIM ];
__device__ __nv_bfloat16 g_Wkl[ (size_t)DIM * DIM ];
__device__ __nv_bfloat16 g_Wvh[ (size_t)DIM * DIM ];
__device__ __nv_bfloat16 g_Wvl[ (size_t)DIM * DIM ];
__device__ __half g_Woh[ (size_t)DIM * DIM ];
__device__ __half g_Wol[ (size_t)DIM * DIM ];
__device__ __half g_Wfh[ (size_t)DIM * DIM ];
__device__ __half g_Wfl[ (size_t)DIM * DIM ];
// Q (pre-scaled 1/32) and K as single fp16
__device__ __half g_Q16[ (size_t)MTOT * LDIM ];
__device__ __half g_K16[ (size_t)MTOT * LDIM ];
// unnormalized exp(scores) fp16 [bh][k][q]
__device__ __half g_Eh[ (size_t)BHTOT * SEQ * SEQ ];
// row-sum partials and inverses
__device__ float g_Spart[ (size_t)BHTOT * (SEQ/128) * SEQ ];
__device__ float g_Sinv [ (size_t)BHTOT * SEQ ];
// (V * 4096 / S) fp16 hi/lo [bh][k][DH]
__device__ __half g_VShi[ (size_t)BHTOT * SEQ * DH ];
__device__ __half g_VSlo[ (size_t)BHTOT * SEQ * DH ];
// attention output as fp16 [MTOT][1024], and l2norm output fp16
__device__ __half g_Z16[ (size_t)MTOT * DIM ];
__device__ __half g_N16[ (size_t)MTOT * DIM ];

// ================= HMMA primitives =================
__device__ __forceinline__ void cp16(uint32_t dst, const void* src) {
    asm volatile("cp.async.cg.shared.global [%0], [%1], 16;" :: "r"(dst), "l"(src));
}
__device__ __forceinline__ void ldm_x4(uint32_t* r, uint32_t addr) {
    asm volatile("ldmatrix.sync.aligned.m8n8.x4.shared.b16 {%0,%1,%2,%3}, [%4];"
                 : "=r"(r[0]), "=r"(r[1]), "=r"(r[2]), "=r"(r[3]) : "r"(addr));
}
__device__ __forceinline__ void ldm_x4t(uint32_t* r, uint32_t addr) {
    asm volatile("ldmatrix.sync.aligned.m8n8.x4.trans.shared.b16 {%0,%1,%2,%3}, [%4];"
                 : "=r"(r[0]), "=r"(r[1]), "=r"(r[2]), "=r"(r[3]) : "r"(addr));
}
__device__ __forceinline__ void mma16816(float* c, const uint32_t* a, const uint32_t* b) {
    asm volatile(
        "mma.sync.aligned.m16n8k16.row.col.f32.bf16.bf16.f32 "
        "{%0,%1,%2,%3}, {%4,%5,%6,%7}, {%8,%9}, {%0,%1,%2,%3};"
        : "+f"(c[0]), "+f"(c[1]), "+f"(c[2]), "+f"(c[3])
        : "r"(a[0]), "r"(a[1]), "r"(a[2]), "r"(a[3]), "r"(b[0]), "r"(b[1]));
}
__device__ __forceinline__ void mma16816_f16(float* c, const uint32_t* a, const uint32_t* b) {
    asm volatile(
        "mma.sync.aligned.m16n8k16.row.col.f32.f16.f16.f32 "
        "{%0,%1,%2,%3}, {%4,%5,%6,%7}, {%8,%9}, {%0,%1,%2,%3};"
        : "+f"(c[0]), "+f"(c[1]), "+f"(c[2]), "+f"(c[3])
        : "r"(a[0]), "r"(a[1]), "r"(a[2]), "r"(a[3]), "r"(b[0]), "r"(b[1]));
}

// ================= x -> bf16 hi/lo =================
__global__ __launch_bounds__(256) void split_bf16(const float* __restrict__ X,
                                                  __nv_bfloat16* __restrict__ hi,
                                                  __nv_bfloat16* __restrict__ lo) {
    const size_t i = ((size_t)blockIdx.x * 256 + threadIdx.x) * 4;
    float4 v = *(const float4*)(X + i);
    __nv_bfloat16 h0 = __float2bfloat16(v.x);
    __nv_bfloat16 h1 = __float2bfloat16(v.y);
    __nv_bfloat16 h2 = __float2bfloat16(v.z);
    __nv_bfloat16 h3 = __float2bfloat16(v.w);
    __nv_bfloat162* hp = (__nv_bfloat162*)(hi + i);
    __nv_bfloat162* lp = (__nv_bfloat162*)(lo + i);
    hp[0] = __nv_bfloat162(h0, h1); hp[1] = __nv_bfloat162(h2, h3);
    lp[0] = __nv_bfloat162(__float2bfloat16(v.x - __bfloat162float(h0)),
                           __float2bfloat16(v.y - __bfloat162float(h1)));
    lp[1] = __nv_bfloat162(__float2bfloat16(v.z - __bfloat162float(h2)),
                           __float2bfloat16(v.w - __bfloat162float(h3)));
}

// ================= transpose + split to bf16 or fp16 =================
__global__ __launch_bounds__(256) void tsplit_bf16(const float* __restrict__ W,
                                                   __nv_bfloat16* __restrict__ Thi,
                                                   __nv_bfloat16* __restrict__ Tlo) {
    __shared__ float tile[32][33];
    const int tx = threadIdx.x & 31, ty = threadIdx.x >> 5;
    const int k0 = blockIdx.y * 32, n0 = blockIdx.x * 32;
#pragma unroll
    for (int j = 0; j < 4; j++)
        tile[ty + j * 8][tx] = W[(size_t)(k0 + ty + j * 8) * DIM + n0 + tx];
    __syncthreads();
#pragma unroll
    for (int j = 0; j < 4; j++) {
        const int n = n0 + ty + j * 8, k = k0 + tx;
        float v = tile[tx][ty + j * 8];
        __nv_bfloat16 h = __float2bfloat16(v);
        Thi[(size_t)n * DIM + k] = h;
        Tlo[(size_t)n * DIM + k] = __float2bfloat16(v - __bfloat162float(h));
    }
}
__global__ __launch_bounds__(256) void tsplit_f16(const float* __restrict__ W,
                                                  __half* __restrict__ Thi,
                                                  __half* __restrict__ Tlo) {
    __shared__ float tile[32][33];
    const int tx = threadIdx.x & 31, ty = threadIdx.x >> 5;
    const int k0 = blockIdx.y * 32, n0 = blockIdx.x * 32;
#pragma unroll
    for (int j = 0; j < 4; j++)
        tile[ty + j * 8][tx] = W[(size_t)(k0 + ty + j * 8) * DIM + n0 + tx];
    __syncthreads();
#pragma unroll
    for (int j = 0; j < 4; j++) {
        const int n = n0 + ty + j * 8, k = k0 + tx;
        float v = tile[tx][ty + j * 8];
        __half h = __float2half_rn(v);
        Thi[(size_t)n * DIM + k] = h;
        Tlo[(size_t)n * DIM + k] = __float2half_rn(v - __half2float(h));
    }
}

// ================= gemm3: A bf16 hi/lo x W bf16 hi/lo, 3 terms =================
// OUT=0: fp32 C.  OUT=1: fp16 C16 = acc*scale.
#define GK 1024
#define GN 1024
#define ROWB 80
#define BUFB (128 * ROWB)
#define STAGE3 (4 * BUFB)
#define SMEM_G3 (2 * STAGE3)   /* 81920 */

template<int OUT>
__global__ __launch_bounds__(256, 2)
void gemm3(const __nv_bfloat16* __restrict__ Ahi, const __nv_bfloat16* __restrict__ Alo,
           const __nv_bfloat16* __restrict__ Bhi, const __nv_bfloat16* __restrict__ Blo,
           float* __restrict__ C, __half* __restrict__ C16, float scale) {
    extern __shared__ char sm[];
    const uint32_t sb = smem_u32(sm);
    const int tid = threadIdx.x;
    const int lane = tid & 31;
    const int wid = tid >> 5;
    const int m0 = blockIdx.y * 128, n0 = blockIdx.x * 128;
    const int wm = (wid & 1) * 64;
    const int wn = (wid >> 1) * 32;

    const int r0g = tid >> 2, s0g = tid & 3;
    const int r1g = (tid + 256) >> 2, s1g = tid & 3;

    const uint32_t a_off = (uint32_t)((wm + (lane & 15)) * ROWB + ((lane >> 4) << 3) * 2);
    const uint32_t b_off = (uint32_t)((wn + ((lane >> 4) << 3) + (lane & 7)) * ROWB + (lane & 8) * 2);

    float acc[4][4][4];
#pragma unroll
    for (int i = 0; i < 4; i++)
#pragma unroll
        for (int j = 0; j < 4; j++)
#pragma unroll
            for (int e = 0; e < 4; e++) acc[i][j][e] = 0.f;

    const int NC = GK / 32;
    {
        uint32_t st = sb;
        cp16(st + 0*BUFB + r0g*ROWB + s0g*16, Ahi + (size_t)(m0 + r0g)*GK + s0g*8);
        cp16(st + 0*BUFB + r1g*ROWB + s1g*16, Ahi + (size_t)(m0 + r1g)*GK + s1g*8);
        cp16(st + 1*BUFB + r0g*ROWB + s0g*16, Alo + (size_t)(m0 + r0g)*GK + s0g*8);
        cp16(st + 1*BUFB + r1g*ROWB + s1g*16, Alo + (size_t)(m0 + r1g)*GK + s1g*8);
        cp16(st + 2*BUFB + r0g*ROWB + s0g*16, Bhi + (size_t)(n0 + r0g)*GK + s0g*8);
        cp16(st + 2*BUFB + r1g*ROWB + s1g*16, Bhi + (size_t)(n0 + r1g)*GK + s1g*8);
        cp16(st + 3*BUFB + r0g*ROWB + s0g*16, Blo + (size_t)(n0 + r0g)*GK + s0g*8);
        cp16(st + 3*BUFB + r1g*ROWB + s1g*16, Blo + (size_t)(n0 + r1g)*GK + s1g*8);
        asm volatile("cp.async.commit_group;" ::: "memory");
    }

    for (int c = 0; c < NC; c++) {
        if (c + 1 < NC) {
            const int kc = (c + 1) * 32;
            uint32_t st = sb + ((c + 1) & 1) * STAGE3;
            cp16(st + 0*BUFB + r0g*ROWB + s0g*16, Ahi + (size_t)(m0 + r0g)*GK + kc + s0g*8);
            cp16(st + 0*BUFB + r1g*ROWB + s1g*16, Ahi + (size_t)(m0 + r1g)*GK + kc + s1g*8);
            cp16(st + 1*BUFB + r0g*ROWB + s0g*16, Alo + (size_t)(m0 + r0g)*GK + kc + s0g*8);
            cp16(st + 1*BUFB + r1g*ROWB + s1g*16, Alo + (size_t)(m0 + r1g)*GK + kc + s1g*8);
            cp16(st + 2*BUFB + r0g*ROWB + s0g*16, Bhi + (size_t)(n0 + r0g)*GK + kc + s0g*8);
            cp16(st + 2*BUFB + r1g*ROWB + s1g*16, Bhi + (size_t)(n0 + r1g)*GK + kc + s1g*8);
            cp16(st + 3*BUFB + r0g*ROWB + s0g*16, Blo + (size_t)(n0 + r0g)*GK + kc + s0g*8);
            cp16(st + 3*BUFB + r1g*ROWB + s1g*16, Blo + (size_t)(n0 + r1g)*GK + kc + s1g*8);
            asm volatile("cp.async.commit_group;" ::: "memory");
            asm volatile("cp.async.wait_group 1;" ::: "memory");
        } else {
            asm volatile("cp.async.wait_group 0;" ::: "memory");
        }
        __syncthreads();

        const uint32_t st = sb + (c & 1) * STAGE3;
#pragma unroll
        for (int kk = 0; kk < 2; kk++) {
            const uint32_t kb = kk * 32;
            uint32_t ahi[4][4], alo[4][4];
#pragma unroll
            for (int mt = 0; mt < 4; mt++) {
                ldm_x4(ahi[mt], st + 0*BUFB + a_off + mt * (16 * ROWB) + kb);
                ldm_x4(alo[mt], st + 1*BUFB + a_off + mt * (16 * ROWB) + kb);
            }
            uint32_t bhi[4][2], blo[4][2];
#pragma unroll
            for (int np = 0; np < 2; np++) {
                uint32_t r[4];
                ldm_x4(r, st + 2*BUFB + b_off + np * (16 * ROWB) + kb);
                bhi[2*np][0] = r[0]; bhi[2*np][1] = r[1];
                bhi[2*np+1][0] = r[2]; bhi[2*np+1][1] = r[3];
                ldm_x4(r, st + 3*BUFB + b_off + np * (16 * ROWB) + kb);
                blo[2*np][0] = r[0]; blo[2*np][1] = r[1];
                blo[2*np+1][0] = r[2]; blo[2*np+1][1] = r[3];
            }
#pragma unroll
            for (int mt = 0; mt < 4; mt++)
#pragma unroll
                for (int nt = 0; nt < 4; nt++) {
                    mma16816(acc[mt][nt], ahi[mt], bhi[nt]);
                    mma16816(acc[mt][nt], ahi[mt], blo[nt]);
                    mma16816(acc[mt][nt], alo[mt], bhi[nt]);
                }
        }
        __syncthreads();
    }

    const int g = lane >> 2, cpr = (lane & 3) * 2;
#pragma unroll
    for (int mt = 0; mt < 4; mt++)
#pragma unroll
        for (int nt = 0; nt < 4; nt++) {
            const int row = m0 + wm + mt * 16 + g;
            const int col = n0 + wn + nt * 8 + cpr;
            if (OUT == 1) {
                *(__half2*)(C16 + (size_t)row * GN + col) =
                    __floats2half2_rn(acc[mt][nt][0] * scale, acc[mt][nt][1] * scale);
                *(__half2*)(C16 + (size_t)(row + 8) * GN + col) =
                    __floats2half2_rn(acc[mt][nt][2] * scale, acc[mt][nt][3] * scale);
            } else {
                float2 p0; p0.x = acc[mt][nt][0]; p0.y = acc[mt][nt][1];
                float2 p1; p1.x = acc[mt][nt][2]; p1.y = acc[mt][nt][3];
                *(float2*)(C + (size_t)row * GN + col)       = p0;
                *(float2*)(C + (size_t)(row + 8) * GN + col) = p1;
            }
        }
}

// ================= gemm2: A fp16 x W fp16 hi/lo, 2 terms -> fp32 =================
#define STAGE2 (3 * BUFB)      /* 30720 */
#define SMEM_G2 (2 * STAGE2)   /* 61440 */

__global__ __launch_bounds__(256, 2)
void gemm2(const __half* __restrict__ A,
           const __half* __restrict__ Bhi, const __half* __restrict__ Blo,
           float* __restrict__ C) {
    extern __shared__ char sm[];
    const uint32_t sb = smem_u32(sm);
    const int tid = threadIdx.x;
    const int lane = tid & 31;
    const int wid = tid >> 5;
    const int m0 = blockIdx.y * 128, n0 = blockIdx.x * 128;
    const int wm = (wid & 1) * 64;
    const int wn = (wid >> 1) * 32;

    const int r0g = tid >> 2, s0g = tid & 3;
    const int r1g = (tid + 256) >> 2, s1g = tid & 3;

    const uint32_t a_off = (uint32_t)((wm + (lane & 15)) * ROWB + ((lane >> 4) << 3) * 2);
    const uint32_t b_off = (uint32_t)((wn + ((lane >> 4) << 3) + (lane & 7)) * ROWB + (lane & 8) * 2);

    float acc[4][4][4];
#pragma unroll
    for (int i = 0; i < 4; i++)
#pragma unroll
        for (int j = 0; j < 4; j++)
#pragma unroll
            for (int e = 0; e < 4; e++) acc[i][j][e] = 0.f;

    const int NC = GK / 32;
    {
        uint32_t st = sb;
        cp16(st + 0*BUFB + r0g*ROWB + s0g*16, A   + (size_t)(m0 + r0g)*GK + s0g*8);
        cp16(st + 0*BUFB + r1g*ROWB + s1g*16, A   + (size_t)(m0 + r1g)*GK + s1g*8);
        cp16(st + 1*BUFB + r0g*ROWB + s0g*16, Bhi + (size_t)(n0 + r0g)*GK + s0g*8);
        cp16(st + 1*BUFB + r1g*ROWB + s1g*16, Bhi + (size_t)(n0 + r1g)*GK + s1g*8);
        cp16(st + 2*BUFB + r0g*ROWB + s0g*16, Blo + (size_t)(n0 + r0g)*GK + s0g*8);
        cp16(st + 2*BUFB + r1g*ROWB + s1g*16, Blo + (size_t)(n0 + r1g)*GK + s1g*8);
        asm volatile("cp.async.commit_group;" ::: "memory");
    }

    for (int c = 0; c < NC; c++) {
        if (c + 1 < NC) {
            const int kc = (c + 1) * 32;
            uint32_t st = sb + ((c + 1) & 1) * STAGE2;
            cp16(st + 0*BUFB + r0g*ROWB + s0g*16, A   + (size_t)(m0 + r0g)*GK + kc + s0g*8);
            cp16(st + 0*BUFB + r1g*ROWB + s1g*16, A   + (size_t)(m0 + r1g)*GK + kc + s1g*8);
            cp16(st + 1*BUFB + r0g*ROWB + s0g*16, Bhi + (size_t)(n0 + r0g)*GK + kc + s0g*8);
            cp16(st + 1*BUFB + r1g*ROWB + s1g*16, Bhi + (size_t)(n0 + r1g)*GK + kc + s1g*8);
            cp16(st + 2*BUFB + r0g*ROWB + s0g*16, Blo + (size_t)(n0 + r0g)*GK + kc + s0g*8);
            cp16(st + 2*BUFB + r1g*ROWB + s1g*16, Blo + (size_t)(n0 + r1g)*GK + kc + s1g*8);
            asm volatile("cp.async.commit_group;" ::: "memory");
            asm volatile("cp.async.wait_group 1;" ::: "memory");
        } else {
            asm volatile("cp.async.wait_group 0;" ::: "memory");
        }
        __syncthreads();

        const uint32_t st = sb + (c & 1) * STAGE2;
#pragma unroll
        for (int kk = 0; kk < 2; kk++) {
            const uint32_t kb = kk * 32;
            uint32_t a[4][4];
#pragma unroll
            for (int mt = 0; mt < 4; mt++)
                ldm_x4(a[mt], st + 0*BUFB + a_off + mt * (16 * ROWB) + kb);
            uint32_t bhi[4][2], blo[4][2];
#pragma unroll
            for (int np = 0; np < 2; np++) {
                uint32_t r[4];
                ldm_x4(r, st + 1*BUFB + b_off + np * (16 * ROWB) + kb);
                bhi[2*np][0] = r[0]; bhi[2*np][1] = r[1];
                bhi[2*np+1][0] = r[2]; bhi[2*np+1][1] = r[3];
                ldm_x4(r, st + 2*BUFB + b_off + np * (16 * ROWB) + kb);
                blo[2*np][0] = r[0]; blo[2*np][1] = r[1];
                blo[2*np+1][0] = r[2]; blo[2*np+1][1] = r[3];
            }
#pragma unroll
            for (int mt = 0; mt < 4; mt++)
#pragma unroll
                for (int nt = 0; nt < 4; nt++) {
                    mma16816_f16(acc[mt][nt], a[mt], bhi[nt]);
                    mma16816_f16(acc[mt][nt], a[mt], blo[nt]);
                }
        }
        __syncthreads();
    }

    const int g = lane >> 2, cpr = (lane & 3) * 2;
#pragma unroll
    for (int mt = 0; mt < 4; mt++)
#pragma unroll
        for (int nt = 0; nt < 4; nt++) {
            const int row = m0 + wm + mt * 16 + g;
            const int col = n0 + wn + nt * 8 + cpr;
            float2 p0; p0.x = acc[mt][nt][0]; p0.y = acc[mt][nt][1];
            float2 p1; p1.x = acc[mt][nt][2]; p1.y = acc[mt][nt][3];
            *(float2*)(C + (size_t)row * GN + col)       = p0;
            *(float2*)(C + (size_t)(row + 8) * GN + col) = p1;
        }
}

// ================= scores+exp: single fp16 MMA term =================
#define SC_ROWB 144
#define SC_BUF  (128 * SC_ROWB)   /* 18432 */
#define SC_TOTAL (2 * SC_BUF)     /* 36864 */

__global__ __launch_bounds__(256, 2)
void scores_exp_f16(const __half* __restrict__ K16, const __half* __restrict__ Q16,
                    __half* __restrict__ Eh, float* __restrict__ Spart) {
    extern __shared__ char sm[];
    __shared__ float part[4][128];
    const uint32_t sb = smem_u32(sm);
    const int tid = threadIdx.x;
    const int lane = tid & 31;
    const int wid = tid >> 5;
    const int bh = blockIdx.z;
    const int b = bh >> 4, h = bh & 15;
    const int kt = blockIdx.y * 128;
    const int qt = blockIdx.x * 128;

    const __half* Ap = K16 + ((size_t)(b * SEQ + kt)) * LDIM + h * DH;
    const __half* Bp = Q16 + ((size_t)(b * SEQ + qt)) * LDIM + h * DH;

#pragma unroll
    for (int i = 0; i < 4; i++) {
        const int cid = tid + i * 256;
        const int row = cid >> 3, seg = cid & 7;
        const uint32_t d = row * SC_ROWB + seg * 16;
        const size_t goff = (size_t)row * LDIM + seg * 8;
        cp16(sb + 0*SC_BUF + d, Ap + goff);
        cp16(sb + 1*SC_BUF + d, Bp + goff);
    }
    asm volatile("cp.async.commit_group;" ::: "memory");
    asm volatile("cp.async.wait_group 0;" ::: "memory");
    __syncthreads();

    const int wm = (wid & 1) * 64;
    const int wn = (wid >> 1) * 32;
    const int wc = wid >> 1;
    const uint32_t a_off = (uint32_t)((wm + (lane & 15)) * SC_ROWB + ((lane >> 4) << 3) * 2);
    const uint32_t b_off = (uint32_t)((wn + ((lane >> 4) << 3) + (lane & 7)) * SC_ROWB + (lane & 8) * 2);

    float acc[4][4][4];
#pragma unroll
    for (int i = 0; i < 4; i++)
#pragma unroll
        for (int j = 0; j < 4; j++)
#pragma unroll
            for (int e = 0; e < 4; e++) acc[i][j][e] = 0.f;

#pragma unroll
    for (int kk = 0; kk < 4; kk++) {
        const uint32_t kb = kk * 32;
        uint32_t a[4][4];
#pragma unroll
        for (int mt = 0; mt < 4; mt++)
            ldm_x4(a[mt], sb + 0*SC_BUF + a_off + mt * (16 * SC_ROWB) + kb);
        uint32_t bb[4][2];
#pragma unroll
        for (int np = 0; np < 2; np++) {
            uint32_t r[4];
            ldm_x4(r, sb + 1*SC_BUF + b_off + np * (16 * SC_ROWB) + kb);
            bb[2*np][0] = r[0]; bb[2*np][1] = r[1];
            bb[2*np+1][0] = r[2]; bb[2*np+1][1] = r[3];
        }
#pragma unroll
        for (int mt = 0; mt < 4; mt++)
#pragma unroll
            for (int nt = 0; nt < 4; nt++)
                mma16816_f16(acc[mt][nt], a[mt], bb[nt]);
    }

    const int g = lane >> 2, cpr = (lane & 3) * 2;
    __half* EH = Eh + (size_t)bh * SEQ * SEQ;
    float rowsum[8];
#pragma unroll
    for (int i = 0; i < 8; i++) rowsum[i] = 0.f;

#pragma unroll
    for (int mt = 0; mt < 4; mt++)
#pragma unroll
        for (int nt = 0; nt < 4; nt++) {
            const int row = kt + wm + mt * 16 + g;
            const int col = qt + wn + nt * 8 + cpr;
            float e0 = __expf(acc[mt][nt][0]);
            float e1 = __expf(acc[mt][nt][1]);
            float e2 = __expf(acc[mt][nt][2]);
            float e3 = __expf(acc[mt][nt][3]);
            *(__half2*)(EH + (size_t)row * SEQ + col)       = __floats2half2_rn(e0, e1);
            *(__half2*)(EH + (size_t)(row + 8) * SEQ + col) = __floats2half2_rn(e2, e3);
            rowsum[mt * 2 + 0] += e0 + e1;
            rowsum[mt * 2 + 1] += e2 + e3;
        }
#pragma unroll
    for (int i = 0; i < 8; i++) {
        rowsum[i] += __shfl_xor_sync(0xffffffffu, rowsum[i], 1);
        rowsum[i] += __shfl_xor_sync(0xffffffffu, rowsum[i], 2);
    }
    if ((lane & 3) == 0) {
#pragma unroll
        for (int mt = 0; mt < 4; mt++) {
            part[wc][wm + mt * 16 + g]     = rowsum[mt * 2 + 0];
            part[wc][wm + mt * 16 + g + 8] = rowsum[mt * 2 + 1];
        }
    }
    __syncthreads();
    if (tid < 128) {
        const float s = part[0][tid] + part[1][tid] + part[2][tid] + part[3][tid];
        Spart[((size_t)bh * (SEQ/128) + blockIdx.x) * SEQ + kt + tid] = s;
    }
}

// ================= reduce partials -> 1/S =================
__global__ __launch_bounds__(256) void reduce_S(const float* __restrict__ Spart,
                                                float* __restrict__ Sinv) {
    const int idx = blockIdx.x * 256 + threadIdx.x;
    const int bh = idx >> 11, k = idx & (SEQ - 1);
    float s = 0.f;
#pragma unroll
    for (int qt = 0; qt < SEQ/128; qt++)
        s += Spart[((size_t)bh * (SEQ/128) + qt) * SEQ + k];
    Sinv[idx] = 1.f / s;
}

// ================= V * (4096/S) -> fp16 hi/lo [bh][k][DH] =================
__global__ __launch_bounds__(256) void vscale(const float* __restrict__ V,
                                              const float* __restrict__ Sinv,
                                              __half* __restrict__ VShi,
                                              __half* __restrict__ VSlo) {
    const int bh = blockIdx.y;
    const int b = bh >> 4, h = bh & 15;
    const int row = blockIdx.x * 4 + (threadIdx.x >> 6);
    const int d = threadIdx.x & 63;
    const float inv = Sinv[bh * SEQ + row] * 4096.f;
    const float v = V[((size_t)b * SEQ + row) * LDIM + h * DH + d] * inv;
    const __half hv = __float2half_rn(v);
    VShi[((size_t)bh * SEQ + row) * DH + d] = hv;
    VSlo[((size_t)bh * SEQ + row) * DH + d] = __float2half_rn(v - __half2float(hv));
}

// ================= att_out: E fp16 x Vs fp16 hi/lo -> Z16 fp16 =================
#define AO_AROW 272
#define AO_ABUF (32 * AO_AROW)
#define AO_VROW 144
#define AO_VBUF (32 * AO_VROW)
#define AO_EH  0
#define AO_VHI AO_ABUF
#define AO_VLO (AO_ABUF + AO_VBUF)
#define AO_STAGE (AO_ABUF + 2 * AO_VBUF)   /* 17920 */
#define AO_TOTAL (2 * AO_STAGE)            /* 35840 */

__global__ __launch_bounds__(256, 2)
void att_out_hmma(const __half* __restrict__ Eh,
                  const __half* __restrict__ VShi, const __half* __restrict__ VSlo,
                  __half* __restrict__ Z16) {
    extern __shared__ char sm[];
    const uint32_t sb = smem_u32(sm);
    const int tid = threadIdx.x;
    const int lane = tid & 31;
    const int wid = tid >> 5;
    const int qt = blockIdx.x * 128;
    const int bh = blockIdx.y;
    const int b = bh >> 4, h = bh & 15;

    const __half* Pb = Eh + (size_t)bh * SEQ * SEQ + qt;
    const __half* Vbh = VShi + (size_t)bh * SEQ * DH;
    const __half* Vbl = VSlo + (size_t)bh * SEQ * DH;

    const int pr0 = tid >> 4, ps0 = tid & 15;
    const int pr1 = (tid + 256) >> 4, ps1 = tid & 15;
    const int vr = tid >> 3, vs = tid & 7;

    const int wm = (wid & 3) * 32;
    const int wn = (wid >> 2) * 32;

    const uint32_t a_tr = (uint32_t)(((lane & 7) + ((lane >> 4) << 3)) * AO_AROW + (wm + (lane & 8)) * 2);
    const uint32_t b_tr = (uint32_t)(((lane & 7) + (lane & 8)) * AO_VROW + (wn + ((lane >> 4) << 3)) * 2);

    float acc[2][4][4];
#pragma unroll
    for (int i = 0; i < 2; i++)
#pragma unroll
        for (int j = 0; j < 4; j++)
#pragma unroll
            for (int e = 0; e < 4; e++) acc[i][j][e] = 0.f;

    const int NC = SEQ / 32;   // 64

    {
        const int k0 = 0;
        const uint32_t st = sb;
        cp16(st + AO_EH + pr0*AO_AROW + ps0*16, Pb + (size_t)(k0 + pr0) * SEQ + ps0*8);
        cp16(st + AO_EH + pr1*AO_AROW + ps1*16, Pb + (size_t)(k0 + pr1) * SEQ + ps1*8);
        cp16(st + AO_VHI + vr*AO_VROW + vs*16,  Vbh + (size_t)(k0 + vr) * DH + vs*8);
        cp16(st + AO_VLO + vr*AO_VROW + vs*16,  Vbl + (size_t)(k0 + vr) * DH + vs*8);
        asm volatile("cp.async.commit_group;" ::: "memory");
    }

    for (int c = 0; c < NC; c++) {
        if (c + 1 < NC) {
            const int k0 = (c + 1) * 32;
            const uint32_t st = sb + ((c + 1) & 1) * AO_STAGE;
            cp16(st + AO_EH + pr0*AO_AROW + ps0*16, Pb + (size_t)(k0 + pr0) * SEQ + ps0*8);
            cp16(st + AO_EH + pr1*AO_AROW + ps1*16, Pb + (size_t)(k0 + pr1) * SEQ + ps1*8);
            cp16(st + AO_VHI + vr*AO_VROW + vs*16,  Vbh + (size_t)(k0 + vr) * DH + vs*8);
            cp16(st + AO_VLO + vr*AO_VROW + vs*16,  Vbl + (size_t)(k0 + vr) * DH + vs*8);
            asm volatile("cp.async.commit_group;" ::: "memory");
            asm volatile("cp.async.wait_group 1;" ::: "memory");
        } else {
            asm volatile("cp.async.wait_group 0;" ::: "memory");
        }
        __syncthreads();

        const uint32_t st = sb + (c & 1) * AO_STAGE;
#pragma unroll
        for (int kk = 0; kk < 2; kk++) {
            uint32_t ah[2][4];
#pragma unroll
            for (int mt = 0; mt < 2; mt++)
                ldm_x4t(ah[mt], st + AO_EH + a_tr + kk * (16 * AO_AROW) + mt * 32);
            uint32_t bh_[4][2], bl_[4][2];
#pragma unroll
            for (int np = 0; np < 2; np++) {
                uint32_t r[4];
                ldm_x4t(r, st + AO_VHI + b_tr + kk * (16 * AO_VROW) + np * 32);
                bh_[2*np][0] = r[0]; bh_[2*np][1] = r[1];
                bh_[2*np+1][0] = r[2]; bh_[2*np+1][1] = r[3];
                ldm_x4t(r, st + AO_VLO + b_tr + kk * (16 * AO_VROW) + np * 32);
                bl_[2*np][0] = r[0]; bl_[2*np][1] = r[1];
                bl_[2*np+1][0] = r[2]; bl_[2*np+1][1] = r[3];
            }
#pragma unroll
            for (int mt = 0; mt < 2; mt++)
#pragma unroll
                for (int nt = 0; nt < 4; nt++) {
                    mma16816_f16(acc[mt][nt], ah[mt], bh_[nt]);
                    mma16816_f16(acc[mt][nt], ah[mt], bl_[nt]);
                }
        }
        __syncthreads();
    }

    const float dsc = 1.f / 4096.f;
    const int g = lane >> 2, cpr = (lane & 3) * 2;
#pragma unroll
    for (int mt = 0; mt < 2; mt++)
#pragma unroll
        for (int nt = 0; nt < 4; nt++) {
            const int q = qt + wm + mt * 16 + g;
            const int col = wn + nt * 8 + cpr;
            const size_t o0 = ((size_t)b * SEQ + q)     * LDIM + h * DH + col;
            const size_t o1 = ((size_t)b * SEQ + q + 8) * LDIM + h * DH + col;
            *(__half2*)(Z16 + o0) = __floats2half2_rn(acc[mt][nt][0] * dsc, acc[mt][nt][1] * dsc);
            *(__half2*)(Z16 + o1) = __floats2half2_rn(acc[mt][nt][2] * dsc, acc[mt][nt][3] * dsc);
        }
}

// ================= row L2 normalize -> fp16 =================
__global__ __launch_bounds__(256) void l2norm_f16(const float* __restrict__ in,
                                                  __half* __restrict__ out) {
    const size_t rowi = blockIdx.x;
    const float* p = in + rowi * DIM;
    const int t = threadIdx.x;
    float v[4];
    float ss = 0.f;
#pragma unroll
    for (int i = 0; i < 4; i++) { v[i] = p[t + 256 * i]; ss += v[i] * v[i]; }
    __shared__ float red[256];
    red[t] = ss; __syncthreads();
    for (int s = 128; s > 0; s >>= 1) {
        if (t < s) red[t] = red[t] + red[t + s];
        __syncthreads();
    }
    const float n = sqrtf(red[0]);
    const float sc = 1.f / fmaxf(n, 1e-12f);
#pragma unroll
    for (int i = 0; i < 4; i++)
        out[rowi * DIM + t + 256 * i] = __float2half_rn(v[i] * sc);
}

// ================= row L2 normalize + exact GELU =================
__global__ __launch_bounds__(256) void l2norm_gelu(const float* __restrict__ in,
                                                   float* __restrict__ out) {
    const size_t rowi = blockIdx.x;
    const float* p = in + rowi * DIM;
    float* o = out + rowi * DIM;
    const int t = threadIdx.x;
    float v[4];
    float ss = 0.f;
#pragma unroll
    for (int i = 0; i < 4; i++) { v[i] = p[t + 256 * i]; ss += v[i] * v[i]; }
    __shared__ float red[256];
    red[t] = ss; __syncthreads();
    for (int s = 128; s > 0; s >>= 1) {
        if (t < s) red[t] = red[t] + red[t + s];
        __syncthreads();
    }
    const float n = sqrtf(red[0]);
    const float sc = 1.f / fmaxf(n, 1e-12f);
#pragma unroll
    for (int i = 0; i < 4; i++) {
        float y = v[i] * sc;
        o[t + 256 * i] = 0.5f * y * (1.f + erff(y * 0.70710678118654752f));
    }
}

// ================= host launcher =================
extern "C" void kernel_launch(void* const* d_in, const int* in_sizes, int n_in,
                              void* d_out, int out_size) {
    const float* x   = (const float*)d_in[0];
    const float* Wq  = (const float*)d_in[1];
    const float* Wk  = (const float*)d_in[2];
    const float* Wv  = (const float*)d_in[3];
    const float* Wo  = (const float*)d_in[4];
    const float* Wff = (const float*)d_in[5];
    float* outp = (float*)d_out;

    float *pV, *pZ2, *pSpart, *pSinv;
    __nv_bfloat16 *pAhi, *pAlo, *pWqh, *pWql, *pWkh, *pWkl, *pWvh, *pWvl;
    __half *pWoh, *pWol, *pWfh, *pWfl, *pQ16, *pK16, *pEh, *pVShi, *pVSlo, *pZ16, *pN16;
    cudaGetSymbolAddress((void**)&pV,   g_V);
    cudaGetSymbolAddress((void**)&pZ2,  g_Z2);
    cudaGetSymbolAddress((void**)&pAhi, g_Ahi);
    cudaGetSymbolAddress((void**)&pAlo, g_Alo);
    cudaGetSymbolAddress((void**)&pWqh, g_Wqh);
    cudaGetSymbolAddress((void**)&pWql, g_Wql);
    cudaGetSymbolAddress((void**)&pWkh, g_Wkh);
    cudaGetSymbolAddress((void**)&pWkl, g_Wkl);
    cudaGetSymbolAddress((void**)&pWvh, g_Wvh);
    cudaGetSymbolAddress((void**)&pWvl, g_Wvl);
    cudaGetSymbolAddress((void**)&pWoh, g_Woh);
    cudaGetSymbolAddress((void**)&pWol, g_Wol);
    cudaGetSymbolAddress((void**)&pWfh, g_Wfh);
    cudaGetSymbolAddress((void**)&pWfl, g_Wfl);
    cudaGetSymbolAddress((void**)&pQ16, g_Q16);
    cudaGetSymbolAddress((void**)&pK16, g_K16);
    cudaGetSymbolAddress((void**)&pEh,  g_Eh);
    cudaGetSymbolAddress((void**)&pSpart, g_Spart);
    cudaGetSymbolAddress((void**)&pSinv,  g_Sinv);
    cudaGetSymbolAddress((void**)&pVShi, g_VShi);
    cudaGetSymbolAddress((void**)&pVSlo, g_VSlo);
    cudaGetSymbolAddress((void**)&pZ16, g_Z16);
    cudaGetSymbolAddress((void**)&pN16, g_N16);

    cudaFuncSetAttribute(gemm3<0>,       cudaFuncAttributeMaxDynamicSharedMemorySize, SMEM_G3);
    cudaFuncSetAttribute(gemm3<1>,       cudaFuncAttributeMaxDynamicSharedMemorySize, SMEM_G3);
    cudaFuncSetAttribute(gemm2,          cudaFuncAttributeMaxDynamicSharedMemorySize, SMEM_G2);
    cudaFuncSetAttribute(scores_exp_f16, cudaFuncAttributeMaxDynamicSharedMemorySize, SC_TOTAL);
    cudaFuncSetAttribute(att_out_hmma,   cudaFuncAttributeMaxDynamicSharedMemorySize, AO_TOTAL);

    const dim3 gG(GN / 128, MTOT / 128);    // (8, 32)
    const dim3 gT(DIM / 32, DIM / 32);      // (32, 32)
    const int  splitBlocksX = (MTOT * DIM) / (256 * 4);

    // launch order tuned so ncu (-s 5 -c 1) profiles gemm3 (launch #6)
    split_bf16<<<splitBlocksX, 256>>>(x, pAhi, pAlo);          // 1
    tsplit_bf16<<<gT, 256>>>(Wq, pWqh, pWql);                  // 2
    tsplit_bf16<<<gT, 256>>>(Wk, pWkh, pWkl);                  // 3
    tsplit_bf16<<<gT, 256>>>(Wv, pWvh, pWvl);                  // 4
    tsplit_f16<<<gT, 256>>>(Wo, pWoh, pWol);                   // 5
    gemm3<1><<<gG, 256, SMEM_G3>>>(pAhi, pAlo, pWqh, pWql, nullptr, pQ16, 0.03125f);  // 6: profiled
    tsplit_f16<<<gT, 256>>>(Wff, pWfh, pWfl);                  // 7
    gemm3<1><<<gG, 256, SMEM_G3>>>(pAhi, pAlo, pWkh, pWkl, nullptr, pK16, 1.0f);
    gemm3<0><<<gG, 256, SMEM_G3>>>(pAhi, pAlo, pWvh, pWvl, pV, nullptr, 1.0f);

    // attention: scores+exp (1-term fp16) -> rowsum -> V*4096/S -> PV (Z16 out)
    scores_exp_f16<<<dim3(SEQ / 128, SEQ / 128, BHTOT), 256, SC_TOTAL>>>(pK16, pQ16, pEh, pSpart);
    reduce_S<<<(BHTOT * SEQ) / 256, 256>>>(pSpart, pSinv);
    vscale<<<dim3(SEQ / 4, BHTOT), 256>>>(pV, pSinv, pVShi, pVSlo);
    att_out_hmma<<<dim3(SEQ / 128, BHTOT), 256, AO_TOTAL>>>(pEh, pVShi, pVSlo, pZ16);

    // out projection (2-term fp16) -> normalize(fp16) -> FFN (2-term) -> norm+gelu
    gemm2<<<gG, 256, SMEM_G2>>>(pZ16, pWoh, pWol, pZ2);
    l2norm_f16<<<MTOT, 256>>>(pZ2, pN16);
    gemm2<<<gG, 256, SMEM_G2>>>(pN16, pWfh, pWfl, pZ2);
    l2norm_gelu<<<MTOT, 256>>>(pZ2, outp);
}

// round 14
// speedup vs baseline: 4.1746x; 1.1289x over previous
#include <cuda_runtime.h>
#include <cuda_fp16.h>
#include <math.h>
#include <cstdint>

#define NBATCH 2
#define SEQ    2048
#define DIM    1024
#define LDIM   1024
#define NH     16
#define DH     64
#define MTOT   (NBATCH*SEQ)   /* 4096 */
#define BHTOT  (NBATCH*NH)    /* 32   */

__device__ __forceinline__ uint32_t smem_u32(const void* p) {
    uint32_t a;
    asm("{ .reg .u64 t; cvta.to.shared.u64 t, %1; cvt.u32.u64 %0, t; }" : "=r"(a) : "l"(p));
    return a;
}

// ================= scratch (static device globals; no allocation) =================
__device__ float g_Z2[ (size_t)MTOT * LDIM ];          // fp32 staging (Wo out, Wff out)
__device__ __half g_X16[ (size_t)MTOT * DIM ];         // x as fp16
// weight splits fp16 hi/lo, [N][K] transposed
__device__ __half g_Wqh[ (size_t)DIM * DIM ];
__device__ __half g_Wql[ (size_t)DIM * DIM ];
__device__ __half g_Wkh[ (size_t)DIM * DIM ];
__device__ __half g_Wkl[ (size_t)DIM * DIM ];
__device__ __half g_Wvh[ (size_t)DIM * DIM ];
__device__ __half g_Wvl[ (size_t)DIM * DIM ];
__device__ __half g_Woh[ (size_t)DIM * DIM ];
__device__ __half g_Wol[ (size_t)DIM * DIM ];
__device__ __half g_Wfh[ (size_t)DIM * DIM ];
__device__ __half g_Wfl[ (size_t)DIM * DIM ];
// Q (pre-scaled 1/32), K, V as single fp16
__device__ __half g_Q16[ (size_t)MTOT * LDIM ];
__device__ __half g_K16[ (size_t)MTOT * LDIM ];
__device__ __half g_V16[ (size_t)MTOT * LDIM ];
// unnormalized exp(scores) fp16 [bh][k][q]
__device__ __half g_Eh[ (size_t)BHTOT * SEQ * SEQ ];
// row-sum partials and inverses
__device__ float g_Spart[ (size_t)BHTOT * (SEQ/128) * SEQ ];
__device__ float g_Sinv [ (size_t)BHTOT * SEQ ];
// (V * 4096 / S) fp16 hi/lo [bh][k][DH]
__device__ __half g_VShi[ (size_t)BHTOT * SEQ * DH ];
__device__ __half g_VSlo[ (size_t)BHTOT * SEQ * DH ];
// attention output fp16, l2norm output fp16
__device__ __half g_Z16[ (size_t)MTOT * DIM ];
__device__ __half g_N16[ (size_t)MTOT * DIM ];

// ================= HMMA primitives =================
__device__ __forceinline__ void cp16(uint32_t dst, const void* src) {
    asm volatile("cp.async.cg.shared.global [%0], [%1], 16;" :: "r"(dst), "l"(src));
}
__device__ __forceinline__ void ldm_x4(uint32_t* r, uint32_t addr) {
    asm volatile("ldmatrix.sync.aligned.m8n8.x4.shared.b16 {%0,%1,%2,%3}, [%4];"
                 : "=r"(r[0]), "=r"(r[1]), "=r"(r[2]), "=r"(r[3]) : "r"(addr));
}
__device__ __forceinline__ void ldm_x4t(uint32_t* r, uint32_t addr) {
    asm volatile("ldmatrix.sync.aligned.m8n8.x4.trans.shared.b16 {%0,%1,%2,%3}, [%4];"
                 : "=r"(r[0]), "=r"(r[1]), "=r"(r[2]), "=r"(r[3]) : "r"(addr));
}
__device__ __forceinline__ void mma16816_f16(float* c, const uint32_t* a, const uint32_t* b) {
    asm volatile(
        "mma.sync.aligned.m16n8k16.row.col.f32.f16.f16.f32 "
        "{%0,%1,%2,%3}, {%4,%5,%6,%7}, {%8,%9}, {%0,%1,%2,%3};"
        : "+f"(c[0]), "+f"(c[1]), "+f"(c[2]), "+f"(c[3])
        : "r"(a[0]), "r"(a[1]), "r"(a[2]), "r"(a[3]), "r"(b[0]), "r"(b[1]));
}

// ================= x -> fp16 =================
__global__ __launch_bounds__(256) void to_f16(const float* __restrict__ X,
                                              __half* __restrict__ Y) {
    const size_t i = ((size_t)blockIdx.x * 256 + threadIdx.x) * 4;
    float4 v = *(const float4*)(X + i);
    __half2* yp = (__half2*)(Y + i);
    yp[0] = __floats2half2_rn(v.x, v.y);
    yp[1] = __floats2half2_rn(v.z, v.w);
}

// ================= transpose + split fp16 hi/lo: W[K][N] -> [N][K] =================
__global__ __launch_bounds__(256) void tsplit_f16(const float* __restrict__ W,
                                                  __half* __restrict__ Thi,
                                                  __half* __restrict__ Tlo) {
    __shared__ float tile[32][33];
    const int tx = threadIdx.x & 31, ty = threadIdx.x >> 5;
    const int k0 = blockIdx.y * 32, n0 = blockIdx.x * 32;
#pragma unroll
    for (int j = 0; j < 4; j++)
        tile[ty + j * 8][tx] = W[(size_t)(k0 + ty + j * 8) * DIM + n0 + tx];
    __syncthreads();
#pragma unroll
    for (int j = 0; j < 4; j++) {
        const int n = n0 + ty + j * 8, k = k0 + tx;
        float v = tile[tx][ty + j * 8];
        __half h = __float2half_rn(v);
        Thi[(size_t)n * DIM + k] = h;
        Tlo[(size_t)n * DIM + k] = __float2half_rn(v - __half2float(h));
    }
}

// ================= gemm2: A fp16 x W fp16 hi/lo, 2 terms =================
// OUT=0: fp32 C.  OUT=1: fp16 C16 = acc*scale.
#define GK 1024
#define GN 1024
#define ROWB 80
#define BUFB (128 * ROWB)
#define STAGE2 (3 * BUFB)      /* 30720 */
#define SMEM_G2 (2 * STAGE2)   /* 61440 */

template<int OUT>
__global__ __launch_bounds__(256, 2)
void gemm2(const __half* __restrict__ A,
           const __half* __restrict__ Bhi, const __half* __restrict__ Blo,
           float* __restrict__ C, __half* __restrict__ C16, float scale) {
    extern __shared__ char sm[];
    const uint32_t sb = smem_u32(sm);
    const int tid = threadIdx.x;
    const int lane = tid & 31;
    const int wid = tid >> 5;
    const int m0 = blockIdx.y * 128, n0 = blockIdx.x * 128;
    const int wm = (wid & 1) * 64;
    const int wn = (wid >> 1) * 32;

    const int r0g = tid >> 2, s0g = tid & 3;
    const int r1g = (tid + 256) >> 2, s1g = tid & 3;

    const uint32_t a_off = (uint32_t)((wm + (lane & 15)) * ROWB + ((lane >> 4) << 3) * 2);
    const uint32_t b_off = (uint32_t)((wn + ((lane >> 4) << 3) + (lane & 7)) * ROWB + (lane & 8) * 2);

    float acc[4][4][4];
#pragma unroll
    for (int i = 0; i < 4; i++)
#pragma unroll
        for (int j = 0; j < 4; j++)
#pragma unroll
            for (int e = 0; e < 4; e++) acc[i][j][e] = 0.f;

    const int NC = GK / 32;
    {
        uint32_t st = sb;
        cp16(st + 0*BUFB + r0g*ROWB + s0g*16, A   + (size_t)(m0 + r0g)*GK + s0g*8);
        cp16(st + 0*BUFB + r1g*ROWB + s1g*16, A   + (size_t)(m0 + r1g)*GK + s1g*8);
        cp16(st + 1*BUFB + r0g*ROWB + s0g*16, Bhi + (size_t)(n0 + r0g)*GK + s0g*8);
        cp16(st + 1*BUFB + r1g*ROWB + s1g*16, Bhi + (size_t)(n0 + r1g)*GK + s1g*8);
        cp16(st + 2*BUFB + r0g*ROWB + s0g*16, Blo + (size_t)(n0 + r0g)*GK + s0g*8);
        cp16(st + 2*BUFB + r1g*ROWB + s1g*16, Blo + (size_t)(n0 + r1g)*GK + s1g*8);
        asm volatile("cp.async.commit_group;" ::: "memory");
    }

    for (int c = 0; c < NC; c++) {
        if (c + 1 < NC) {
            const int kc = (c + 1) * 32;
            uint32_t st = sb + ((c + 1) & 1) * STAGE2;
            cp16(st + 0*BUFB + r0g*ROWB + s0g*16, A   + (size_t)(m0 + r0g)*GK + kc + s0g*8);
            cp16(st + 0*BUFB + r1g*ROWB + s1g*16, A   + (size_t)(m0 + r1g)*GK + kc + s1g*8);
            cp16(st + 1*BUFB + r0g*ROWB + s0g*16, Bhi + (size_t)(n0 + r0g)*GK + kc + s0g*8);
            cp16(st + 1*BUFB + r1g*ROWB + s1g*16, Bhi + (size_t)(n0 + r1g)*GK + kc + s1g*8);
            cp16(st + 2*BUFB + r0g*ROWB + s0g*16, Blo + (size_t)(n0 + r0g)*GK + kc + s0g*8);
            cp16(st + 2*BUFB + r1g*ROWB + s1g*16, Blo + (size_t)(n0 + r1g)*GK + kc + s1g*8);
            asm volatile("cp.async.commit_group;" ::: "memory");
            asm volatile("cp.async.wait_group 1;" ::: "memory");
        } else {
            asm volatile("cp.async.wait_group 0;" ::: "memory");
        }
        __syncthreads();

        const uint32_t st = sb + (c & 1) * STAGE2;
#pragma unroll
        for (int kk = 0; kk < 2; kk++) {
            const uint32_t kb = kk * 32;
            uint32_t a[4][4];
#pragma unroll
            for (int mt = 0; mt < 4; mt++)
                ldm_x4(a[mt], st + 0*BUFB + a_off + mt * (16 * ROWB) + kb);
            uint32_t bhi[4][2], blo[4][2];
#pragma unroll
            for (int np = 0; np < 2; np++) {
                uint32_t r[4];
                ldm_x4(r, st + 1*BUFB + b_off + np * (16 * ROWB) + kb);
                bhi[2*np][0] = r[0]; bhi[2*np][1] = r[1];
                bhi[2*np+1][0] = r[2]; bhi[2*np+1][1] = r[3];
                ldm_x4(r, st + 2*BUFB + b_off + np * (16 * ROWB) + kb);
                blo[2*np][0] = r[0]; blo[2*np][1] = r[1];
                blo[2*np+1][0] = r[2]; blo[2*np+1][1] = r[3];
            }
#pragma unroll
            for (int mt = 0; mt < 4; mt++)
#pragma unroll
                for (int nt = 0; nt < 4; nt++) {
                    mma16816_f16(acc[mt][nt], a[mt], bhi[nt]);
                    mma16816_f16(acc[mt][nt], a[mt], blo[nt]);
                }
        }
        __syncthreads();
    }

    const int g = lane >> 2, cpr = (lane & 3) * 2;
#pragma unroll
    for (int mt = 0; mt < 4; mt++)
#pragma unroll
        for (int nt = 0; nt < 4; nt++) {
            const int row = m0 + wm + mt * 16 + g;
            const int col = n0 + wn + nt * 8 + cpr;
            if (OUT == 1) {
                *(__half2*)(C16 + (size_t)row * GN + col) =
                    __floats2half2_rn(acc[mt][nt][0] * scale, acc[mt][nt][1] * scale);
                *(__half2*)(C16 + (size_t)(row + 8) * GN + col) =
                    __floats2half2_rn(acc[mt][nt][2] * scale, acc[mt][nt][3] * scale);
            } else {
                float2 p0; p0.x = acc[mt][nt][0]; p0.y = acc[mt][nt][1];
                float2 p1; p1.x = acc[mt][nt][2]; p1.y = acc[mt][nt][3];
                *(float2*)(C + (size_t)row * GN + col)       = p0;
                *(float2*)(C + (size_t)(row + 8) * GN + col) = p1;
            }
        }
}

// ================= scores+exp: single fp16 MMA term =================
#define SC_ROWB 144
#define SC_BUF  (128 * SC_ROWB)   /* 18432 */
#define SC_TOTAL (2 * SC_BUF)     /* 36864 */

__global__ __launch_bounds__(256, 2)
void scores_exp_f16(const __half* __restrict__ K16, const __half* __restrict__ Q16,
                    __half* __restrict__ Eh, float* __restrict__ Spart) {
    extern __shared__ char sm[];
    __shared__ float part[4][128];
    const uint32_t sb = smem_u32(sm);
    const int tid = threadIdx.x;
    const int lane = tid & 31;
    const int wid = tid >> 5;
    const int bh = blockIdx.z;
    const int b = bh >> 4, h = bh & 15;
    const int kt = blockIdx.y * 128;
    const int qt = blockIdx.x * 128;

    const __half* Ap = K16 + ((size_t)(b * SEQ + kt)) * LDIM + h * DH;
    const __half* Bp = Q16 + ((size_t)(b * SEQ + qt)) * LDIM + h * DH;

#pragma unroll
    for (int i = 0; i < 4; i++) {
        const int cid = tid + i * 256;
        const int row = cid >> 3, seg = cid & 7;
        const uint32_t d = row * SC_ROWB + seg * 16;
        const size_t goff = (size_t)row * LDIM + seg * 8;
        cp16(sb + 0*SC_BUF + d, Ap + goff);
        cp16(sb + 1*SC_BUF + d, Bp + goff);
    }
    asm volatile("cp.async.commit_group;" ::: "memory");
    asm volatile("cp.async.wait_group 0;" ::: "memory");
    __syncthreads();

    const int wm = (wid & 1) * 64;
    const int wn = (wid >> 1) * 32;
    const int wc = wid >> 1;
    const uint32_t a_off = (uint32_t)((wm + (lane & 15)) * SC_ROWB + ((lane >> 4) << 3) * 2);
    const uint32_t b_off = (uint32_t)((wn + ((lane >> 4) << 3) + (lane & 7)) * SC_ROWB + (lane & 8) * 2);

    float acc[4][4][4];
#pragma unroll
    for (int i = 0; i < 4; i++)
#pragma unroll
        for (int j = 0; j < 4; j++)
#pragma unroll
            for (int e = 0; e < 4; e++) acc[i][j][e] = 0.f;

#pragma unroll
    for (int kk = 0; kk < 4; kk++) {
        const uint32_t kb = kk * 32;
        uint32_t a[4][4];
#pragma unroll
        for (int mt = 0; mt < 4; mt++)
            ldm_x4(a[mt], sb + 0*SC_BUF + a_off + mt * (16 * SC_ROWB) + kb);
        uint32_t bb[4][2];
#pragma unroll
        for (int np = 0; np < 2; np++) {
            uint32_t r[4];
            ldm_x4(r, sb + 1*SC_BUF + b_off + np * (16 * SC_ROWB) + kb);
            bb[2*np][0] = r[0]; bb[2*np][1] = r[1];
            bb[2*np+1][0] = r[2]; bb[2*np+1][1] = r[3];
        }
#pragma unroll
        for (int mt = 0; mt < 4; mt++)
#pragma unroll
            for (int nt = 0; nt < 4; nt++)
                mma16816_f16(acc[mt][nt], a[mt], bb[nt]);
    }

    const int g = lane >> 2, cpr = (lane & 3) * 2;
    __half* EH = Eh + (size_t)bh * SEQ * SEQ;
    float rowsum[8];
#pragma unroll
    for (int i = 0; i < 8; i++) rowsum[i] = 0.f;

#pragma unroll
    for (int mt = 0; mt < 4; mt++)
#pragma unroll
        for (int nt = 0; nt < 4; nt++) {
            const int row = kt + wm + mt * 16 + g;
            const int col = qt + wn + nt * 8 + cpr;
            float e0 = __expf(acc[mt][nt][0]);
            float e1 = __expf(acc[mt][nt][1]);
            float e2 = __expf(acc[mt][nt][2]);
            float e3 = __expf(acc[mt][nt][3]);
            *(__half2*)(EH + (size_t)row * SEQ + col)       = __floats2half2_rn(e0, e1);
            *(__half2*)(EH + (size_t)(row + 8) * SEQ + col) = __floats2half2_rn(e2, e3);
            rowsum[mt * 2 + 0] += e0 + e1;
            rowsum[mt * 2 + 1] += e2 + e3;
        }
#pragma unroll
    for (int i = 0; i < 8; i++) {
        rowsum[i] += __shfl_xor_sync(0xffffffffu, rowsum[i], 1);
        rowsum[i] += __shfl_xor_sync(0xffffffffu, rowsum[i], 2);
    }
    if ((lane & 3) == 0) {
#pragma unroll
        for (int mt = 0; mt < 4; mt++) {
            part[wc][wm + mt * 16 + g]     = rowsum[mt * 2 + 0];
            part[wc][wm + mt * 16 + g + 8] = rowsum[mt * 2 + 1];
        }
    }
    __syncthreads();
    if (tid < 128) {
        const float s = part[0][tid] + part[1][tid] + part[2][tid] + part[3][tid];
        Spart[((size_t)bh * (SEQ/128) + blockIdx.x) * SEQ + kt + tid] = s;
    }
}

// ================= reduce partials -> 1/S =================
__global__ __launch_bounds__(256) void reduce_S(const float* __restrict__ Spart,
                                                float* __restrict__ Sinv) {
    const int idx = blockIdx.x * 256 + threadIdx.x;
    const int bh = idx >> 11, k = idx & (SEQ - 1);
    float s = 0.f;
#pragma unroll
    for (int qt = 0; qt < SEQ/128; qt++)
        s += Spart[((size_t)bh * (SEQ/128) + qt) * SEQ + k];
    Sinv[idx] = 1.f / s;
}

// ================= V16 * (4096/S) -> fp16 hi/lo [bh][k][DH] =================
__global__ __launch_bounds__(256) void vscale(const __half* __restrict__ V16,
                                              const float* __restrict__ Sinv,
                                              __half* __restrict__ VShi,
                                              __half* __restrict__ VSlo) {
    const int bh = blockIdx.y;
    const int b = bh >> 4, h = bh & 15;
    const int row = blockIdx.x * 4 + (threadIdx.x >> 6);
    const int d = threadIdx.x & 63;
    const float inv = Sinv[bh * SEQ + row] * 4096.f;
    const float v = __half2float(V16[((size_t)b * SEQ + row) * LDIM + h * DH + d]) * inv;
    const __half hv = __float2half_rn(v);
    VShi[((size_t)bh * SEQ + row) * DH + d] = hv;
    VSlo[((size_t)bh * SEQ + row) * DH + d] = __float2half_rn(v - __half2float(hv));
}

// ================= att_out: E fp16 x Vs fp16 hi/lo -> Z16 fp16 =================
#define AO_AROW 272
#define AO_ABUF (32 * AO_AROW)
#define AO_VROW 144
#define AO_VBUF (32 * AO_VROW)
#define AO_EH  0
#define AO_VHI AO_ABUF
#define AO_VLO (AO_ABUF + AO_VBUF)
#define AO_STAGE (AO_ABUF + 2 * AO_VBUF)   /* 17920 */
#define AO_TOTAL (2 * AO_STAGE)            /* 35840 */

__global__ __launch_bounds__(256, 2)
void att_out_hmma(const __half* __restrict__ Eh,
                  const __half* __restrict__ VShi, const __half* __restrict__ VSlo,
                  __half* __restrict__ Z16) {
    extern __shared__ char sm[];
    const uint32_t sb = smem_u32(sm);
    const int tid = threadIdx.x;
    const int lane = tid & 31;
    const int wid = tid >> 5;
    const int qt = blockIdx.x * 128;
    const int bh = blockIdx.y;
    const int b = bh >> 4, h = bh & 15;

    const __half* Pb = Eh + (size_t)bh * SEQ * SEQ + qt;
    const __half* Vbh = VShi + (size_t)bh * SEQ * DH;
    const __half* Vbl = VSlo + (size_t)bh * SEQ * DH;

    const int pr0 = tid >> 4, ps0 = tid & 15;
    const int pr1 = (tid + 256) >> 4, ps1 = tid & 15;
    const int vr = tid >> 3, vs = tid & 7;

    const int wm = (wid & 3) * 32;
    const int wn = (wid >> 2) * 32;

    const uint32_t a_tr = (uint32_t)(((lane & 7) + ((lane >> 4) << 3)) * AO_AROW + (wm + (lane & 8)) * 2);
    const uint32_t b_tr = (uint32_t)(((lane & 7) + (lane & 8)) * AO_VROW + (wn + ((lane >> 4) << 3)) * 2);

    float acc[2][4][4];
#pragma unroll
    for (int i = 0; i < 2; i++)
#pragma unroll
        for (int j = 0; j < 4; j++)
#pragma unroll
            for (int e = 0; e < 4; e++) acc[i][j][e] = 0.f;

    const int NC = SEQ / 32;   // 64

    {
        const int k0 = 0;
        const uint32_t st = sb;
        cp16(st + AO_EH + pr0*AO_AROW + ps0*16, Pb + (size_t)(k0 + pr0) * SEQ + ps0*8);
        cp16(st + AO_EH + pr1*AO_AROW + ps1*16, Pb + (size_t)(k0 + pr1) * SEQ + ps1*8);
        cp16(st + AO_VHI + vr*AO_VROW + vs*16,  Vbh + (size_t)(k0 + vr) * DH + vs*8);
        cp16(st + AO_VLO + vr*AO_VROW + vs*16,  Vbl + (size_t)(k0 + vr) * DH + vs*8);
        asm volatile("cp.async.commit_group;" ::: "memory");
    }

    for (int c = 0; c < NC; c++) {
        if (c + 1 < NC) {
            const int k0 = (c + 1) * 32;
            const uint32_t st = sb + ((c + 1) & 1) * AO_STAGE;
            cp16(st + AO_EH + pr0*AO_AROW + ps0*16, Pb + (size_t)(k0 + pr0) * SEQ + ps0*8);
            cp16(st + AO_EH + pr1*AO_AROW + ps1*16, Pb + (size_t)(k0 + pr1) * SEQ + ps1*8);
            cp16(st + AO_VHI + vr*AO_VROW + vs*16,  Vbh + (size_t)(k0 + vr) * DH + vs*8);
            cp16(st + AO_VLO + vr*AO_VROW + vs*16,  Vbl + (size_t)(k0 + vr) * DH + vs*8);
            asm volatile("cp.async.commit_group;" ::: "memory");
            asm volatile("cp.async.wait_group 1;" ::: "memory");
        } else {
            asm volatile("cp.async.wait_group 0;" ::: "memory");
        }
        __syncthreads();

        const uint32_t st = sb + (c & 1) * AO_STAGE;
#pragma unroll
        for (int kk = 0; kk < 2; kk++) {
            uint32_t ah[2][4];
#pragma unroll
            for (int mt = 0; mt < 2; mt++)
                ldm_x4t(ah[mt], st + AO_EH + a_tr + kk * (16 * AO_AROW) + mt * 32);
            uint32_t bh_[4][2], bl_[4][2];
#pragma unroll
            for (int np = 0; np < 2; np++) {
                uint32_t r[4];
                ldm_x4t(r, st + AO_VHI + b_tr + kk * (16 * AO_VROW) + np * 32);
                bh_[2*np][0] = r[0]; bh_[2*np][1] = r[1];
                bh_[2*np+1][0] = r[2]; bh_[2*np+1][1] = r[3];
                ldm_x4t(r, st + AO_VLO + b_tr + kk * (16 * AO_VROW) + np * 32);
                bl_[2*np][0] = r[0]; bl_[2*np][1] = r[1];
                bl_[2*np+1][0] = r[2]; bl_[2*np+1][1] = r[3];
            }
#pragma unroll
            for (int mt = 0; mt < 2; mt++)
#pragma unroll
                for (int nt = 0; nt < 4; nt++) {
                    mma16816_f16(acc[mt][nt], ah[mt], bh_[nt]);
                    mma16816_f16(acc[mt][nt], ah[mt], bl_[nt]);
                }
        }
        __syncthreads();
    }

    const float dsc = 1.f / 4096.f;
    const int g = lane >> 2, cpr = (lane & 3) * 2;
#pragma unroll
    for (int mt = 0; mt < 2; mt++)
#pragma unroll
        for (int nt = 0; nt < 4; nt++) {
            const int q = qt + wm + mt * 16 + g;
            const int col = wn + nt * 8 + cpr;
            const size_t o0 = ((size_t)b * SEQ + q)     * LDIM + h * DH + col;
            const size_t o1 = ((size_t)b * SEQ + q + 8) * LDIM + h * DH + col;
            *(__half2*)(Z16 + o0) = __floats2half2_rn(acc[mt][nt][0] * dsc, acc[mt][nt][1] * dsc);
            *(__half2*)(Z16 + o1) = __floats2half2_rn(acc[mt][nt][2] * dsc, acc[mt][nt][3] * dsc);
        }
}

// ================= row L2 normalize -> fp16 =================
__global__ __launch_bounds__(256) void l2norm_f16(const float* __restrict__ in,
                                                  __half* __restrict__ out) {
    const size_t rowi = blockIdx.x;
    const float* p = in + rowi * DIM;
    const int t = threadIdx.x;
    float v[4];
    float ss = 0.f;
#pragma unroll
    for (int i = 0; i < 4; i++) { v[i] = p[t + 256 * i]; ss += v[i] * v[i]; }
    __shared__ float red[256];
    red[t] = ss; __syncthreads();
    for (int s = 128; s > 0; s >>= 1) {
        if (t < s) red[t] = red[t] + red[t + s];
        __syncthreads();
    }
    const float n = sqrtf(red[0]);
    const float sc = 1.f / fmaxf(n, 1e-12f);
#pragma unroll
    for (int i = 0; i < 4; i++)
        out[rowi * DIM + t + 256 * i] = __float2half_rn(v[i] * sc);
}

// ================= row L2 normalize + exact GELU =================
__global__ __launch_bounds__(256) void l2norm_gelu(const float* __restrict__ in,
                                                   float* __restrict__ out) {
    const size_t rowi = blockIdx.x;
    const float* p = in + rowi * DIM;
    float* o = out + rowi * DIM;
    const int t = threadIdx.x;
    float v[4];
    float ss = 0.f;
#pragma unroll
    for (int i = 0; i < 4; i++) { v[i] = p[t + 256 * i]; ss += v[i] * v[i]; }
    __shared__ float red[256];
    red[t] = ss; __syncthreads();
    for (int s = 128; s > 0; s >>= 1) {
        if (t < s) red[t] = red[t] + red[t + s];
        __syncthreads();
    }
    const float n = sqrtf(red[0]);
    const float sc = 1.f / fmaxf(n, 1e-12f);
#pragma unroll
    for (int i = 0; i < 4; i++) {
        float y = v[i] * sc;
        o[t + 256 * i] = 0.5f * y * (1.f + erff(y * 0.70710678118654752f));
    }
}

// ================= host launcher =================
extern "C" void kernel_launch(void* const* d_in, const int* in_sizes, int n_in,
                              void* d_out, int out_size) {
    const float* x   = (const float*)d_in[0];
    const float* Wq  = (const float*)d_in[1];
    const float* Wk  = (const float*)d_in[2];
    const float* Wv  = (const float*)d_in[3];
    const float* Wo  = (const float*)d_in[4];
    const float* Wff = (const float*)d_in[5];
    float* outp = (float*)d_out;

    float *pZ2, *pSpart, *pSinv;
    __half *pX16, *pWqh, *pWql, *pWkh, *pWkl, *pWvh, *pWvl;
    __half *pWoh, *pWol, *pWfh, *pWfl;
    __half *pQ16, *pK16, *pV16, *pEh, *pVShi, *pVSlo, *pZ16, *pN16;
    cudaGetSymbolAddress((void**)&pZ2,  g_Z2);
    cudaGetSymbolAddress((void**)&pX16, g_X16);
    cudaGetSymbolAddress((void**)&pWqh, g_Wqh);
    cudaGetSymbolAddress((void**)&pWql, g_Wql);
    cudaGetSymbolAddress((void**)&pWkh, g_Wkh);
    cudaGetSymbolAddress((void**)&pWkl, g_Wkl);
    cudaGetSymbolAddress((void**)&pWvh, g_Wvh);
    cudaGetSymbolAddress((void**)&pWvl, g_Wvl);
    cudaGetSymbolAddress((void**)&pWoh, g_Woh);
    cudaGetSymbolAddress((void**)&pWol, g_Wol);
    cudaGetSymbolAddress((void**)&pWfh, g_Wfh);
    cudaGetSymbolAddress((void**)&pWfl, g_Wfl);
    cudaGetSymbolAddress((void**)&pQ16, g_Q16);
    cudaGetSymbolAddress((void**)&pK16, g_K16);
    cudaGetSymbolAddress((void**)&pV16, g_V16);
    cudaGetSymbolAddress((void**)&pEh,  g_Eh);
    cudaGetSymbolAddress((void**)&pSpart, g_Spart);
    cudaGetSymbolAddress((void**)&pSinv,  g_Sinv);
    cudaGetSymbolAddress((void**)&pVShi, g_VShi);
    cudaGetSymbolAddress((void**)&pVSlo, g_VSlo);
    cudaGetSymbolAddress((void**)&pZ16, g_Z16);
    cudaGetSymbolAddress((void**)&pN16, g_N16);

    cudaFuncSetAttribute(gemm2<0>,       cudaFuncAttributeMaxDynamicSharedMemorySize, SMEM_G2);
    cudaFuncSetAttribute(gemm2<1>,       cudaFuncAttributeMaxDynamicSharedMemorySize, SMEM_G2);
    cudaFuncSetAttribute(scores_exp_f16, cudaFuncAttributeMaxDynamicSharedMemorySize, SC_TOTAL);
    cudaFuncSetAttribute(att_out_hmma,   cudaFuncAttributeMaxDynamicSharedMemorySize, AO_TOTAL);

    const dim3 gG(GN / 128, MTOT / 128);    // (8, 32)
    const dim3 gT(DIM / 32, DIM / 32);      // (32, 32)
    const int  convBlocksX = (MTOT * DIM) / (256 * 4);

    // conversions + QKV projections (2-term fp16)
    to_f16<<<convBlocksX, 256>>>(x, pX16);                    // 1
    tsplit_f16<<<gT, 256>>>(Wq, pWqh, pWql);                  // 2
    tsplit_f16<<<gT, 256>>>(Wk, pWkh, pWkl);                  // 3
    tsplit_f16<<<gT, 256>>>(Wv, pWvh, pWvl);                  // 4
    tsplit_f16<<<gT, 256>>>(Wo, pWoh, pWol);                  // 5
    gemm2<1><<<gG, 256, SMEM_G2>>>(pX16, pWqh, pWql, nullptr, pQ16, 0.03125f);  // 6
    tsplit_f16<<<gT, 256>>>(Wff, pWfh, pWfl);                 // 7
    gemm2<1><<<gG, 256, SMEM_G2>>>(pX16, pWkh, pWkl, nullptr, pK16, 1.0f);
    gemm2<1><<<gG, 256, SMEM_G2>>>(pX16, pWvh, pWvl, nullptr, pV16, 1.0f);

    // attention: scores+exp -> rowsum -> V*4096/S -> PV
    scores_exp_f16<<<dim3(SEQ / 128, SEQ / 128, BHTOT), 256, SC_TOTAL>>>(pK16, pQ16, pEh, pSpart);
    reduce_S<<<(BHTOT * SEQ) / 256, 256>>>(pSpart, pSinv);
    vscale<<<dim3(SEQ / 4, BHTOT), 256>>>(pV16, pSinv, pVShi, pVSlo);
    att_out_hmma<<<dim3(SEQ / 128, BHTOT), 256, AO_TOTAL>>>(pEh, pVShi, pVSlo, pZ16);

    // out projection -> normalize(fp16) -> FFN -> norm+gelu
    gemm2<0><<<gG, 256, SMEM_G2>>>(pZ16, pWoh, pWol, pZ2, nullptr, 1.0f);
    l2norm_f16<<<MTOT, 256>>>(pZ2, pN16);
    gemm2<0><<<gG, 256, SMEM_G2>>>(pN16, pWfh, pWfl, pZ2, nullptr, 1.0f);
    l2norm_gelu<<<MTOT, 256>>>(pZ2, outp);
}